// round 1
// baseline (speedup 1.0000x reference)
#include <cuda_runtime.h>

typedef unsigned long long u64;

#define MAX_N 100000
#define MAX_E 3200000

// ---------------- scratch (static device allocations are the allowed path) ---
__device__ float g_hA[MAX_N * 128];
__device__ float g_hB[MAX_N * 128];
__device__ float g_sup[MAX_N * 128];
__device__ float g_self[MAX_N * 128];
__device__ int   g_cnt[MAX_N];
__device__ int   g_off[MAX_N + 1];
__device__ int   g_cur[MAX_N];
__device__ int   g_bsum[128];
__device__ int   g_bscan[128];
__device__ int   g_ecol[MAX_E];
__device__ float g_eval[MAX_E];

// ---------------- helpers ----------------------------------------------------
__device__ __forceinline__ u64 dup32(float v) {
    u64 b = (u64)__float_as_uint(v);
    return b | (b << 32);
}
__device__ __forceinline__ void fmax2(u64& d, u64 a, u64 b) {
    asm("fma.rn.f32x2 %0, %1, %2, %0;" : "+l"(d) : "l"(a), "l"(b));
}
__device__ __forceinline__ float loF(u64 d) { return __int_as_float((int)(unsigned)(d & 0xffffffffULL)); }
__device__ __forceinline__ float hiF(u64 d) { return __int_as_float((int)(unsigned)(d >> 32)); }

// ---------------- CSR build --------------------------------------------------
__global__ void k_zero(int n) {
    int i = blockIdx.x * blockDim.x + threadIdx.x;
    if (i < n) g_cnt[i] = 0;
}

__global__ void k_hist(const int* __restrict__ rows, int E) {
    int i = blockIdx.x * blockDim.x + threadIdx.x;
    if (i < E) atomicAdd(&g_cnt[rows[i]], 1);
}

__global__ void k_scan1(int n) {
    __shared__ int buf[2][1024];
    int i = blockIdx.x * 1024 + threadIdx.x;
    int v = (i < n) ? g_cnt[i] : 0;
    int src = 0;
    buf[0][threadIdx.x] = v;
    for (int ofs = 1; ofs < 1024; ofs <<= 1) {
        __syncthreads();
        int t = buf[src][threadIdx.x];
        if ((int)threadIdx.x >= ofs) t += buf[src][threadIdx.x - ofs];
        buf[1 - src][threadIdx.x] = t;
        src ^= 1;
    }
    __syncthreads();
    int incl = buf[src][threadIdx.x];
    if (i < n) g_cnt[i] = incl;
    if (threadIdx.x == 1023) g_bsum[blockIdx.x] = incl;
}

__global__ void k_scan2(int nb) {
    __shared__ int buf[2][128];
    int tid = threadIdx.x;
    int v = (tid < nb) ? g_bsum[tid] : 0;
    int src = 0;
    buf[0][tid] = v;
    for (int ofs = 1; ofs < 128; ofs <<= 1) {
        __syncthreads();
        int t = buf[src][tid];
        if (tid >= ofs) t += buf[src][tid - ofs];
        buf[1 - src][tid] = t;
        src ^= 1;
    }
    __syncthreads();
    g_bscan[tid] = buf[src][tid];
}

__global__ void k_scan3(int n) {
    int i = blockIdx.x * blockDim.x + threadIdx.x;
    if (i < n) {
        int blk = i >> 10;
        int pre = blk ? g_bscan[blk - 1] : 0;
        g_off[i + 1] = g_cnt[i] + pre;
        if (i == 0) g_off[0] = 0;
    }
}

__global__ void k_cursor(int n) {
    int i = blockIdx.x * blockDim.x + threadIdx.x;
    if (i < n) g_cur[i] = g_off[i];
}

__global__ void k_scatter(const int* __restrict__ rows, const int* __restrict__ cols,
                          const float* __restrict__ vals, int E) {
    int e = blockIdx.x * blockDim.x + threadIdx.x;
    if (e < E) {
        int r = rows[e];
        int p = atomicAdd(&g_cur[r], 1);
        g_ecol[p] = cols[e];
        g_eval[p] = vals[e];
    }
}

// ---------------- fused fc1+relu+fc2+relu+layernorm --------------------------
// smem: w1T[128][128] | w2T[128][128] | sxd u64[8][4][128] | sh1d u64[8][4][128]
__global__ void __launch_bounds__(256, 1) k_fc(
    const float* __restrict__ x,
    const float* __restrict__ w1, const float* __restrict__ b1,
    const float* __restrict__ w2, const float* __restrict__ b2,
    const float* __restrict__ gamma, const float* __restrict__ beta,
    float* __restrict__ hout, int n)
{
    extern __shared__ char smem[];
    float* w1T = (float*)smem;
    float* w2T = w1T + 16384;
    u64*   sxd = (u64*)(w2T + 16384);
    u64*   sh1d = sxd + 4096;

    int tid = threadIdx.x;
    for (int i = tid; i < 16384; i += 256) {
        int k = i >> 7, j = i & 127;
        w1T[i] = w1[j * 128 + k];
        w2T[i] = w2[j * 128 + k];
    }
    __syncthreads();

    int warp = tid >> 5, lane = tid & 31;
    u64* myx = sxd + warp * 512;
    u64* myh = sh1d + warp * 512;
    int ngroups = (n + 3) >> 2;

    for (int g = blockIdx.x * 8 + warp; g < ngroups; g += gridDim.x * 8) {
        int r0 = g << 2;
        // load 4 rows of x, duplicated into (x,x) u64 pairs
        #pragma unroll
        for (int r = 0; r < 4; r++) {
            int row = r0 + r;
            float4 xv = make_float4(0.f, 0.f, 0.f, 0.f);
            if (row < n) xv = ((const float4*)(x + (size_t)row * 128))[lane];
            u64* dst = myx + r * 128 + lane * 4;
            dst[0] = dup32(xv.x); dst[1] = dup32(xv.y);
            dst[2] = dup32(xv.z); dst[3] = dup32(xv.w);
        }
        __syncwarp();

        // ----- phase 1: h1 = relu(x @ w1^T + b1)
        u64 a1[4][2] = {{0, 0}, {0, 0}, {0, 0}, {0, 0}};
        #pragma unroll 8
        for (int k = 0; k < 128; k++) {
            ulonglong2 w = *(const ulonglong2*)(w1T + k * 128 + lane * 4);
            #pragma unroll
            for (int r = 0; r < 4; r++) {
                u64 xk = myx[r * 128 + k];
                fmax2(a1[r][0], xk, w.x);
                fmax2(a1[r][1], xk, w.y);
            }
        }
        float4 bb1 = ((const float4*)b1)[lane];
        #pragma unroll
        for (int r = 0; r < 4; r++) {
            float v0 = fmaxf(loF(a1[r][0]) + bb1.x, 0.f);
            float v1 = fmaxf(hiF(a1[r][0]) + bb1.y, 0.f);
            float v2 = fmaxf(loF(a1[r][1]) + bb1.z, 0.f);
            float v3 = fmaxf(hiF(a1[r][1]) + bb1.w, 0.f);
            u64* dst = myh + r * 128 + lane * 4;
            dst[0] = dup32(v0); dst[1] = dup32(v1);
            dst[2] = dup32(v2); dst[3] = dup32(v3);
        }
        __syncwarp();

        // ----- phase 2: h2 = relu(h1 @ w2^T + b2)
        u64 a2[4][2] = {{0, 0}, {0, 0}, {0, 0}, {0, 0}};
        #pragma unroll 8
        for (int k = 0; k < 128; k++) {
            ulonglong2 w = *(const ulonglong2*)(w2T + k * 128 + lane * 4);
            #pragma unroll
            for (int r = 0; r < 4; r++) {
                u64 hk = myh[r * 128 + k];
                fmax2(a2[r][0], hk, w.x);
                fmax2(a2[r][1], hk, w.y);
            }
        }
        float4 bb2 = ((const float4*)b2)[lane];
        float4 gg = ((const float4*)gamma)[lane];
        float4 be = ((const float4*)beta)[lane];
        #pragma unroll
        for (int r = 0; r < 4; r++) {
            int row = r0 + r;
            float v0 = fmaxf(loF(a2[r][0]) + bb2.x, 0.f);
            float v1 = fmaxf(hiF(a2[r][0]) + bb2.y, 0.f);
            float v2 = fmaxf(loF(a2[r][1]) + bb2.z, 0.f);
            float v3 = fmaxf(hiF(a2[r][1]) + bb2.w, 0.f);
            // layernorm over 128 features of this row (unbiased std, torch-style)
            float s = v0 + v1 + v2 + v3;
            float q = fmaf(v0, v0, fmaf(v1, v1, fmaf(v2, v2, v3 * v3)));
            #pragma unroll
            for (int o = 16; o; o >>= 1) {
                s += __shfl_xor_sync(0xffffffffu, s, o);
                q += __shfl_xor_sync(0xffffffffu, q, o);
            }
            float mean = s * (1.f / 128.f);
            float var = (q - s * mean) * (1.f / 127.f);
            var = fmaxf(var, 0.f);
            float inv = 1.f / (sqrtf(var) + 1e-6f);
            if (row < n) {
                float4 o4;
                o4.x = gg.x * (v0 - mean) * inv + be.x;
                o4.y = gg.y * (v1 - mean) * inv + be.y;
                o4.z = gg.z * (v2 - mean) * inv + be.z;
                o4.w = gg.w * (v3 - mean) * inv + be.w;
                ((float4*)(hout + (size_t)row * 128))[lane] = o4;
            }
        }
        __syncwarp();
    }
}

// ---------------- GCN dense part: sup = h@wn ; selfb = h@ws + b ---------------
template <int OUT>
__global__ void __launch_bounds__(256, 1) k_gemm2(
    const float* __restrict__ h,
    const float* __restrict__ wn, const float* __restrict__ ws,
    const float* __restrict__ bias,
    float* __restrict__ sup, float* __restrict__ selfb, int n)
{
    extern __shared__ char smem[];
    float* wns = (float*)smem;            // [128][OUT], k-major (input layout)
    float* wss = wns + 128 * OUT;
    u64*   sxd = (u64*)(wss + 128 * OUT);

    int tid = threadIdx.x;
    for (int i = tid; i < 128 * OUT; i += 256) {
        wns[i] = wn[i];
        wss[i] = ws[i];
    }
    __syncthreads();

    constexpr int PAIRS = OUT / 64;  // 2 for OUT=128, 1 for OUT=64
    int warp = tid >> 5, lane = tid & 31;
    u64* myx = sxd + warp * 512;
    int ngroups = (n + 3) >> 2;

    for (int g = blockIdx.x * 8 + warp; g < ngroups; g += gridDim.x * 8) {
        int r0 = g << 2;
        #pragma unroll
        for (int r = 0; r < 4; r++) {
            int row = r0 + r;
            float4 xv = make_float4(0.f, 0.f, 0.f, 0.f);
            if (row < n) xv = ((const float4*)(h + (size_t)row * 128))[lane];
            u64* dst = myx + r * 128 + lane * 4;
            dst[0] = dup32(xv.x); dst[1] = dup32(xv.y);
            dst[2] = dup32(xv.z); dst[3] = dup32(xv.w);
        }
        __syncwarp();

        u64 aN[4][PAIRS], aS[4][PAIRS];
        #pragma unroll
        for (int r = 0; r < 4; r++)
            #pragma unroll
            for (int p = 0; p < PAIRS; p++) { aN[r][p] = 0; aS[r][p] = 0; }

        #pragma unroll 8
        for (int k = 0; k < 128; k++) {
            if (PAIRS == 2) {
                ulonglong2 wN = *(const ulonglong2*)(wns + k * OUT + lane * 4);
                ulonglong2 wS = *(const ulonglong2*)(wss + k * OUT + lane * 4);
                #pragma unroll
                for (int r = 0; r < 4; r++) {
                    u64 xk = myx[r * 128 + k];
                    fmax2(aN[r][0], xk, wN.x);
                    fmax2(aN[r][1], xk, wN.y);
                    fmax2(aS[r][0], xk, wS.x);
                    fmax2(aS[r][1], xk, wS.y);
                }
            } else {
                u64 wN = *(const u64*)(wns + k * OUT + lane * 2);
                u64 wS = *(const u64*)(wss + k * OUT + lane * 2);
                #pragma unroll
                for (int r = 0; r < 4; r++) {
                    u64 xk = myx[r * 128 + k];
                    fmax2(aN[r][0], xk, wN);
                    fmax2(aS[r][0], xk, wS);
                }
            }
        }

        if (PAIRS == 2) {
            float4 bv = ((const float4*)bias)[lane];
            #pragma unroll
            for (int r = 0; r < 4; r++) {
                int row = r0 + r;
                if (row >= n) continue;
                float4 vN = make_float4(loF(aN[r][0]), hiF(aN[r][0]),
                                        loF(aN[r][1]), hiF(aN[r][1]));
                ((float4*)(sup + (size_t)row * OUT))[lane] = vN;
                float4 vS = make_float4(loF(aS[r][0]) + bv.x, hiF(aS[r][0]) + bv.y,
                                        loF(aS[r][1]) + bv.z, hiF(aS[r][1]) + bv.w);
                ((float4*)(selfb + (size_t)row * OUT))[lane] = vS;
            }
        } else {
            float2 bv = ((const float2*)bias)[lane];
            #pragma unroll
            for (int r = 0; r < 4; r++) {
                int row = r0 + r;
                if (row >= n) continue;
                float2 vN = make_float2(loF(aN[r][0]), hiF(aN[r][0]));
                ((float2*)(sup + (size_t)row * OUT))[lane] = vN;
                float2 vS = make_float2(loF(aS[r][0]) + bv.x, hiF(aS[r][0]) + bv.y);
                ((float2*)(selfb + (size_t)row * OUT))[lane] = vS;
            }
        }
        __syncwarp();
    }
}

// ---------------- sparse neighbor aggregation + relu -------------------------
template <int OUT>
__global__ void k_spmm(const float* __restrict__ sup, const float* __restrict__ selfb,
                       float* __restrict__ out, int n)
{
    int warp = (blockIdx.x * blockDim.x + threadIdx.x) >> 5;
    int lane = threadIdx.x & 31;
    if (warp >= n) return;
    int e0 = g_off[warp], e1 = g_off[warp + 1];

    if (OUT == 128) {
        float4 acc = make_float4(0.f, 0.f, 0.f, 0.f);
        int e = e0;
        for (; e + 1 < e1; e += 2) {
            int c0 = __ldg(&g_ecol[e]);
            int c1 = __ldg(&g_ecol[e + 1]);
            float v0 = __ldg(&g_eval[e]);
            float v1 = __ldg(&g_eval[e + 1]);
            float4 s0 = ((const float4*)(sup + (size_t)c0 * 128))[lane];
            float4 s1 = ((const float4*)(sup + (size_t)c1 * 128))[lane];
            acc.x = fmaf(v0, s0.x, fmaf(v1, s1.x, acc.x));
            acc.y = fmaf(v0, s0.y, fmaf(v1, s1.y, acc.y));
            acc.z = fmaf(v0, s0.z, fmaf(v1, s1.z, acc.z));
            acc.w = fmaf(v0, s0.w, fmaf(v1, s1.w, acc.w));
        }
        if (e < e1) {
            int c0 = __ldg(&g_ecol[e]);
            float v0 = __ldg(&g_eval[e]);
            float4 s0 = ((const float4*)(sup + (size_t)c0 * 128))[lane];
            acc.x = fmaf(v0, s0.x, acc.x);
            acc.y = fmaf(v0, s0.y, acc.y);
            acc.z = fmaf(v0, s0.z, acc.z);
            acc.w = fmaf(v0, s0.w, acc.w);
        }
        float4 sb = ((const float4*)(selfb + (size_t)warp * 128))[lane];
        float4 o;
        o.x = fmaxf(acc.x + sb.x, 0.f);
        o.y = fmaxf(acc.y + sb.y, 0.f);
        o.z = fmaxf(acc.z + sb.z, 0.f);
        o.w = fmaxf(acc.w + sb.w, 0.f);
        ((float4*)(out + (size_t)warp * 128))[lane] = o;
    } else {
        float2 acc = make_float2(0.f, 0.f);
        int e = e0;
        for (; e + 1 < e1; e += 2) {
            int c0 = __ldg(&g_ecol[e]);
            int c1 = __ldg(&g_ecol[e + 1]);
            float v0 = __ldg(&g_eval[e]);
            float v1 = __ldg(&g_eval[e + 1]);
            float2 s0 = ((const float2*)(sup + (size_t)c0 * 64))[lane];
            float2 s1 = ((const float2*)(sup + (size_t)c1 * 64))[lane];
            acc.x = fmaf(v0, s0.x, fmaf(v1, s1.x, acc.x));
            acc.y = fmaf(v0, s0.y, fmaf(v1, s1.y, acc.y));
        }
        if (e < e1) {
            int c0 = __ldg(&g_ecol[e]);
            float v0 = __ldg(&g_eval[e]);
            float2 s0 = ((const float2*)(sup + (size_t)c0 * 64))[lane];
            acc.x = fmaf(v0, s0.x, acc.x);
            acc.y = fmaf(v0, s0.y, acc.y);
        }
        float2 sb = ((const float2*)(selfb + (size_t)warp * 64))[lane];
        float2 o;
        o.x = fmaxf(acc.x + sb.x, 0.f);
        o.y = fmaxf(acc.y + sb.y, 0.f);
        ((float2*)(out + (size_t)warp * 64))[lane] = o;
    }
}

// ---------------- launch -----------------------------------------------------
extern "C" void kernel_launch(void* const* d_in, const int* in_sizes, int n_in,
                              void* d_out, int out_size)
{
    const float* x     = (const float*)d_in[0];
    const int*   erow  = (const int*)d_in[1];
    const int*   ecol  = (const int*)d_in[2];
    const float* eval  = (const float*)d_in[3];
    const float* w1    = (const float*)d_in[4];
    const float* b1    = (const float*)d_in[5];
    const float* w2    = (const float*)d_in[6];
    const float* b2    = (const float*)d_in[7];
    const float* gam   = (const float*)d_in[8];
    const float* bet   = (const float*)d_in[9];
    const float* gwn[4] = {(const float*)d_in[10], (const float*)d_in[13],
                           (const float*)d_in[16], (const float*)d_in[19]};
    const float* gws[4] = {(const float*)d_in[11], (const float*)d_in[14],
                           (const float*)d_in[17], (const float*)d_in[20]};
    const float* gb[4]  = {(const float*)d_in[12], (const float*)d_in[15],
                           (const float*)d_in[18], (const float*)d_in[21]};
    float* out = (float*)d_out;

    int n = in_sizes[0] / 128;
    int E = in_sizes[1];

    float *hA, *hB, *sup, *self;
    cudaGetSymbolAddress((void**)&hA, g_hA);
    cudaGetSymbolAddress((void**)&hB, g_hB);
    cudaGetSymbolAddress((void**)&sup, g_sup);
    cudaGetSymbolAddress((void**)&self, g_self);

    cudaFuncSetAttribute(k_fc, cudaFuncAttributeMaxDynamicSharedMemorySize, 192 * 1024);
    cudaFuncSetAttribute(k_gemm2<128>, cudaFuncAttributeMaxDynamicSharedMemorySize, 160 * 1024);
    cudaFuncSetAttribute(k_gemm2<64>, cudaFuncAttributeMaxDynamicSharedMemorySize, 96 * 1024);

    int nb = (n + 1023) / 1024;

    // CSR build
    k_zero<<<(n + 255) / 256, 256>>>(n);
    k_hist<<<(E + 255) / 256, 256>>>(erow, E);
    k_scan1<<<nb, 1024>>>(n);
    k_scan2<<<1, 128>>>(nb);
    k_scan3<<<(n + 255) / 256, 256>>>(n);
    k_cursor<<<(n + 255) / 256, 256>>>(n);
    k_scatter<<<(E + 255) / 256, 256>>>(erow, ecol, eval, E);

    // fc1 + relu + fc2 + relu + layernorm
    k_fc<<<148, 256, 192 * 1024>>>(x, w1, b1, w2, b2, gam, bet, hA, n);

    int spblocks = (n + 7) / 8;

    // GCN layers 1-3 (OUT=128)
    k_gemm2<128><<<148, 256, 160 * 1024>>>(hA, gwn[0], gws[0], gb[0], sup, self, n);
    k_spmm<128><<<spblocks, 256>>>(sup, self, hB, n);

    k_gemm2<128><<<148, 256, 160 * 1024>>>(hB, gwn[1], gws[1], gb[1], sup, self, n);
    k_spmm<128><<<spblocks, 256>>>(sup, self, hA, n);

    k_gemm2<128><<<148, 256, 160 * 1024>>>(hA, gwn[2], gws[2], gb[2], sup, self, n);
    k_spmm<128><<<spblocks, 256>>>(sup, self, hB, n);

    // GCN layer 4 (OUT=64) -> d_out
    k_gemm2<64><<<148, 256, 96 * 1024>>>(hB, gwn[3], gws[3], gb[3], sup, self, n);
    k_spmm<64><<<spblocks, 256>>>(sup, self, out, n);
}

// round 4
// speedup vs baseline: 1.1523x; 1.1523x over previous
#include <cuda_runtime.h>
#include <cuda_bf16.h>
#include <cstdint>

typedef unsigned long long u64;

#define MAX_N 100000
#define MAX_E 3200000

// ---------------- scratch ----------------------------------------------------
__device__ float g_sup[MAX_N * 128];
__device__ float g_self[MAX_N * 128];
__device__ __align__(16) __nv_bfloat16 g_hh[MAX_N * 128];
__device__ __align__(16) __nv_bfloat16 g_hl[MAX_N * 128];
__device__ __align__(16) __nv_bfloat16 g_wbh[4 * 32768];
__device__ __align__(16) __nv_bfloat16 g_wbl[4 * 32768];
__device__ int   g_cnt[MAX_N];
__device__ int   g_off[MAX_N + 1];
__device__ int   g_cur[MAX_N];
__device__ int   g_ecol[MAX_E];
__device__ float g_eval[MAX_E];

// ---------------- small helpers ----------------------------------------------
__device__ __forceinline__ u64 dup32(float v) {
    u64 b = (u64)__float_as_uint(v);
    return b | (b << 32);
}
__device__ __forceinline__ void fmax2(u64& d, u64 a, u64 b) {
    asm("fma.rn.f32x2 %0, %1, %2, %0;" : "+l"(d) : "l"(a), "l"(b));
}
__device__ __forceinline__ float loF(u64 d) { return __int_as_float((int)(unsigned)(d & 0xffffffffULL)); }
__device__ __forceinline__ float hiF(u64 d) { return __int_as_float((int)(unsigned)(d >> 32)); }

// pack two floats into bf16x2 word, returning residuals
__device__ __forceinline__ unsigned pack_bf2(float a, float b, float& ra, float& rb) {
    __nv_bfloat16 ha = __float2bfloat16_rn(a), hb = __float2bfloat16_rn(b);
    ra = a - __bfloat162float(ha);
    rb = b - __bfloat162float(hb);
    return ((unsigned)__bfloat16_as_ushort(hb) << 16) | (unsigned)__bfloat16_as_ushort(ha);
}
__device__ __forceinline__ unsigned pack_bf2n(float a, float b) {
    __nv_bfloat16 ha = __float2bfloat16_rn(a), hb = __float2bfloat16_rn(b);
    return ((unsigned)__bfloat16_as_ushort(hb) << 16) | (unsigned)__bfloat16_as_ushort(ha);
}

__device__ __forceinline__ void mma_bf16(float& d0, float& d1, float& d2, float& d3,
                                         uint32_t a0, uint32_t a1, uint32_t a2, uint32_t a3,
                                         uint32_t b0, uint32_t b1) {
    asm volatile("mma.sync.aligned.m16n8k16.row.col.f32.bf16.bf16.f32 "
                 "{%0,%1,%2,%3}, {%4,%5,%6,%7}, {%8,%9}, {%0,%1,%2,%3};"
                 : "+f"(d0), "+f"(d1), "+f"(d2), "+f"(d3)
                 : "r"(a0), "r"(a1), "r"(a2), "r"(a3), "r"(b0), "r"(b1));
}

// ---------------- weight prep: fp32 [128,O] -> bf16 hi/lo [N2][K] n-major ----
__global__ void k_prep_w(const float* __restrict__ wn0, const float* __restrict__ ws0,
                         const float* __restrict__ wn1, const float* __restrict__ ws1,
                         const float* __restrict__ wn2, const float* __restrict__ ws2,
                         const float* __restrict__ wn3, const float* __restrict__ ws3) {
    int idx = blockIdx.x * blockDim.x + threadIdx.x;
    if (idx >= 4 * 32768) return;
    int l = idx >> 15, rem = idx & 32767;
    int O = (l == 3) ? 64 : 128;
    if (rem >= 2 * O * 128) return;
    int nn = rem >> 7, k = rem & 127;
    const float* wn = (l == 0) ? wn0 : (l == 1) ? wn1 : (l == 2) ? wn2 : wn3;
    const float* ws = (l == 0) ? ws0 : (l == 1) ? ws1 : (l == 2) ? ws2 : ws3;
    float w = (nn < O) ? wn[k * O + nn] : ws[k * O + (nn - O)];
    __nv_bfloat16 h = __float2bfloat16_rn(w);
    __nv_bfloat16 lo = __float2bfloat16_rn(w - __bfloat162float(h));
    g_wbh[l * 32768 + rem] = h;
    g_wbl[l * 32768 + rem] = lo;
}

// ---------------- CSR build --------------------------------------------------
__global__ void k_zero(int n) {
    int i = blockIdx.x * blockDim.x + threadIdx.x;
    if (i < n) g_cnt[i] = 0;
}
__global__ void k_hist(const int* __restrict__ rows, int E) {
    int i = blockIdx.x * blockDim.x + threadIdx.x;
    if (i < E) atomicAdd(&g_cnt[rows[i]], 1);
}
__global__ void k_scan(int n) {
    __shared__ int wsum[32];
    __shared__ int s_carry;
    int tid = threadIdx.x, lane = tid & 31, wid = tid >> 5;
    if (tid == 0) { s_carry = 0; g_off[0] = 0; }
    __syncthreads();
    for (int base = 0; base < n; base += 1024) {
        int i = base + tid;
        int v = (i < n) ? g_cnt[i] : 0;
        int incl = v;
        #pragma unroll
        for (int o = 1; o < 32; o <<= 1) {
            int t = __shfl_up_sync(0xffffffffu, incl, o);
            if (lane >= o) incl += t;
        }
        if (lane == 31) wsum[wid] = incl;
        __syncthreads();
        if (wid == 0) {
            int w = wsum[lane];
            int wi = w;
            #pragma unroll
            for (int o = 1; o < 32; o <<= 1) {
                int t = __shfl_up_sync(0xffffffffu, wi, o);
                if (lane >= o) wi += t;
            }
            wsum[lane] = wi - w;
        }
        __syncthreads();
        int tot = s_carry + wsum[wid] + incl;
        if (i < n) { g_off[i + 1] = tot; g_cur[i] = tot - v; }
        __syncthreads();
        if (tid == 1023) s_carry = tot;
        __syncthreads();
    }
}
__global__ void k_scatter(const int* __restrict__ rows, const int* __restrict__ cols,
                          const float* __restrict__ vals, int E) {
    int e = blockIdx.x * blockDim.x + threadIdx.x;
    if (e < E) {
        int r = rows[e];
        int p = atomicAdd(&g_cur[r], 1);
        g_ecol[p] = cols[e];
        g_eval[p] = vals[e];
    }
}

// ---------------- fused fc1+relu+fc2+relu+layernorm -> bf16 hi/lo ------------
__global__ void __launch_bounds__(256, 1) k_fc(
    const float* __restrict__ x,
    const float* __restrict__ w1, const float* __restrict__ b1,
    const float* __restrict__ w2, const float* __restrict__ b2,
    const float* __restrict__ gamma, const float* __restrict__ beta, int n)
{
    extern __shared__ __align__(1024) char smem[];
    float* w1T = (float*)smem;
    float* w2T = w1T + 16384;
    u64*   sxd = (u64*)(w2T + 16384);
    u64*   sh1d = sxd + 4096;

    int tid = threadIdx.x;
    for (int i = tid; i < 16384; i += 256) {
        int k = i >> 7, j = i & 127;
        w1T[i] = w1[j * 128 + k];
        w2T[i] = w2[j * 128 + k];
    }
    __syncthreads();

    int warp = tid >> 5, lane = tid & 31;
    u64* myx = sxd + warp * 512;
    u64* myh = sh1d + warp * 512;
    int ngroups = (n + 3) >> 2;

    for (int g = blockIdx.x * 8 + warp; g < ngroups; g += gridDim.x * 8) {
        int r0 = g << 2;
        #pragma unroll
        for (int r = 0; r < 4; r++) {
            int row = r0 + r;
            float4 xv = make_float4(0.f, 0.f, 0.f, 0.f);
            if (row < n) xv = ((const float4*)(x + (size_t)row * 128))[lane];
            u64* dst = myx + r * 128 + lane * 4;
            dst[0] = dup32(xv.x); dst[1] = dup32(xv.y);
            dst[2] = dup32(xv.z); dst[3] = dup32(xv.w);
        }
        __syncwarp();

        u64 a1[4][2] = {{0, 0}, {0, 0}, {0, 0}, {0, 0}};
        #pragma unroll 8
        for (int k = 0; k < 128; k++) {
            ulonglong2 w = *(const ulonglong2*)(w1T + k * 128 + lane * 4);
            #pragma unroll
            for (int r = 0; r < 4; r++) {
                u64 xk = myx[r * 128 + k];
                fmax2(a1[r][0], xk, w.x);
                fmax2(a1[r][1], xk, w.y);
            }
        }
        float4 bb1 = ((const float4*)b1)[lane];
        #pragma unroll
        for (int r = 0; r < 4; r++) {
            float v0 = fmaxf(loF(a1[r][0]) + bb1.x, 0.f);
            float v1 = fmaxf(hiF(a1[r][0]) + bb1.y, 0.f);
            float v2 = fmaxf(loF(a1[r][1]) + bb1.z, 0.f);
            float v3 = fmaxf(hiF(a1[r][1]) + bb1.w, 0.f);
            u64* dst = myh + r * 128 + lane * 4;
            dst[0] = dup32(v0); dst[1] = dup32(v1);
            dst[2] = dup32(v2); dst[3] = dup32(v3);
        }
        __syncwarp();

        u64 a2[4][2] = {{0, 0}, {0, 0}, {0, 0}, {0, 0}};
        #pragma unroll 8
        for (int k = 0; k < 128; k++) {
            ulonglong2 w = *(const ulonglong2*)(w2T + k * 128 + lane * 4);
            #pragma unroll
            for (int r = 0; r < 4; r++) {
                u64 hk = myh[r * 128 + k];
                fmax2(a2[r][0], hk, w.x);
                fmax2(a2[r][1], hk, w.y);
            }
        }
        float4 bb2 = ((const float4*)b2)[lane];
        float4 gg = ((const float4*)gamma)[lane];
        float4 be = ((const float4*)beta)[lane];
        #pragma unroll
        for (int r = 0; r < 4; r++) {
            int row = r0 + r;
            float v0 = fmaxf(loF(a2[r][0]) + bb2.x, 0.f);
            float v1 = fmaxf(hiF(a2[r][0]) + bb2.y, 0.f);
            float v2 = fmaxf(loF(a2[r][1]) + bb2.z, 0.f);
            float v3 = fmaxf(hiF(a2[r][1]) + bb2.w, 0.f);
            float s = v0 + v1 + v2 + v3;
            float q = fmaf(v0, v0, fmaf(v1, v1, fmaf(v2, v2, v3 * v3)));
            #pragma unroll
            for (int o = 16; o; o >>= 1) {
                s += __shfl_xor_sync(0xffffffffu, s, o);
                q += __shfl_xor_sync(0xffffffffu, q, o);
            }
            float mean = s * (1.f / 128.f);
            float var = fmaxf((q - s * mean) * (1.f / 127.f), 0.f);
            float inv = 1.f / (sqrtf(var) + 1e-6f);
            if (row < n) {
                float o0 = gg.x * (v0 - mean) * inv + be.x;
                float o1 = gg.y * (v1 - mean) * inv + be.y;
                float o2 = gg.z * (v2 - mean) * inv + be.z;
                float o3 = gg.w * (v3 - mean) * inv + be.w;
                float l0, l1, l2, l3;
                unsigned p01 = pack_bf2(o0, o1, l0, l1);
                unsigned p23 = pack_bf2(o2, o3, l2, l3);
                ((uint2*)(g_hh + (size_t)row * 128))[lane] = make_uint2(p01, p23);
                ((uint2*)(g_hl + (size_t)row * 128))[lane] = make_uint2(pack_bf2n(l0, l1), pack_bf2n(l2, l3));
            }
        }
        __syncwarp();
    }
}

// ---------------- HMMA GEMM: [sup | selfb] = h @ [wn | ws] (+bias) -----------
// 3-pass bf16 hi/lo split via mma.sync.m16n8k16 (base sm_80 PTX -> HMMA).
// Persistent 148 CTAs x 8 warps. B (hi/lo) staged once in smem; each warp
// independently owns a 16-row x 128-col task; A rows staged per-task into
// warp-private smem. Stride 68 u32 per row => conflict-free fragment LDS.
template <int N2>
__global__ void __launch_bounds__(256, 1) k_mma(
    const __nv_bfloat16* __restrict__ hh, const __nv_bfloat16* __restrict__ hl,
    const __nv_bfloat16* __restrict__ wbh, const __nv_bfloat16* __restrict__ wbl,
    const float* __restrict__ bias,
    float* __restrict__ sup, float* __restrict__ selfb, int n)
{
    constexpr int OUT = N2 / 2;
    constexpr int NHALF = N2 / 128;
    constexpr int BSTRIDE = 68;            // u32 per B row (64 data + 4 pad)
    extern __shared__ __align__(16) uint32_t sm32[];
    uint32_t* Bh = sm32;                   // [N2][68]
    uint32_t* Bl = Bh + N2 * BSTRIDE;
    int tid = threadIdx.x, wid = tid >> 5, lane = tid & 31;
    uint32_t* Aw = Bl + N2 * BSTRIDE + wid * (2 * 16 * BSTRIDE);
    uint32_t* Ahi = Aw;                    // [16][68]
    uint32_t* Alo = Aw + 16 * BSTRIDE;

    // stage weights (hi/lo) once
    for (int i = tid; i < N2 * 16; i += 256) {
        int r = i >> 4, q = i & 15;
        uint4 vh = ((const uint4*)wbh)[i];
        uint4 vl = ((const uint4*)wbl)[i];
        *(uint4*)(Bh + r * BSTRIDE + q * 4) = vh;
        *(uint4*)(Bl + r * BSTRIDE + q * 4) = vl;
    }
    __syncthreads();

    int q4 = lane & 3, r4 = lane >> 2;     // fragment coords
    int nRowTiles = (n + 15) >> 4;
    int ntasks = nRowTiles * NHALF;
    int gw = blockIdx.x * 8 + wid;

    for (int t = gw; t < ntasks; t += 148 * 8) {
        int rowTile = (NHALF == 2) ? (t >> 1) : t;
        int half = (NHALF == 2) ? (t & 1) : 0;
        int rowBase = rowTile << 4;

        // stage this warp's 16 A rows (hi/lo) into warp-private smem
        #pragma unroll
        for (int i = 0; i < 8; i++) {
            int idx = i * 32 + lane;
            int r = idx >> 4, q = idx & 15;
            int grow = rowBase + r;
            if (grow > n - 1) grow = n - 1;
            uint4 vh = ((const uint4*)(hh + (size_t)grow * 128))[q];
            uint4 vl = ((const uint4*)(hl + (size_t)grow * 128))[q];
            *(uint4*)(Ahi + r * BSTRIDE + q * 4) = vh;
            *(uint4*)(Alo + r * BSTRIDE + q * 4) = vl;
        }
        __syncwarp();

        float acc[16][4];
        #pragma unroll
        for (int nt = 0; nt < 16; nt++)
            #pragma unroll
            for (int j = 0; j < 4; j++) acc[nt][j] = 0.f;

        int nbase = half * 128;
        #pragma unroll 1
        for (int pass = 0; pass < 3; pass++) {
            const uint32_t* As = (pass == 1) ? Alo : Ahi;
            const uint32_t* Bs = (pass == 2) ? Bl : Bh;
            const uint32_t* Arow0 = As + r4 * BSTRIDE + q4;
            const uint32_t* Arow8 = As + (r4 + 8) * BSTRIDE + q4;
            const uint32_t* Bbase = Bs + (nbase + r4) * BSTRIDE + q4;
            #pragma unroll 2
            for (int ks = 0; ks < 8; ks++) {
                int kp = ks * 8;
                uint32_t a0 = Arow0[kp];
                uint32_t a1 = Arow8[kp];
                uint32_t a2 = Arow0[kp + 4];
                uint32_t a3 = Arow8[kp + 4];
                #pragma unroll
                for (int nt = 0; nt < 16; nt++) {
                    const uint32_t* bp = Bbase + nt * 8 * BSTRIDE + kp;
                    uint32_t b0 = bp[0];
                    uint32_t b1 = bp[4];
                    mma_bf16(acc[nt][0], acc[nt][1], acc[nt][2], acc[nt][3],
                             a0, a1, a2, a3, b0, b1);
                }
            }
        }

        // store: rows rowBase+r4 and +8; col = nbase + nt*8 + q4*2
        int row0 = rowBase + r4, row1 = row0 + 8;
        #pragma unroll
        for (int nt = 0; nt < 16; nt++) {
            int col = nbase + nt * 8 + q4 * 2;
            if (col < OUT) {
                if (row0 < n) *(float2*)(sup + (size_t)row0 * OUT + col) = make_float2(acc[nt][0], acc[nt][1]);
                if (row1 < n) *(float2*)(sup + (size_t)row1 * OUT + col) = make_float2(acc[nt][2], acc[nt][3]);
            } else {
                int c = col - OUT;
                float2 bv = *(const float2*)(bias + c);
                if (row0 < n) *(float2*)(selfb + (size_t)row0 * OUT + c) = make_float2(acc[nt][0] + bv.x, acc[nt][1] + bv.y);
                if (row1 < n) *(float2*)(selfb + (size_t)row1 * OUT + c) = make_float2(acc[nt][2] + bv.x, acc[nt][3] + bv.y);
            }
        }
        __syncwarp();
    }
}

// ---------------- sparse aggregation + relu ----------------------------------
__global__ void k_spmm128(const float* __restrict__ sup, const float* __restrict__ selfb, int n)
{
    int warp = (blockIdx.x * blockDim.x + threadIdx.x) >> 5;
    int lane = threadIdx.x & 31;
    if (warp >= n) return;
    int e0 = g_off[warp], e1 = g_off[warp + 1];

    float4 acc = make_float4(0.f, 0.f, 0.f, 0.f);
    int e = e0;
    for (; e + 1 < e1; e += 2) {
        int c0 = __ldg(&g_ecol[e]);
        int c1 = __ldg(&g_ecol[e + 1]);
        float v0 = __ldg(&g_eval[e]);
        float v1 = __ldg(&g_eval[e + 1]);
        float4 s0 = ((const float4*)(sup + (size_t)c0 * 128))[lane];
        float4 s1 = ((const float4*)(sup + (size_t)c1 * 128))[lane];
        acc.x = fmaf(v0, s0.x, fmaf(v1, s1.x, acc.x));
        acc.y = fmaf(v0, s0.y, fmaf(v1, s1.y, acc.y));
        acc.z = fmaf(v0, s0.z, fmaf(v1, s1.z, acc.z));
        acc.w = fmaf(v0, s0.w, fmaf(v1, s1.w, acc.w));
    }
    if (e < e1) {
        int c0 = __ldg(&g_ecol[e]);
        float v0 = __ldg(&g_eval[e]);
        float4 s0 = ((const float4*)(sup + (size_t)c0 * 128))[lane];
        acc.x = fmaf(v0, s0.x, acc.x);
        acc.y = fmaf(v0, s0.y, acc.y);
        acc.z = fmaf(v0, s0.z, acc.z);
        acc.w = fmaf(v0, s0.w, acc.w);
    }
    float4 sb = ((const float4*)(selfb + (size_t)warp * 128))[lane];
    float o0 = fmaxf(acc.x + sb.x, 0.f);
    float o1 = fmaxf(acc.y + sb.y, 0.f);
    float o2 = fmaxf(acc.z + sb.z, 0.f);
    float o3 = fmaxf(acc.w + sb.w, 0.f);
    float l0, l1, l2, l3;
    unsigned p01 = pack_bf2(o0, o1, l0, l1);
    unsigned p23 = pack_bf2(o2, o3, l2, l3);
    ((uint2*)(g_hh + (size_t)warp * 128))[lane] = make_uint2(p01, p23);
    ((uint2*)(g_hl + (size_t)warp * 128))[lane] = make_uint2(pack_bf2n(l0, l1), pack_bf2n(l2, l3));
}

__global__ void k_spmm64(const float* __restrict__ sup, const float* __restrict__ selfb,
                         float* __restrict__ out, int n)
{
    int warp = (blockIdx.x * blockDim.x + threadIdx.x) >> 5;
    int lane = threadIdx.x & 31;
    if (warp >= n) return;
    int e0 = g_off[warp], e1 = g_off[warp + 1];

    float2 acc = make_float2(0.f, 0.f);
    int e = e0;
    for (; e + 1 < e1; e += 2) {
        int c0 = __ldg(&g_ecol[e]);
        int c1 = __ldg(&g_ecol[e + 1]);
        float v0 = __ldg(&g_eval[e]);
        float v1 = __ldg(&g_eval[e + 1]);
        float2 s0 = ((const float2*)(sup + (size_t)c0 * 64))[lane];
        float2 s1 = ((const float2*)(sup + (size_t)c1 * 64))[lane];
        acc.x = fmaf(v0, s0.x, fmaf(v1, s1.x, acc.x));
        acc.y = fmaf(v0, s0.y, fmaf(v1, s1.y, acc.y));
    }
    if (e < e1) {
        int c0 = __ldg(&g_ecol[e]);
        float v0 = __ldg(&g_eval[e]);
        float2 s0 = ((const float2*)(sup + (size_t)c0 * 64))[lane];
        acc.x = fmaf(v0, s0.x, acc.x);
        acc.y = fmaf(v0, s0.y, acc.y);
    }
    float2 sb = ((const float2*)(selfb + (size_t)warp * 64))[lane];
    float2 o;
    o.x = fmaxf(acc.x + sb.x, 0.f);
    o.y = fmaxf(acc.y + sb.y, 0.f);
    ((float2*)(out + (size_t)warp * 64))[lane] = o;
}

// ---------------- launch -----------------------------------------------------
extern "C" void kernel_launch(void* const* d_in, const int* in_sizes, int n_in,
                              void* d_out, int out_size)
{
    const float* x    = (const float*)d_in[0];
    const int*   erow = (const int*)d_in[1];
    const int*   ecol = (const int*)d_in[2];
    const float* eval = (const float*)d_in[3];
    const float* w1   = (const float*)d_in[4];
    const float* b1   = (const float*)d_in[5];
    const float* w2   = (const float*)d_in[6];
    const float* b2   = (const float*)d_in[7];
    const float* gam  = (const float*)d_in[8];
    const float* bet  = (const float*)d_in[9];
    const float* gwn[4] = {(const float*)d_in[10], (const float*)d_in[13],
                           (const float*)d_in[16], (const float*)d_in[19]};
    const float* gws[4] = {(const float*)d_in[11], (const float*)d_in[14],
                           (const float*)d_in[17], (const float*)d_in[20]};
    const float* gb[4]  = {(const float*)d_in[12], (const float*)d_in[15],
                           (const float*)d_in[18], (const float*)d_in[21]};
    float* out = (float*)d_out;

    int n = in_sizes[0] / 128;
    int E = in_sizes[1];

    float *sup, *self;
    __nv_bfloat16 *hh, *hl, *wbh, *wbl;
    cudaGetSymbolAddress((void**)&sup, g_sup);
    cudaGetSymbolAddress((void**)&self, g_self);
    cudaGetSymbolAddress((void**)&hh, g_hh);
    cudaGetSymbolAddress((void**)&hl, g_hl);
    cudaGetSymbolAddress((void**)&wbh, g_wbh);
    cudaGetSymbolAddress((void**)&wbl, g_wbl);

    // smem sizes: B hi/lo [N2][68]u32 + 8 warps * A hi/lo [16][68]u32
    const int SM256 = (2 * 256 * 68 + 8 * 2 * 16 * 68) * 4;  // 208896 B
    const int SM128 = (2 * 128 * 68 + 8 * 2 * 16 * 68) * 4;  // 139264 B

    cudaFuncSetAttribute(k_fc, cudaFuncAttributeMaxDynamicSharedMemorySize, 192 * 1024);
    cudaFuncSetAttribute(k_mma<256>, cudaFuncAttributeMaxDynamicSharedMemorySize, SM256);
    cudaFuncSetAttribute(k_mma<128>, cudaFuncAttributeMaxDynamicSharedMemorySize, SM128);

    // weight prep + CSR build
    k_prep_w<<<512, 256>>>(gwn[0], gws[0], gwn[1], gws[1], gwn[2], gws[2], gwn[3], gws[3]);
    k_zero<<<(n + 255) / 256, 256>>>(n);
    k_hist<<<(E + 255) / 256, 256>>>(erow, E);
    k_scan<<<1, 1024>>>(n);
    k_scatter<<<(E + 255) / 256, 256>>>(erow, ecol, eval, E);

    // fc stack -> bf16 hi/lo h
    k_fc<<<148, 256, 192 * 1024>>>(x, w1, b1, w2, b2, gam, bet, n);

    int spblocks = (n + 7) / 8;

    k_mma<256><<<148, 256, SM256>>>(hh, hl, wbh + 0 * 32768, wbl + 0 * 32768, gb[0], sup, self, n);
    k_spmm128<<<spblocks, 256>>>(sup, self, n);

    k_mma<256><<<148, 256, SM256>>>(hh, hl, wbh + 1 * 32768, wbl + 1 * 32768, gb[1], sup, self, n);
    k_spmm128<<<spblocks, 256>>>(sup, self, n);

    k_mma<256><<<148, 256, SM256>>>(hh, hl, wbh + 2 * 32768, wbl + 2 * 32768, gb[2], sup, self, n);
    k_spmm128<<<spblocks, 256>>>(sup, self, n);

    k_mma<128><<<148, 256, SM128>>>(hh, hl, wbh + 3 * 32768, wbl + 3 * 32768, gb[3], sup, self, n);
    k_spmm64<<<spblocks, 256>>>(sup, self, out, n);
}

// round 5
// speedup vs baseline: 1.3192x; 1.1449x over previous
#include <cuda_runtime.h>
#include <cuda_bf16.h>
#include <cstdint>

#define MAX_N 100000
#define MAX_E 3200000

// ---------------- scratch ----------------------------------------------------
__device__ float g_sup[MAX_N * 128];
__device__ float g_self[MAX_N * 128];
__device__ __align__(16) __nv_bfloat16 g_hh[MAX_N * 128];
__device__ __align__(16) __nv_bfloat16 g_hl[MAX_N * 128];
__device__ int  g_cnt[MAX_N];
__device__ int  g_off[MAX_N + 1];
__device__ int  g_cur[MAX_N];
__device__ int  g_bsum[128];
__device__ int  g_bscan[128];
__device__ __align__(8) int2 g_epack[MAX_E];   // (col, val bits)

// ---------------- helpers ----------------------------------------------------
__device__ __forceinline__ unsigned pack_bf2(float a, float b, float& ra, float& rb) {
    __nv_bfloat16 ha = __float2bfloat16_rn(a), hb = __float2bfloat16_rn(b);
    ra = a - __bfloat162float(ha);
    rb = b - __bfloat162float(hb);
    return ((unsigned)__bfloat16_as_ushort(hb) << 16) | (unsigned)__bfloat16_as_ushort(ha);
}
__device__ __forceinline__ unsigned pack_bf2n(float a, float b) {
    __nv_bfloat16 ha = __float2bfloat16_rn(a), hb = __float2bfloat16_rn(b);
    return ((unsigned)__bfloat16_as_ushort(hb) << 16) | (unsigned)__bfloat16_as_ushort(ha);
}

__device__ __forceinline__ void mma_bf16(float& d0, float& d1, float& d2, float& d3,
                                         uint32_t a0, uint32_t a1, uint32_t a2, uint32_t a3,
                                         uint32_t b0, uint32_t b1) {
    asm volatile("mma.sync.aligned.m16n8k16.row.col.f32.bf16.bf16.f32 "
                 "{%0,%1,%2,%3}, {%4,%5,%6,%7}, {%8,%9}, {%0,%1,%2,%3};"
                 : "+f"(d0), "+f"(d1), "+f"(d2), "+f"(d3)
                 : "r"(a0), "r"(a1), "r"(a2), "r"(a3), "r"(b0), "r"(b1));
}

// ---------------- CSR build --------------------------------------------------
__global__ void k_zero(int n) {
    int i = blockIdx.x * blockDim.x + threadIdx.x;
    if (i < n) g_cnt[i] = 0;
}
__global__ void k_hist(const int* __restrict__ rows, int E) {
    int i = blockIdx.x * blockDim.x + threadIdx.x;
    if (i < E) atomicAdd(&g_cnt[rows[i]], 1);
}
__global__ void k_scan1(int n) {
    __shared__ int buf[2][1024];
    int i = blockIdx.x * 1024 + threadIdx.x;
    int v = (i < n) ? g_cnt[i] : 0;
    int src = 0;
    buf[0][threadIdx.x] = v;
    for (int ofs = 1; ofs < 1024; ofs <<= 1) {
        __syncthreads();
        int t = buf[src][threadIdx.x];
        if ((int)threadIdx.x >= ofs) t += buf[src][threadIdx.x - ofs];
        buf[1 - src][threadIdx.x] = t;
        src ^= 1;
    }
    __syncthreads();
    int incl = buf[src][threadIdx.x];
    if (i < n) g_cnt[i] = incl;
    if (threadIdx.x == 1023) g_bsum[blockIdx.x] = incl;
}
__global__ void k_scan2(int nb) {
    __shared__ int buf[2][128];
    int tid = threadIdx.x;
    int v = (tid < nb) ? g_bsum[tid] : 0;
    int src = 0;
    buf[0][tid] = v;
    for (int ofs = 1; ofs < 128; ofs <<= 1) {
        __syncthreads();
        int t = buf[src][tid];
        if (tid >= ofs) t += buf[src][tid - ofs];
        buf[1 - src][tid] = t;
        src ^= 1;
    }
    __syncthreads();
    g_bscan[tid] = buf[src][tid];
}
// writes g_off and g_cur (fused cursor)
__global__ void k_scan3(int n) {
    int i = blockIdx.x * blockDim.x + threadIdx.x;
    if (i < n) {
        int blk = i >> 10;
        int pre = blk ? g_bscan[blk - 1] : 0;
        g_off[i + 1] = g_cnt[i] + pre;
        if (i == 0) g_off[0] = 0;
        int prev = (i & 1023) ? g_cnt[i - 1] : 0;
        g_cur[i] = prev + pre;
    }
}
__global__ void k_scatter(const int* __restrict__ rows, const int* __restrict__ cols,
                          const float* __restrict__ vals, int E) {
    int e = blockIdx.x * blockDim.x + threadIdx.x;
    if (e < E) {
        int r = rows[e];
        int p = atomicAdd(&g_cur[r], 1);
        g_epack[p] = make_int2(cols[e], __float_as_int(vals[e]));
    }
}

// ---------------- HMMA fc: h = LN(relu(relu(x@w1T+b1)@w2T+b2)) -> bf16 hi/lo --
// Persistent 148 CTAs x 8 warps; w1/w2 split hi/lo into smem once; each warp
// owns a 16-row task: x split -> MMA(w1) -> relu -> smem -> MMA(w2) -> relu+LN.
__global__ void __launch_bounds__(256, 1) k_fc(
    const float* __restrict__ x,
    const float* __restrict__ w1, const float* __restrict__ b1,
    const float* __restrict__ w2, const float* __restrict__ b2,
    const float* __restrict__ gamma, const float* __restrict__ beta, int n)
{
    constexpr int BSTRIDE = 68;
    extern __shared__ __align__(16) uint32_t sm32[];
    uint32_t* W1h = sm32;                 // [128][68]
    uint32_t* W1l = W1h + 128 * BSTRIDE;
    uint32_t* W2h = W1l + 128 * BSTRIDE;
    uint32_t* W2l = W2h + 128 * BSTRIDE;
    int tid = threadIdx.x, wid = tid >> 5, lane = tid & 31;
    uint32_t* Aw  = W2l + 128 * BSTRIDE + wid * (2 * 16 * BSTRIDE);
    uint32_t* Ahi = Aw;
    uint32_t* Alo = Aw + 16 * BSTRIDE;

    // stage weights hi/lo ([out][in] row-major == B[n][k])
    for (int i = tid; i < 128 * 64; i += 256) {
        int nn = i >> 6, q = i & 63;
        float2 a = *(const float2*)(w1 + nn * 128 + q * 2);
        float r0, r1;
        uint32_t h = pack_bf2(a.x, a.y, r0, r1);
        W1h[nn * BSTRIDE + q] = h;
        W1l[nn * BSTRIDE + q] = pack_bf2n(r0, r1);
        float2 b = *(const float2*)(w2 + nn * 128 + q * 2);
        uint32_t h2 = pack_bf2(b.x, b.y, r0, r1);
        W2h[nn * BSTRIDE + q] = h2;
        W2l[nn * BSTRIDE + q] = pack_bf2n(r0, r1);
    }
    __syncthreads();

    int q4 = lane & 3, r4 = lane >> 2;
    int ntiles = (n + 15) >> 4;

    for (int t = blockIdx.x * 8 + wid; t < ntiles; t += 148 * 8) {
        int rowBase = t << 4;
        // stage x (fp32 -> bf16 hi/lo) into warp smem
        for (int i = lane; i < 512; i += 32) {
            int r = i >> 5, f4 = i & 31;
            int grow = rowBase + r;
            if (grow > n - 1) grow = n - 1;
            float4 v = ((const float4*)(x + (size_t)grow * 128))[f4];
            float r0, r1;
            uint32_t h0 = pack_bf2(v.x, v.y, r0, r1);
            uint32_t l0 = pack_bf2n(r0, r1);
            uint32_t h1 = pack_bf2(v.z, v.w, r0, r1);
            uint32_t l1 = pack_bf2n(r0, r1);
            Ahi[r * BSTRIDE + f4 * 2] = h0;
            Ahi[r * BSTRIDE + f4 * 2 + 1] = h1;
            Alo[r * BSTRIDE + f4 * 2] = l0;
            Alo[r * BSTRIDE + f4 * 2 + 1] = l1;
        }
        __syncwarp();

        float acc[16][4];
        #pragma unroll
        for (int nt = 0; nt < 16; nt++)
            #pragma unroll
            for (int j = 0; j < 4; j++) acc[nt][j] = 0.f;

        // ---- layer 1
        #pragma unroll 1
        for (int pass = 0; pass < 3; pass++) {
            const uint32_t* As = (pass == 1) ? Alo : Ahi;
            const uint32_t* Bs = (pass == 2) ? W1l : W1h;
            const uint32_t* Arow0 = As + r4 * BSTRIDE + q4;
            const uint32_t* Arow8 = As + (r4 + 8) * BSTRIDE + q4;
            const uint32_t* Bbase = Bs + r4 * BSTRIDE + q4;
            #pragma unroll 2
            for (int ks = 0; ks < 8; ks++) {
                int kp = ks * 8;
                uint32_t a0 = Arow0[kp], a1 = Arow8[kp];
                uint32_t a2 = Arow0[kp + 4], a3 = Arow8[kp + 4];
                #pragma unroll
                for (int nt = 0; nt < 16; nt++) {
                    const uint32_t* bp = Bbase + nt * 8 * BSTRIDE + kp;
                    mma_bf16(acc[nt][0], acc[nt][1], acc[nt][2], acc[nt][3],
                             a0, a1, a2, a3, bp[0], bp[4]);
                }
            }
        }
        __syncwarp();
        // relu + b1, write back as next A
        #pragma unroll
        for (int nt = 0; nt < 16; nt++) {
            int col = nt * 8 + q4 * 2;
            float2 bv = *(const float2*)(b1 + col);
            float v0 = fmaxf(acc[nt][0] + bv.x, 0.f);
            float v1 = fmaxf(acc[nt][1] + bv.y, 0.f);
            float v2 = fmaxf(acc[nt][2] + bv.x, 0.f);
            float v3 = fmaxf(acc[nt][3] + bv.y, 0.f);
            float r0, r1;
            uint32_t h0 = pack_bf2(v0, v1, r0, r1);
            Ahi[r4 * BSTRIDE + nt * 4 + q4] = h0;
            Alo[r4 * BSTRIDE + nt * 4 + q4] = pack_bf2n(r0, r1);
            uint32_t h1 = pack_bf2(v2, v3, r0, r1);
            Ahi[(r4 + 8) * BSTRIDE + nt * 4 + q4] = h1;
            Alo[(r4 + 8) * BSTRIDE + nt * 4 + q4] = pack_bf2n(r0, r1);
        }
        __syncwarp();

        #pragma unroll
        for (int nt = 0; nt < 16; nt++)
            #pragma unroll
            for (int j = 0; j < 4; j++) acc[nt][j] = 0.f;

        // ---- layer 2
        #pragma unroll 1
        for (int pass = 0; pass < 3; pass++) {
            const uint32_t* As = (pass == 1) ? Alo : Ahi;
            const uint32_t* Bs = (pass == 2) ? W2l : W2h;
            const uint32_t* Arow0 = As + r4 * BSTRIDE + q4;
            const uint32_t* Arow8 = As + (r4 + 8) * BSTRIDE + q4;
            const uint32_t* Bbase = Bs + r4 * BSTRIDE + q4;
            #pragma unroll 2
            for (int ks = 0; ks < 8; ks++) {
                int kp = ks * 8;
                uint32_t a0 = Arow0[kp], a1 = Arow8[kp];
                uint32_t a2 = Arow0[kp + 4], a3 = Arow8[kp + 4];
                #pragma unroll
                for (int nt = 0; nt < 16; nt++) {
                    const uint32_t* bp = Bbase + nt * 8 * BSTRIDE + kp;
                    mma_bf16(acc[nt][0], acc[nt][1], acc[nt][2], acc[nt][3],
                             a0, a1, a2, a3, bp[0], bp[4]);
                }
            }
        }
        __syncwarp();

        // relu + b2, then layernorm per row (quad-shuffle reduction)
        float s0 = 0.f, q0 = 0.f, s1 = 0.f, q1 = 0.f;
        #pragma unroll
        for (int nt = 0; nt < 16; nt++) {
            int col = nt * 8 + q4 * 2;
            float2 bv = *(const float2*)(b2 + col);
            float v0 = fmaxf(acc[nt][0] + bv.x, 0.f);
            float v1 = fmaxf(acc[nt][1] + bv.y, 0.f);
            float v2 = fmaxf(acc[nt][2] + bv.x, 0.f);
            float v3 = fmaxf(acc[nt][3] + bv.y, 0.f);
            acc[nt][0] = v0; acc[nt][1] = v1; acc[nt][2] = v2; acc[nt][3] = v3;
            s0 += v0 + v1; q0 = fmaf(v0, v0, fmaf(v1, v1, q0));
            s1 += v2 + v3; q1 = fmaf(v2, v2, fmaf(v3, v3, q1));
        }
        #pragma unroll
        for (int o = 1; o <= 2; o <<= 1) {
            s0 += __shfl_xor_sync(0xffffffffu, s0, o);
            q0 += __shfl_xor_sync(0xffffffffu, q0, o);
            s1 += __shfl_xor_sync(0xffffffffu, s1, o);
            q1 += __shfl_xor_sync(0xffffffffu, q1, o);
        }
        float mean0 = s0 * (1.f / 128.f);
        float var0 = fmaxf((q0 - s0 * mean0) * (1.f / 127.f), 0.f);
        float inv0 = 1.f / (sqrtf(var0) + 1e-6f);
        float mean1 = s1 * (1.f / 128.f);
        float var1 = fmaxf((q1 - s1 * mean1) * (1.f / 127.f), 0.f);
        float inv1 = 1.f / (sqrtf(var1) + 1e-6f);

        #pragma unroll
        for (int nt = 0; nt < 16; nt++) {
            int col = nt * 8 + q4 * 2;
            float2 gg = *(const float2*)(gamma + col);
            float2 be = *(const float2*)(beta + col);
            float o0 = gg.x * (acc[nt][0] - mean0) * inv0 + be.x;
            float o1 = gg.y * (acc[nt][1] - mean0) * inv0 + be.y;
            float o2 = gg.x * (acc[nt][2] - mean1) * inv1 + be.x;
            float o3 = gg.y * (acc[nt][3] - mean1) * inv1 + be.y;
            float r0, r1;
            uint32_t h0 = pack_bf2(o0, o1, r0, r1);
            Ahi[r4 * BSTRIDE + nt * 4 + q4] = h0;
            Alo[r4 * BSTRIDE + nt * 4 + q4] = pack_bf2n(r0, r1);
            uint32_t h1 = pack_bf2(o2, o3, r0, r1);
            Ahi[(r4 + 8) * BSTRIDE + nt * 4 + q4] = h1;
            Alo[(r4 + 8) * BSTRIDE + nt * 4 + q4] = pack_bf2n(r0, r1);
        }
        __syncwarp();
        // vectorized copy smem -> g_hh/g_hl
        for (int idx = lane; idx < 256; idx += 32) {
            int r = idx >> 4, qv = idx & 15;
            int row = rowBase + r;
            if (row < n) {
                uint4 vh = *(const uint4*)(Ahi + r * BSTRIDE + qv * 4);
                uint4 vl = *(const uint4*)(Alo + r * BSTRIDE + qv * 4);
                ((uint4*)(g_hh + (size_t)row * 128))[qv] = vh;
                ((uint4*)(g_hl + (size_t)row * 128))[qv] = vl;
            }
        }
        __syncwarp();
    }
}

// ---------------- HMMA GCN GEMM: [sup | selfb] = h @ [wn | ws] (+bias) -------
template <int N2>
__global__ void __launch_bounds__(256, 1) k_mma(
    const __nv_bfloat16* __restrict__ hh, const __nv_bfloat16* __restrict__ hl,
    const float* __restrict__ wn, const float* __restrict__ ws,
    const float* __restrict__ bias,
    float* __restrict__ sup, float* __restrict__ selfb, int n)
{
    constexpr int OUT = N2 / 2;
    constexpr int NHALF = N2 / 128;
    constexpr int BSTRIDE = 68;
    extern __shared__ __align__(16) uint32_t sm32[];
    uint32_t* Bh = sm32;                   // [N2][68]
    uint32_t* Bl = Bh + N2 * BSTRIDE;
    int tid = threadIdx.x, wid = tid >> 5, lane = tid & 31;
    uint32_t* Aw  = Bl + N2 * BSTRIDE + wid * (2 * 16 * BSTRIDE);
    uint32_t* Ahi = Aw;
    uint32_t* Alo = Aw + 16 * BSTRIDE;

    // stage + split weights (w is [K=128][O] k-major; B[n][k] needed)
    for (int i = tid; i < N2 * 64; i += 256) {
        int kp = i / N2, nn = i % N2;      // kp = k-pair
        float a0, a1;
        if (nn < OUT) {
            a0 = wn[(2 * kp) * OUT + nn];
            a1 = wn[(2 * kp + 1) * OUT + nn];
        } else {
            a0 = ws[(2 * kp) * OUT + nn - OUT];
            a1 = ws[(2 * kp + 1) * OUT + nn - OUT];
        }
        float r0, r1;
        uint32_t h = pack_bf2(a0, a1, r0, r1);
        Bh[nn * BSTRIDE + kp] = h;
        Bl[nn * BSTRIDE + kp] = pack_bf2n(r0, r1);
    }
    __syncthreads();

    int q4 = lane & 3, r4 = lane >> 2;
    int nRowTiles = (n + 15) >> 4;
    int ntasks = nRowTiles * NHALF;

    for (int t = blockIdx.x * 8 + wid; t < ntasks; t += 148 * 8) {
        int rowTile = (NHALF == 2) ? (t >> 1) : t;
        int half = (NHALF == 2) ? (t & 1) : 0;
        int rowBase = rowTile << 4;

        #pragma unroll
        for (int i = 0; i < 8; i++) {
            int idx = i * 32 + lane;
            int r = idx >> 4, q = idx & 15;
            int grow = rowBase + r;
            if (grow > n - 1) grow = n - 1;
            uint4 vh = ((const uint4*)(hh + (size_t)grow * 128))[q];
            uint4 vl = ((const uint4*)(hl + (size_t)grow * 128))[q];
            *(uint4*)(Ahi + r * BSTRIDE + q * 4) = vh;
            *(uint4*)(Alo + r * BSTRIDE + q * 4) = vl;
        }
        __syncwarp();

        float acc[16][4];
        #pragma unroll
        for (int nt = 0; nt < 16; nt++)
            #pragma unroll
            for (int j = 0; j < 4; j++) acc[nt][j] = 0.f;

        int nbase = half * 128;
        #pragma unroll 1
        for (int pass = 0; pass < 3; pass++) {
            const uint32_t* As = (pass == 1) ? Alo : Ahi;
            const uint32_t* Bs = (pass == 2) ? Bl : Bh;
            const uint32_t* Arow0 = As + r4 * BSTRIDE + q4;
            const uint32_t* Arow8 = As + (r4 + 8) * BSTRIDE + q4;
            const uint32_t* Bbase = Bs + (nbase + r4) * BSTRIDE + q4;
            #pragma unroll 2
            for (int ks = 0; ks < 8; ks++) {
                int kp = ks * 8;
                uint32_t a0 = Arow0[kp], a1 = Arow8[kp];
                uint32_t a2 = Arow0[kp + 4], a3 = Arow8[kp + 4];
                #pragma unroll
                for (int nt = 0; nt < 16; nt++) {
                    const uint32_t* bp = Bbase + nt * 8 * BSTRIDE + kp;
                    mma_bf16(acc[nt][0], acc[nt][1], acc[nt][2], acc[nt][3],
                             a0, a1, a2, a3, bp[0], bp[4]);
                }
            }
        }

        int row0 = rowBase + r4, row1 = row0 + 8;
        #pragma unroll
        for (int nt = 0; nt < 16; nt++) {
            int col = nbase + nt * 8 + q4 * 2;
            if (col < OUT) {
                if (row0 < n) *(float2*)(sup + (size_t)row0 * OUT + col) = make_float2(acc[nt][0], acc[nt][1]);
                if (row1 < n) *(float2*)(sup + (size_t)row1 * OUT + col) = make_float2(acc[nt][2], acc[nt][3]);
            } else {
                int c = col - OUT;
                float2 bv = *(const float2*)(bias + c);
                if (row0 < n) *(float2*)(selfb + (size_t)row0 * OUT + c) = make_float2(acc[nt][0] + bv.x, acc[nt][1] + bv.y);
                if (row1 < n) *(float2*)(selfb + (size_t)row1 * OUT + c) = make_float2(acc[nt][2] + bv.x, acc[nt][3] + bv.y);
            }
        }
        __syncwarp();
    }
}

// ---------------- sparse aggregation + relu ----------------------------------
__global__ void k_spmm128(const float* __restrict__ sup, const float* __restrict__ selfb, int n)
{
    int warp = (blockIdx.x * blockDim.x + threadIdx.x) >> 5;
    int lane = threadIdx.x & 31;
    if (warp >= n) return;
    int e0 = g_off[warp], e1 = g_off[warp + 1];

    float4 acc = make_float4(0.f, 0.f, 0.f, 0.f);
    int e = e0;
    for (; e + 1 < e1; e += 2) {
        int2 p0 = __ldg(&g_epack[e]);
        int2 p1 = __ldg(&g_epack[e + 1]);
        float v0 = __int_as_float(p0.y);
        float v1 = __int_as_float(p1.y);
        float4 s0 = ((const float4*)(sup + (size_t)p0.x * 128))[lane];
        float4 s1 = ((const float4*)(sup + (size_t)p1.x * 128))[lane];
        acc.x = fmaf(v0, s0.x, fmaf(v1, s1.x, acc.x));
        acc.y = fmaf(v0, s0.y, fmaf(v1, s1.y, acc.y));
        acc.z = fmaf(v0, s0.z, fmaf(v1, s1.z, acc.z));
        acc.w = fmaf(v0, s0.w, fmaf(v1, s1.w, acc.w));
    }
    if (e < e1) {
        int2 p0 = __ldg(&g_epack[e]);
        float v0 = __int_as_float(p0.y);
        float4 s0 = ((const float4*)(sup + (size_t)p0.x * 128))[lane];
        acc.x = fmaf(v0, s0.x, acc.x);
        acc.y = fmaf(v0, s0.y, acc.y);
        acc.z = fmaf(v0, s0.z, acc.z);
        acc.w = fmaf(v0, s0.w, acc.w);
    }
    float4 sb = ((const float4*)(selfb + (size_t)warp * 128))[lane];
    float o0 = fmaxf(acc.x + sb.x, 0.f);
    float o1 = fmaxf(acc.y + sb.y, 0.f);
    float o2 = fmaxf(acc.z + sb.z, 0.f);
    float o3 = fmaxf(acc.w + sb.w, 0.f);
    float l0, l1, l2, l3;
    unsigned p01 = pack_bf2(o0, o1, l0, l1);
    unsigned p23 = pack_bf2(o2, o3, l2, l3);
    ((uint2*)(g_hh + (size_t)warp * 128))[lane] = make_uint2(p01, p23);
    ((uint2*)(g_hl + (size_t)warp * 128))[lane] = make_uint2(pack_bf2n(l0, l1), pack_bf2n(l2, l3));
}

__global__ void k_spmm64(const float* __restrict__ sup, const float* __restrict__ selfb,
                         float* __restrict__ out, int n)
{
    int warp = (blockIdx.x * blockDim.x + threadIdx.x) >> 5;
    int lane = threadIdx.x & 31;
    if (warp >= n) return;
    int e0 = g_off[warp], e1 = g_off[warp + 1];

    float2 acc = make_float2(0.f, 0.f);
    int e = e0;
    for (; e + 1 < e1; e += 2) {
        int2 p0 = __ldg(&g_epack[e]);
        int2 p1 = __ldg(&g_epack[e + 1]);
        float v0 = __int_as_float(p0.y);
        float v1 = __int_as_float(p1.y);
        float2 s0 = ((const float2*)(sup + (size_t)p0.x * 64))[lane];
        float2 s1 = ((const float2*)(sup + (size_t)p1.x * 64))[lane];
        acc.x = fmaf(v0, s0.x, fmaf(v1, s1.x, acc.x));
        acc.y = fmaf(v0, s0.y, fmaf(v1, s1.y, acc.y));
    }
    if (e < e1) {
        int2 p0 = __ldg(&g_epack[e]);
        float v0 = __int_as_float(p0.y);
        float2 s0 = ((const float2*)(sup + (size_t)p0.x * 64))[lane];
        acc.x = fmaf(v0, s0.x, acc.x);
        acc.y = fmaf(v0, s0.y, acc.y);
    }
    float2 sb = ((const float2*)(selfb + (size_t)warp * 64))[lane];
    float2 o;
    o.x = fmaxf(acc.x + sb.x, 0.f);
    o.y = fmaxf(acc.y + sb.y, 0.f);
    ((float2*)(out + (size_t)warp * 64))[lane] = o;
}

// ---------------- launch -----------------------------------------------------
extern "C" void kernel_launch(void* const* d_in, const int* in_sizes, int n_in,
                              void* d_out, int out_size)
{
    const float* x    = (const float*)d_in[0];
    const int*   erow = (const int*)d_in[1];
    const int*   ecol = (const int*)d_in[2];
    const float* eval = (const float*)d_in[3];
    const float* w1   = (const float*)d_in[4];
    const float* b1   = (const float*)d_in[5];
    const float* w2   = (const float*)d_in[6];
    const float* b2   = (const float*)d_in[7];
    const float* gam  = (const float*)d_in[8];
    const float* bet  = (const float*)d_in[9];
    const float* gwn[4] = {(const float*)d_in[10], (const float*)d_in[13],
                           (const float*)d_in[16], (const float*)d_in[19]};
    const float* gws[4] = {(const float*)d_in[11], (const float*)d_in[14],
                           (const float*)d_in[17], (const float*)d_in[20]};
    const float* gb[4]  = {(const float*)d_in[12], (const float*)d_in[15],
                           (const float*)d_in[18], (const float*)d_in[21]};
    float* out = (float*)d_out;

    int n = in_sizes[0] / 128;
    int E = in_sizes[1];

    float *sup, *self;
    __nv_bfloat16 *hh, *hl;
    cudaGetSymbolAddress((void**)&sup, g_sup);
    cudaGetSymbolAddress((void**)&self, g_self);
    cudaGetSymbolAddress((void**)&hh, g_hh);
    cudaGetSymbolAddress((void**)&hl, g_hl);

    const int SMFC  = (4 * 128 * 68 + 8 * 2 * 16 * 68) * 4;   // 208896
    const int SM256 = (2 * 256 * 68 + 8 * 2 * 16 * 68) * 4;   // 208896
    const int SM128 = (2 * 128 * 68 + 8 * 2 * 16 * 68) * 4;   // 139264

    cudaFuncSetAttribute(k_fc, cudaFuncAttributeMaxDynamicSharedMemorySize, SMFC);
    cudaFuncSetAttribute(k_mma<256>, cudaFuncAttributeMaxDynamicSharedMemorySize, SM256);
    cudaFuncSetAttribute(k_mma<128>, cudaFuncAttributeMaxDynamicSharedMemorySize, SM128);

    int nb = (n + 1023) / 1024;
    int spblocks = (n + 7) / 8;

    // 0-3 ordered so launch #3 (profiled) = k_mma<256> layer 1
    k_zero<<<(n + 255) / 256, 256>>>(n);
    k_fc<<<148, 256, SMFC>>>(x, w1, b1, w2, b2, gam, bet, n);
    k_hist<<<(E + 255) / 256, 256>>>(erow, E);
    k_mma<256><<<148, 256, SM256>>>(hh, hl, gwn[0], gws[0], gb[0], sup, self, n);

    k_scan1<<<nb, 1024>>>(n);
    k_scan2<<<1, 128>>>(nb);
    k_scan3<<<(n + 255) / 256, 256>>>(n);
    k_scatter<<<(E + 255) / 256, 256>>>(erow, ecol, eval, E);

    k_spmm128<<<spblocks, 256>>>(sup, self, n);

    k_mma<256><<<148, 256, SM256>>>(hh, hl, gwn[1], gws[1], gb[1], sup, self, n);
    k_spmm128<<<spblocks, 256>>>(sup, self, n);

    k_mma<256><<<148, 256, SM256>>>(hh, hl, gwn[2], gws[2], gb[2], sup, self, n);
    k_spmm128<<<spblocks, 256>>>(sup, self, n);

    k_mma<128><<<148, 256, SM128>>>(hh, hl, gwn[3], gws[3], gb[3], sup, self, n);
    k_spmm64<<<spblocks, 256>>>(sup, self, out, n);
}

// round 6
// speedup vs baseline: 1.3521x; 1.0249x over previous
#include <cuda_runtime.h>
#include <cuda_bf16.h>
#include <cstdint>

#define MAX_N 100000
#define MAX_E 3200000

// ---------------- scratch ----------------------------------------------------
__device__ float g_sup[MAX_N * 128];
__device__ float g_self[MAX_N * 128];
__device__ __align__(16) __nv_bfloat16 g_hh[MAX_N * 128];
__device__ __align__(16) __nv_bfloat16 g_hl[MAX_N * 128];
__device__ int  g_cnt[MAX_N];
__device__ int  g_off[MAX_N + 1];
__device__ int  g_cur[MAX_N];
__device__ int  g_bsum[128];
__device__ int  g_bscan[128];
__device__ __align__(8) int2 g_epack[MAX_E];   // (col, val bits)

// ---------------- helpers ----------------------------------------------------
__device__ __forceinline__ unsigned pack_bf2(float a, float b, float& ra, float& rb) {
    __nv_bfloat16 ha = __float2bfloat16_rn(a), hb = __float2bfloat16_rn(b);
    ra = a - __bfloat162float(ha);
    rb = b - __bfloat162float(hb);
    return ((unsigned)__bfloat16_as_ushort(hb) << 16) | (unsigned)__bfloat16_as_ushort(ha);
}
__device__ __forceinline__ unsigned pack_bf2n(float a, float b) {
    __nv_bfloat16 ha = __float2bfloat16_rn(a), hb = __float2bfloat16_rn(b);
    return ((unsigned)__bfloat16_as_ushort(hb) << 16) | (unsigned)__bfloat16_as_ushort(ha);
}

__device__ __forceinline__ void mma_bf16(float& d0, float& d1, float& d2, float& d3,
                                         uint32_t a0, uint32_t a1, uint32_t a2, uint32_t a3,
                                         uint32_t b0, uint32_t b1) {
    asm volatile("mma.sync.aligned.m16n8k16.row.col.f32.bf16.bf16.f32 "
                 "{%0,%1,%2,%3}, {%4,%5,%6,%7}, {%8,%9}, {%0,%1,%2,%3};"
                 : "+f"(d0), "+f"(d1), "+f"(d2), "+f"(d3)
                 : "r"(a0), "r"(a1), "r"(a2), "r"(a3), "r"(b0), "r"(b1));
}

// ---------------- CSR build --------------------------------------------------
__global__ void k_zero(int n) {
    int i = blockIdx.x * blockDim.x + threadIdx.x;
    if (i < n) g_cnt[i] = 0;
}
__global__ void k_hist(const int* __restrict__ rows, int E) {
    int i = blockIdx.x * blockDim.x + threadIdx.x;
    if (i < E) atomicAdd(&g_cnt[rows[i]], 1);
}
__global__ void k_scan1(int n) {
    __shared__ int buf[2][1024];
    int i = blockIdx.x * 1024 + threadIdx.x;
    int v = (i < n) ? g_cnt[i] : 0;
    int src = 0;
    buf[0][threadIdx.x] = v;
    for (int ofs = 1; ofs < 1024; ofs <<= 1) {
        __syncthreads();
        int t = buf[src][threadIdx.x];
        if ((int)threadIdx.x >= ofs) t += buf[src][threadIdx.x - ofs];
        buf[1 - src][threadIdx.x] = t;
        src ^= 1;
    }
    __syncthreads();
    int incl = buf[src][threadIdx.x];
    if (i < n) g_cnt[i] = incl;
    if (threadIdx.x == 1023) g_bsum[blockIdx.x] = incl;
}
__global__ void k_scan2(int nb) {
    __shared__ int buf[2][128];
    int tid = threadIdx.x;
    int v = (tid < nb) ? g_bsum[tid] : 0;
    int src = 0;
    buf[0][tid] = v;
    for (int ofs = 1; ofs < 128; ofs <<= 1) {
        __syncthreads();
        int t = buf[src][tid];
        if (tid >= ofs) t += buf[src][tid - ofs];
        buf[1 - src][tid] = t;
        src ^= 1;
    }
    __syncthreads();
    g_bscan[tid] = buf[src][tid];
}
__global__ void k_scan3(int n) {
    int i = blockIdx.x * blockDim.x + threadIdx.x;
    if (i < n) {
        int blk = i >> 10;
        int pre = blk ? g_bscan[blk - 1] : 0;
        g_off[i + 1] = g_cnt[i] + pre;
        if (i == 0) g_off[0] = 0;
        int prev = (i & 1023) ? g_cnt[i - 1] : 0;
        g_cur[i] = prev + pre;
    }
}
__global__ void k_scatter(const int* __restrict__ rows, const int* __restrict__ cols,
                          const float* __restrict__ vals, int E) {
    int e = blockIdx.x * blockDim.x + threadIdx.x;
    if (e < E) {
        int r = rows[e];
        int p = atomicAdd(&g_cur[r], 1);
        g_epack[p] = make_int2(cols[e], __float_as_int(vals[e]));
    }
}

// ---------------- HMMA fc: h = LN(relu(relu(x@w1T+b1)@w2T+b2)) -> bf16 hi/lo --
__global__ void __launch_bounds__(256, 1) k_fc(
    const float* __restrict__ x,
    const float* __restrict__ w1, const float* __restrict__ b1,
    const float* __restrict__ w2, const float* __restrict__ b2,
    const float* __restrict__ gamma, const float* __restrict__ beta, int n)
{
    constexpr int BSTRIDE = 68;
    extern __shared__ __align__(16) uint32_t sm32[];
    uint32_t* W1h = sm32;                 // [128][68]
    uint32_t* W1l = W1h + 128 * BSTRIDE;
    uint32_t* W2h = W1l + 128 * BSTRIDE;
    uint32_t* W2l = W2h + 128 * BSTRIDE;
    int tid = threadIdx.x, wid = tid >> 5, lane = tid & 31;
    uint32_t* Aw  = W2l + 128 * BSTRIDE + wid * (2 * 16 * BSTRIDE);
    uint32_t* Ahi = Aw;
    uint32_t* Alo = Aw + 16 * BSTRIDE;

    for (int i = tid; i < 128 * 64; i += 256) {
        int nn = i >> 6, q = i & 63;
        float2 a = *(const float2*)(w1 + nn * 128 + q * 2);
        float r0, r1;
        uint32_t h = pack_bf2(a.x, a.y, r0, r1);
        W1h[nn * BSTRIDE + q] = h;
        W1l[nn * BSTRIDE + q] = pack_bf2n(r0, r1);
        float2 b = *(const float2*)(w2 + nn * 128 + q * 2);
        uint32_t h2 = pack_bf2(b.x, b.y, r0, r1);
        W2h[nn * BSTRIDE + q] = h2;
        W2l[nn * BSTRIDE + q] = pack_bf2n(r0, r1);
    }
    __syncthreads();

    int q4 = lane & 3, r4 = lane >> 2;
    int ntiles = (n + 15) >> 4;

    for (int t = blockIdx.x * 8 + wid; t < ntiles; t += 148 * 8) {
        int rowBase = t << 4;
        for (int i = lane; i < 512; i += 32) {
            int r = i >> 5, f4 = i & 31;
            int grow = rowBase + r;
            if (grow > n - 1) grow = n - 1;
            float4 v = ((const float4*)(x + (size_t)grow * 128))[f4];
            float r0, r1;
            uint32_t h0 = pack_bf2(v.x, v.y, r0, r1);
            uint32_t l0 = pack_bf2n(r0, r1);
            uint32_t h1 = pack_bf2(v.z, v.w, r0, r1);
            uint32_t l1 = pack_bf2n(r0, r1);
            Ahi[r * BSTRIDE + f4 * 2] = h0;
            Ahi[r * BSTRIDE + f4 * 2 + 1] = h1;
            Alo[r * BSTRIDE + f4 * 2] = l0;
            Alo[r * BSTRIDE + f4 * 2 + 1] = l1;
        }
        __syncwarp();

        float acc[16][4];
        #pragma unroll
        for (int nt = 0; nt < 16; nt++)
            #pragma unroll
            for (int j = 0; j < 4; j++) acc[nt][j] = 0.f;

        #pragma unroll 1
        for (int pass = 0; pass < 3; pass++) {
            const uint32_t* As = (pass == 1) ? Alo : Ahi;
            const uint32_t* Bs = (pass == 2) ? W1l : W1h;
            const uint32_t* Arow0 = As + r4 * BSTRIDE + q4;
            const uint32_t* Arow8 = As + (r4 + 8) * BSTRIDE + q4;
            const uint32_t* Bbase = Bs + r4 * BSTRIDE + q4;
            #pragma unroll 2
            for (int ks = 0; ks < 8; ks++) {
                int kp = ks * 8;
                uint32_t a0 = Arow0[kp], a1 = Arow8[kp];
                uint32_t a2 = Arow0[kp + 4], a3 = Arow8[kp + 4];
                #pragma unroll
                for (int nt = 0; nt < 16; nt++) {
                    const uint32_t* bp = Bbase + nt * 8 * BSTRIDE + kp;
                    mma_bf16(acc[nt][0], acc[nt][1], acc[nt][2], acc[nt][3],
                             a0, a1, a2, a3, bp[0], bp[4]);
                }
            }
        }
        __syncwarp();
        #pragma unroll
        for (int nt = 0; nt < 16; nt++) {
            int col = nt * 8 + q4 * 2;
            float2 bv = *(const float2*)(b1 + col);
            float v0 = fmaxf(acc[nt][0] + bv.x, 0.f);
            float v1 = fmaxf(acc[nt][1] + bv.y, 0.f);
            float v2 = fmaxf(acc[nt][2] + bv.x, 0.f);
            float v3 = fmaxf(acc[nt][3] + bv.y, 0.f);
            float r0, r1;
            uint32_t h0 = pack_bf2(v0, v1, r0, r1);
            Ahi[r4 * BSTRIDE + nt * 4 + q4] = h0;
            Alo[r4 * BSTRIDE + nt * 4 + q4] = pack_bf2n(r0, r1);
            uint32_t h1 = pack_bf2(v2, v3, r0, r1);
            Ahi[(r4 + 8) * BSTRIDE + nt * 4 + q4] = h1;
            Alo[(r4 + 8) * BSTRIDE + nt * 4 + q4] = pack_bf2n(r0, r1);
        }
        __syncwarp();

        #pragma unroll
        for (int nt = 0; nt < 16; nt++)
            #pragma unroll
            for (int j = 0; j < 4; j++) acc[nt][j] = 0.f;

        #pragma unroll 1
        for (int pass = 0; pass < 3; pass++) {
            const uint32_t* As = (pass == 1) ? Alo : Ahi;
            const uint32_t* Bs = (pass == 2) ? W2l : W2h;
            const uint32_t* Arow0 = As + r4 * BSTRIDE + q4;
            const uint32_t* Arow8 = As + (r4 + 8) * BSTRIDE + q4;
            const uint32_t* Bbase = Bs + r4 * BSTRIDE + q4;
            #pragma unroll 2
            for (int ks = 0; ks < 8; ks++) {
                int kp = ks * 8;
                uint32_t a0 = Arow0[kp], a1 = Arow8[kp];
                uint32_t a2 = Arow0[kp + 4], a3 = Arow8[kp + 4];
                #pragma unroll
                for (int nt = 0; nt < 16; nt++) {
                    const uint32_t* bp = Bbase + nt * 8 * BSTRIDE + kp;
                    mma_bf16(acc[nt][0], acc[nt][1], acc[nt][2], acc[nt][3],
                             a0, a1, a2, a3, bp[0], bp[4]);
                }
            }
        }
        __syncwarp();

        float s0 = 0.f, q0 = 0.f, s1 = 0.f, q1 = 0.f;
        #pragma unroll
        for (int nt = 0; nt < 16; nt++) {
            int col = nt * 8 + q4 * 2;
            float2 bv = *(const float2*)(b2 + col);
            float v0 = fmaxf(acc[nt][0] + bv.x, 0.f);
            float v1 = fmaxf(acc[nt][1] + bv.y, 0.f);
            float v2 = fmaxf(acc[nt][2] + bv.x, 0.f);
            float v3 = fmaxf(acc[nt][3] + bv.y, 0.f);
            acc[nt][0] = v0; acc[nt][1] = v1; acc[nt][2] = v2; acc[nt][3] = v3;
            s0 += v0 + v1; q0 = fmaf(v0, v0, fmaf(v1, v1, q0));
            s1 += v2 + v3; q1 = fmaf(v2, v2, fmaf(v3, v3, q1));
        }
        #pragma unroll
        for (int o = 1; o <= 2; o <<= 1) {
            s0 += __shfl_xor_sync(0xffffffffu, s0, o);
            q0 += __shfl_xor_sync(0xffffffffu, q0, o);
            s1 += __shfl_xor_sync(0xffffffffu, s1, o);
            q1 += __shfl_xor_sync(0xffffffffu, q1, o);
        }
        float mean0 = s0 * (1.f / 128.f);
        float var0 = fmaxf((q0 - s0 * mean0) * (1.f / 127.f), 0.f);
        float inv0 = 1.f / (sqrtf(var0) + 1e-6f);
        float mean1 = s1 * (1.f / 128.f);
        float var1 = fmaxf((q1 - s1 * mean1) * (1.f / 127.f), 0.f);
        float inv1 = 1.f / (sqrtf(var1) + 1e-6f);

        #pragma unroll
        for (int nt = 0; nt < 16; nt++) {
            int col = nt * 8 + q4 * 2;
            float2 gg = *(const float2*)(gamma + col);
            float2 be = *(const float2*)(beta + col);
            float o0 = gg.x * (acc[nt][0] - mean0) * inv0 + be.x;
            float o1 = gg.y * (acc[nt][1] - mean0) * inv0 + be.y;
            float o2 = gg.x * (acc[nt][2] - mean1) * inv1 + be.x;
            float o3 = gg.y * (acc[nt][3] - mean1) * inv1 + be.y;
            float r0, r1;
            uint32_t h0 = pack_bf2(o0, o1, r0, r1);
            Ahi[r4 * BSTRIDE + nt * 4 + q4] = h0;
            Alo[r4 * BSTRIDE + nt * 4 + q4] = pack_bf2n(r0, r1);
            uint32_t h1 = pack_bf2(o2, o3, r0, r1);
            Ahi[(r4 + 8) * BSTRIDE + nt * 4 + q4] = h1;
            Alo[(r4 + 8) * BSTRIDE + nt * 4 + q4] = pack_bf2n(r0, r1);
        }
        __syncwarp();
        for (int idx = lane; idx < 256; idx += 32) {
            int r = idx >> 4, qv = idx & 15;
            int row = rowBase + r;
            if (row < n) {
                uint4 vh = *(const uint4*)(Ahi + r * BSTRIDE + qv * 4);
                uint4 vl = *(const uint4*)(Alo + r * BSTRIDE + qv * 4);
                ((uint4*)(g_hh + (size_t)row * 128))[qv] = vh;
                ((uint4*)(g_hl + (size_t)row * 128))[qv] = vl;
            }
        }
        __syncwarp();
    }
}

// ---------------- HMMA GCN GEMM, B-fragments-in-registers --------------------
// Each warp owns 32 cols (4 ntiles): B hi+lo = 128 regs, loaded once.
// Warps grouped (WPG per group) share one 16-row A tile in smem, double-buffered.
template <int N2>
__global__ void __launch_bounds__(256, 1) k_mma(
    const __nv_bfloat16* __restrict__ hh, const __nv_bfloat16* __restrict__ hl,
    const float* __restrict__ wn, const float* __restrict__ ws,
    const float* __restrict__ bias,
    float* __restrict__ sup, float* __restrict__ selfb, int n)
{
    constexpr int OUT = N2 / 2;
    constexpr int WPG = N2 / 32;           // warps per group (8 for 256, 4 for 128)
    constexpr int G = 8 / WPG;             // groups per CTA
    constexpr int BSTRIDE = 68;
    constexpr int ABUF = 2 * 16 * BSTRIDE; // u32 per (hi+lo) A buffer

    extern __shared__ __align__(16) uint32_t sm32[];
    uint32_t* Bh = sm32;                   // [N2][68]
    uint32_t* Bl = Bh + N2 * BSTRIDE;
    uint32_t* Abase = Bl + N2 * BSTRIDE;   // [G][2][ABUF]

    int tid = threadIdx.x, wid = tid >> 5, lane = tid & 31;
    int g = wid / WPG, wg = wid % WPG;
    int lt = tid - g * (WPG * 32);         // thread id within group
    int q4 = lane & 3, r4 = lane >> 2;

    // ---- stage + split weights into smem (w is [K=128][O] k-major)
    for (int i = tid; i < N2 * 64; i += 256) {
        int kp = i / N2, nn = i % N2;
        float a0, a1;
        if (nn < OUT) {
            a0 = wn[(2 * kp) * OUT + nn];
            a1 = wn[(2 * kp + 1) * OUT + nn];
        } else {
            a0 = ws[(2 * kp) * OUT + nn - OUT];
            a1 = ws[(2 * kp + 1) * OUT + nn - OUT];
        }
        float r0, r1;
        uint32_t h = pack_bf2(a0, a1, r0, r1);
        Bh[nn * BSTRIDE + kp] = h;
        Bl[nn * BSTRIDE + kp] = pack_bf2n(r0, r1);
    }
    __syncthreads();

    // ---- load this warp's B fragments into registers (held entire kernel)
    uint32_t bh[4][8][2], bl[4][8][2];
    #pragma unroll
    for (int nt = 0; nt < 4; nt++) {
        #pragma unroll
        for (int ks = 0; ks < 8; ks++) {
            const uint32_t* p  = Bh + (wg * 32 + nt * 8 + r4) * BSTRIDE + ks * 8 + q4;
            const uint32_t* pl = Bl + (wg * 32 + nt * 8 + r4) * BSTRIDE + ks * 8 + q4;
            bh[nt][ks][0] = p[0];  bh[nt][ks][1] = p[4];
            bl[nt][ks][0] = pl[0]; bl[nt][ks][1] = pl[4];
        }
    }

    int ntasks = (n + 15) >> 4;
    int stride = 148 * G;
    int t0 = blockIdx.x * G + g;
    int iters = (ntasks + stride - 1) / stride;

    // prologue: stage first tile into buffer 0
    {
        int t = t0;
        if (t < ntasks) {
            uint32_t* Ah = Abase + g * 2 * ABUF;
            uint32_t* Al = Ah + 16 * BSTRIDE;
            int rowBase = t << 4;
            for (int i = lt; i < 256; i += WPG * 32) {
                int r = i >> 4, q = i & 15;
                int grow = rowBase + r;
                if (grow > n - 1) grow = n - 1;
                uint4 vh = ((const uint4*)(hh + (size_t)grow * 128))[q];
                uint4 vl = ((const uint4*)(hl + (size_t)grow * 128))[q];
                *(uint4*)(Ah + r * BSTRIDE + q * 4) = vh;
                *(uint4*)(Al + r * BSTRIDE + q * 4) = vl;
            }
        }
    }
    __syncthreads();

    int cur = 0;
    for (int it = 0; it < iters; it++) {
        int t = t0 + it * stride;
        int tn = t + stride;

        // stage next tile into other buffer (overlaps with compute below)
        if (tn < ntasks) {
            uint32_t* Ah = Abase + (g * 2 + (cur ^ 1)) * ABUF;
            uint32_t* Al = Ah + 16 * BSTRIDE;
            int rowBase = tn << 4;
            for (int i = lt; i < 256; i += WPG * 32) {
                int r = i >> 4, q = i & 15;
                int grow = rowBase + r;
                if (grow > n - 1) grow = n - 1;
                uint4 vh = ((const uint4*)(hh + (size_t)grow * 128))[q];
                uint4 vl = ((const uint4*)(hl + (size_t)grow * 128))[q];
                *(uint4*)(Ah + r * BSTRIDE + q * 4) = vh;
                *(uint4*)(Al + r * BSTRIDE + q * 4) = vl;
            }
        }

        if (t < ntasks) {
            const uint32_t* Ah = Abase + (g * 2 + cur) * ABUF;
            const uint32_t* Al = Ah + 16 * BSTRIDE;
            const uint32_t* Ar0h = Ah + r4 * BSTRIDE + q4;
            const uint32_t* Ar8h = Ah + (r4 + 8) * BSTRIDE + q4;
            const uint32_t* Ar0l = Al + r4 * BSTRIDE + q4;
            const uint32_t* Ar8l = Al + (r4 + 8) * BSTRIDE + q4;

            float acc[4][4];
            #pragma unroll
            for (int nt = 0; nt < 4; nt++)
                #pragma unroll
                for (int j = 0; j < 4; j++) acc[nt][j] = 0.f;

            #pragma unroll
            for (int ks = 0; ks < 8; ks++) {
                int kp = ks * 8;
                uint32_t ah0 = Ar0h[kp], ah1 = Ar8h[kp];
                uint32_t ah2 = Ar0h[kp + 4], ah3 = Ar8h[kp + 4];
                uint32_t al0 = Ar0l[kp], al1 = Ar8l[kp];
                uint32_t al2 = Ar0l[kp + 4], al3 = Ar8l[kp + 4];
                #pragma unroll
                for (int nt = 0; nt < 4; nt++) {
                    mma_bf16(acc[nt][0], acc[nt][1], acc[nt][2], acc[nt][3],
                             ah0, ah1, ah2, ah3, bh[nt][ks][0], bh[nt][ks][1]);
                    mma_bf16(acc[nt][0], acc[nt][1], acc[nt][2], acc[nt][3],
                             al0, al1, al2, al3, bh[nt][ks][0], bh[nt][ks][1]);
                    mma_bf16(acc[nt][0], acc[nt][1], acc[nt][2], acc[nt][3],
                             ah0, ah1, ah2, ah3, bl[nt][ks][0], bl[nt][ks][1]);
                }
            }

            int rowBase = t << 4;
            int row0 = rowBase + r4, row1 = row0 + 8;
            #pragma unroll
            for (int nt = 0; nt < 4; nt++) {
                int col = wg * 32 + nt * 8 + q4 * 2;
                if (col < OUT) {
                    if (row0 < n) *(float2*)(sup + (size_t)row0 * OUT + col) = make_float2(acc[nt][0], acc[nt][1]);
                    if (row1 < n) *(float2*)(sup + (size_t)row1 * OUT + col) = make_float2(acc[nt][2], acc[nt][3]);
                } else {
                    int c = col - OUT;
                    float2 bv = *(const float2*)(bias + c);
                    if (row0 < n) *(float2*)(selfb + (size_t)row0 * OUT + c) = make_float2(acc[nt][0] + bv.x, acc[nt][1] + bv.y);
                    if (row1 < n) *(float2*)(selfb + (size_t)row1 * OUT + c) = make_float2(acc[nt][2] + bv.x, acc[nt][3] + bv.y);
                }
            }
        }
        __syncthreads();
        cur ^= 1;
    }
}

// ---------------- sparse aggregation + relu ----------------------------------
__global__ void k_spmm128(const float* __restrict__ sup, const float* __restrict__ selfb, int n)
{
    int warp = (blockIdx.x * blockDim.x + threadIdx.x) >> 5;
    int lane = threadIdx.x & 31;
    if (warp >= n) return;
    int e0 = g_off[warp], e1 = g_off[warp + 1];

    float4 acc = make_float4(0.f, 0.f, 0.f, 0.f);
    int e = e0;
    for (; e + 1 < e1; e += 2) {
        int2 p0 = __ldg(&g_epack[e]);
        int2 p1 = __ldg(&g_epack[e + 1]);
        float v0 = __int_as_float(p0.y);
        float v1 = __int_as_float(p1.y);
        float4 s0 = ((const float4*)(sup + (size_t)p0.x * 128))[lane];
        float4 s1 = ((const float4*)(sup + (size_t)p1.x * 128))[lane];
        acc.x = fmaf(v0, s0.x, fmaf(v1, s1.x, acc.x));
        acc.y = fmaf(v0, s0.y, fmaf(v1, s1.y, acc.y));
        acc.z = fmaf(v0, s0.z, fmaf(v1, s1.z, acc.z));
        acc.w = fmaf(v0, s0.w, fmaf(v1, s1.w, acc.w));
    }
    if (e < e1) {
        int2 p0 = __ldg(&g_epack[e]);
        float v0 = __int_as_float(p0.y);
        float4 s0 = ((const float4*)(sup + (size_t)p0.x * 128))[lane];
        acc.x = fmaf(v0, s0.x, acc.x);
        acc.y = fmaf(v0, s0.y, acc.y);
        acc.z = fmaf(v0, s0.z, acc.z);
        acc.w = fmaf(v0, s0.w, acc.w);
    }
    float4 sb = ((const float4*)(selfb + (size_t)warp * 128))[lane];
    float o0 = fmaxf(acc.x + sb.x, 0.f);
    float o1 = fmaxf(acc.y + sb.y, 0.f);
    float o2 = fmaxf(acc.z + sb.z, 0.f);
    float o3 = fmaxf(acc.w + sb.w, 0.f);
    float l0, l1, l2, l3;
    unsigned p01 = pack_bf2(o0, o1, l0, l1);
    unsigned p23 = pack_bf2(o2, o3, l2, l3);
    ((uint2*)(g_hh + (size_t)warp * 128))[lane] = make_uint2(p01, p23);
    ((uint2*)(g_hl + (size_t)warp * 128))[lane] = make_uint2(pack_bf2n(l0, l1), pack_bf2n(l2, l3));
}

__global__ void k_spmm64(const float* __restrict__ sup, const float* __restrict__ selfb,
                         float* __restrict__ out, int n)
{
    int warp = (blockIdx.x * blockDim.x + threadIdx.x) >> 5;
    int lane = threadIdx.x & 31;
    if (warp >= n) return;
    int e0 = g_off[warp], e1 = g_off[warp + 1];

    float2 acc = make_float2(0.f, 0.f);
    int e = e0;
    for (; e + 1 < e1; e += 2) {
        int2 p0 = __ldg(&g_epack[e]);
        int2 p1 = __ldg(&g_epack[e + 1]);
        float v0 = __int_as_float(p0.y);
        float v1 = __int_as_float(p1.y);
        float2 s0 = ((const float2*)(sup + (size_t)p0.x * 64))[lane];
        float2 s1 = ((const float2*)(sup + (size_t)p1.x * 64))[lane];
        acc.x = fmaf(v0, s0.x, fmaf(v1, s1.x, acc.x));
        acc.y = fmaf(v0, s0.y, fmaf(v1, s1.y, acc.y));
    }
    if (e < e1) {
        int2 p0 = __ldg(&g_epack[e]);
        float v0 = __int_as_float(p0.y);
        float2 s0 = ((const float2*)(sup + (size_t)p0.x * 64))[lane];
        acc.x = fmaf(v0, s0.x, acc.x);
        acc.y = fmaf(v0, s0.y, acc.y);
    }
    float2 sb = ((const float2*)(selfb + (size_t)warp * 64))[lane];
    float2 o;
    o.x = fmaxf(acc.x + sb.x, 0.f);
    o.y = fmaxf(acc.y + sb.y, 0.f);
    ((float2*)(out + (size_t)warp * 64))[lane] = o;
}

// ---------------- launch -----------------------------------------------------
extern "C" void kernel_launch(void* const* d_in, const int* in_sizes, int n_in,
                              void* d_out, int out_size)
{
    const float* x    = (const float*)d_in[0];
    const int*   erow = (const int*)d_in[1];
    const int*   ecol = (const int*)d_in[2];
    const float* eval = (const float*)d_in[3];
    const float* w1   = (const float*)d_in[4];
    const float* b1   = (const float*)d_in[5];
    const float* w2   = (const float*)d_in[6];
    const float* b2   = (const float*)d_in[7];
    const float* gam  = (const float*)d_in[8];
    const float* bet  = (const float*)d_in[9];
    const float* gwn[4] = {(const float*)d_in[10], (const float*)d_in[13],
                           (const float*)d_in[16], (const float*)d_in[19]};
    const float* gws[4] = {(const float*)d_in[11], (const float*)d_in[14],
                           (const float*)d_in[17], (const float*)d_in[20]};
    const float* gb[4]  = {(const float*)d_in[12], (const float*)d_in[15],
                           (const float*)d_in[18], (const float*)d_in[21]};
    float* out = (float*)d_out;

    int n = in_sizes[0] / 128;
    int E = in_sizes[1];

    float *sup, *self;
    __nv_bfloat16 *hh, *hl;
    cudaGetSymbolAddress((void**)&sup, g_sup);
    cudaGetSymbolAddress((void**)&self, g_self);
    cudaGetSymbolAddress((void**)&hh, g_hh);
    cudaGetSymbolAddress((void**)&hl, g_hl);

    const int SMFC  = (4 * 128 * 68 + 8 * 2 * 16 * 68) * 4;          // 208896
    const int SM256 = (2 * 256 * 68 + 1 * 2 * 2 * 16 * 68) * 4;      // 156672
    const int SM128 = (2 * 128 * 68 + 2 * 2 * 2 * 16 * 68) * 4;      // 104448

    cudaFuncSetAttribute(k_fc, cudaFuncAttributeMaxDynamicSharedMemorySize, SMFC);
    cudaFuncSetAttribute(k_mma<256>, cudaFuncAttributeMaxDynamicSharedMemorySize, SM256);
    cudaFuncSetAttribute(k_mma<128>, cudaFuncAttributeMaxDynamicSharedMemorySize, SM128);

    int nb = (n + 1023) / 1024;
    int spblocks = (n + 7) / 8;

    // ordered so launch #3 (profiled) = k_mma<256> layer 1
    k_zero<<<(n + 255) / 256, 256>>>(n);
    k_fc<<<148, 256, SMFC>>>(x, w1, b1, w2, b2, gam, bet, n);
    k_hist<<<(E + 255) / 256, 256>>>(erow, E);
    k_mma<256><<<148, 256, SM256>>>(hh, hl, gwn[0], gws[0], gb[0], sup, self, n);

    k_scan1<<<nb, 1024>>>(n);
    k_scan2<<<1, 128>>>(nb);
    k_scan3<<<(n + 255) / 256, 256>>>(n);
    k_scatter<<<(E + 255) / 256, 256>>>(erow, ecol, eval, E);

    k_spmm128<<<spblocks, 256>>>(sup, self, n);

    k_mma<256><<<148, 256, SM256>>>(hh, hl, gwn[1], gws[1], gb[1], sup, self, n);
    k_spmm128<<<spblocks, 256>>>(sup, self, n);

    k_mma<256><<<148, 256, SM256>>>(hh, hl, gwn[2], gws[2], gb[2], sup, self, n);
    k_spmm128<<<spblocks, 256>>>(sup, self, n);

    k_mma<128><<<148, 256, SM128>>>(hh, hl, gwn[3], gws[3], gb[3], sup, self, n);
    k_spmm64<<<spblocks, 256>>>(sup, self, out, n);
}

// round 8
// speedup vs baseline: 1.4767x; 1.0921x over previous
#include <cuda_runtime.h>
#include <cuda_bf16.h>
#include <cstdint>

#define MAX_N 100000
#define MAX_E 3200000

// ---------------- scratch ----------------------------------------------------
__device__ float g_sup[MAX_N * 128];
__device__ float g_self[MAX_N * 128];
__device__ __align__(16) __nv_bfloat16 g_hh[MAX_N * 128];
__device__ __align__(16) __nv_bfloat16 g_hl[MAX_N * 128];
__device__ int  g_cnt[MAX_N];
__device__ int  g_off[MAX_N + 1];
__device__ int  g_cur[MAX_N];
__device__ int  g_bsum[128];
__device__ int  g_bscan[128];
__device__ __align__(8) int2 g_epack[MAX_E];   // (col, val bits)

// ---------------- helpers ----------------------------------------------------
__device__ __forceinline__ unsigned pack_bf2(float a, float b, float& ra, float& rb) {
    __nv_bfloat16 ha = __float2bfloat16_rn(a), hb = __float2bfloat16_rn(b);
    ra = a - __bfloat162float(ha);
    rb = b - __bfloat162float(hb);
    return ((unsigned)__bfloat16_as_ushort(hb) << 16) | (unsigned)__bfloat16_as_ushort(ha);
}
__device__ __forceinline__ unsigned pack_bf2n(float a, float b) {
    __nv_bfloat16 ha = __float2bfloat16_rn(a), hb = __float2bfloat16_rn(b);
    return ((unsigned)__bfloat16_as_ushort(hb) << 16) | (unsigned)__bfloat16_as_ushort(ha);
}

__device__ __forceinline__ void mma_bf16(float& d0, float& d1, float& d2, float& d3,
                                         uint32_t a0, uint32_t a1, uint32_t a2, uint32_t a3,
                                         uint32_t b0, uint32_t b1) {
    asm volatile("mma.sync.aligned.m16n8k16.row.col.f32.bf16.bf16.f32 "
                 "{%0,%1,%2,%3}, {%4,%5,%6,%7}, {%8,%9}, {%0,%1,%2,%3};"
                 : "+f"(d0), "+f"(d1), "+f"(d2), "+f"(d3)
                 : "r"(a0), "r"(a1), "r"(a2), "r"(a3), "r"(b0), "r"(b1));
}

__device__ __forceinline__ void ldsm4(uint32_t& r0, uint32_t& r1, uint32_t& r2, uint32_t& r3,
                                      uint32_t addr) {
    asm volatile("ldmatrix.sync.aligned.m8n8.x4.shared.b16 {%0,%1,%2,%3}, [%4];"
                 : "=r"(r0), "=r"(r1), "=r"(r2), "=r"(r3) : "r"(addr));
}

__device__ __forceinline__ uint32_t smem_u32(const void* p) {
    uint32_t a;
    asm("{ .reg .u64 t; cvta.to.shared.u64 t, %1; cvt.u32.u64 %0, t; }" : "=r"(a) : "l"(p));
    return a;
}

#define CP_ASYNC_CG(dst, src) \
    asm volatile("cp.async.cg.shared.global [%0], [%1], 16;" :: "r"(dst), "l"(src))
#define CP_COMMIT() asm volatile("cp.async.commit_group;" ::: "memory")
#define CP_WAIT1()  asm volatile("cp.async.wait_group 1;" ::: "memory")

// ---------------- CSR build --------------------------------------------------
__global__ void k_zero(int n) {
    int i = blockIdx.x * blockDim.x + threadIdx.x;
    if (i < n) g_cnt[i] = 0;
}
__global__ void k_hist(const int* __restrict__ rows, int E) {
    int i = blockIdx.x * blockDim.x + threadIdx.x;
    if (i < E) atomicAdd(&g_cnt[rows[i]], 1);
}
__global__ void k_scan1(int n) {
    __shared__ int buf[2][1024];
    int i = blockIdx.x * 1024 + threadIdx.x;
    int v = (i < n) ? g_cnt[i] : 0;
    int src = 0;
    buf[0][threadIdx.x] = v;
    for (int ofs = 1; ofs < 1024; ofs <<= 1) {
        __syncthreads();
        int t = buf[src][threadIdx.x];
        if ((int)threadIdx.x >= ofs) t += buf[src][threadIdx.x - ofs];
        buf[1 - src][threadIdx.x] = t;
        src ^= 1;
    }
    __syncthreads();
    int incl = buf[src][threadIdx.x];
    if (i < n) g_cnt[i] = incl;
    if (threadIdx.x == 1023) g_bsum[blockIdx.x] = incl;
}
__global__ void k_scan2(int nb) {
    __shared__ int buf[2][128];
    int tid = threadIdx.x;
    int v = (tid < nb) ? g_bsum[tid] : 0;
    int src = 0;
    buf[0][tid] = v;
    for (int ofs = 1; ofs < 128; ofs <<= 1) {
        __syncthreads();
        int t = buf[src][tid];
        if (tid >= ofs) t += buf[src][tid - ofs];
        buf[1 - src][tid] = t;
        src ^= 1;
    }
    __syncthreads();
    g_bscan[tid] = buf[src][tid];
}
__global__ void k_scan3(int n) {
    int i = blockIdx.x * blockDim.x + threadIdx.x;
    if (i < n) {
        int blk = i >> 10;
        int pre = blk ? g_bscan[blk - 1] : 0;
        g_off[i + 1] = g_cnt[i] + pre;
        if (i == 0) g_off[0] = 0;
        int prev = (i & 1023) ? g_cnt[i - 1] : 0;
        g_cur[i] = prev + pre;
    }
}
__global__ void k_scatter(const int* __restrict__ rows, const int* __restrict__ cols,
                          const float* __restrict__ vals, int E) {
    int e = blockIdx.x * blockDim.x + threadIdx.x;
    if (e < E) {
        int r = rows[e];
        int p = atomicAdd(&g_cur[r], 1);
        g_epack[p] = make_int2(cols[e], __float_as_int(vals[e]));
    }
}

// ---------------- HMMA fc: h = LN(relu(relu(x@w1T+b1)@w2T+b2)) -> bf16 hi/lo --
__global__ void __launch_bounds__(256, 1) k_fc(
    const float* __restrict__ x,
    const float* __restrict__ w1, const float* __restrict__ b1,
    const float* __restrict__ w2, const float* __restrict__ b2,
    const float* __restrict__ gamma, const float* __restrict__ beta, int n)
{
    constexpr int BSTRIDE = 68;
    extern __shared__ __align__(16) uint32_t sm32[];
    uint32_t* W1h = sm32;                 // [128][68]
    uint32_t* W1l = W1h + 128 * BSTRIDE;
    uint32_t* W2h = W1l + 128 * BSTRIDE;
    uint32_t* W2l = W2h + 128 * BSTRIDE;
    int tid = threadIdx.x, wid = tid >> 5, lane = tid & 31;
    uint32_t* Aw  = W2l + 128 * BSTRIDE + wid * (2 * 16 * BSTRIDE);
    uint32_t* Ahi = Aw;
    uint32_t* Alo = Aw + 16 * BSTRIDE;

    for (int i = tid; i < 128 * 64; i += 256) {
        int nn = i >> 6, q = i & 63;
        float2 a = *(const float2*)(w1 + nn * 128 + q * 2);
        float r0, r1;
        uint32_t h = pack_bf2(a.x, a.y, r0, r1);
        W1h[nn * BSTRIDE + q] = h;
        W1l[nn * BSTRIDE + q] = pack_bf2n(r0, r1);
        float2 b = *(const float2*)(w2 + nn * 128 + q * 2);
        uint32_t h2 = pack_bf2(b.x, b.y, r0, r1);
        W2h[nn * BSTRIDE + q] = h2;
        W2l[nn * BSTRIDE + q] = pack_bf2n(r0, r1);
    }
    __syncthreads();

    int q4 = lane & 3, r4 = lane >> 2;
    int ntiles = (n + 15) >> 4;

    for (int t = blockIdx.x * 8 + wid; t < ntiles; t += 148 * 8) {
        int rowBase = t << 4;
        for (int i = lane; i < 512; i += 32) {
            int r = i >> 5, f4 = i & 31;
            int grow = rowBase + r;
            if (grow > n - 1) grow = n - 1;
            float4 v = ((const float4*)(x + (size_t)grow * 128))[f4];
            float r0, r1;
            uint32_t h0 = pack_bf2(v.x, v.y, r0, r1);
            uint32_t l0 = pack_bf2n(r0, r1);
            uint32_t h1 = pack_bf2(v.z, v.w, r0, r1);
            uint32_t l1 = pack_bf2n(r0, r1);
            Ahi[r * BSTRIDE + f4 * 2] = h0;
            Ahi[r * BSTRIDE + f4 * 2 + 1] = h1;
            Alo[r * BSTRIDE + f4 * 2] = l0;
            Alo[r * BSTRIDE + f4 * 2 + 1] = l1;
        }
        __syncwarp();

        float acc[16][4];
        #pragma unroll
        for (int nt = 0; nt < 16; nt++)
            #pragma unroll
            for (int j = 0; j < 4; j++) acc[nt][j] = 0.f;

        #pragma unroll 1
        for (int pass = 0; pass < 3; pass++) {
            const uint32_t* As = (pass == 1) ? Alo : Ahi;
            const uint32_t* Bs = (pass == 2) ? W1l : W1h;
            const uint32_t* Arow0 = As + r4 * BSTRIDE + q4;
            const uint32_t* Arow8 = As + (r4 + 8) * BSTRIDE + q4;
            const uint32_t* Bbase = Bs + r4 * BSTRIDE + q4;
            #pragma unroll 2
            for (int ks = 0; ks < 8; ks++) {
                int kp = ks * 8;
                uint32_t a0 = Arow0[kp], a1 = Arow8[kp];
                uint32_t a2 = Arow0[kp + 4], a3 = Arow8[kp + 4];
                #pragma unroll
                for (int nt = 0; nt < 16; nt++) {
                    const uint32_t* bp = Bbase + nt * 8 * BSTRIDE + kp;
                    mma_bf16(acc[nt][0], acc[nt][1], acc[nt][2], acc[nt][3],
                             a0, a1, a2, a3, bp[0], bp[4]);
                }
            }
        }
        __syncwarp();
        #pragma unroll
        for (int nt = 0; nt < 16; nt++) {
            int col = nt * 8 + q4 * 2;
            float2 bv = *(const float2*)(b1 + col);
            float v0 = fmaxf(acc[nt][0] + bv.x, 0.f);
            float v1 = fmaxf(acc[nt][1] + bv.y, 0.f);
            float v2 = fmaxf(acc[nt][2] + bv.x, 0.f);
            float v3 = fmaxf(acc[nt][3] + bv.y, 0.f);
            float r0, r1;
            uint32_t h0 = pack_bf2(v0, v1, r0, r1);
            Ahi[r4 * BSTRIDE + nt * 4 + q4] = h0;
            Alo[r4 * BSTRIDE + nt * 4 + q4] = pack_bf2n(r0, r1);
            uint32_t h1 = pack_bf2(v2, v3, r0, r1);
            Ahi[(r4 + 8) * BSTRIDE + nt * 4 + q4] = h1;
            Alo[(r4 + 8) * BSTRIDE + nt * 4 + q4] = pack_bf2n(r0, r1);
        }
        __syncwarp();

        #pragma unroll
        for (int nt = 0; nt < 16; nt++)
            #pragma unroll
            for (int j = 0; j < 4; j++) acc[nt][j] = 0.f;

        #pragma unroll 1
        for (int pass = 0; pass < 3; pass++) {
            const uint32_t* As = (pass == 1) ? Alo : Ahi;
            const uint32_t* Bs = (pass == 2) ? W2l : W2h;
            const uint32_t* Arow0 = As + r4 * BSTRIDE + q4;
            const uint32_t* Arow8 = As + (r4 + 8) * BSTRIDE + q4;
            const uint32_t* Bbase = Bs + r4 * BSTRIDE + q4;
            #pragma unroll 2
            for (int ks = 0; ks < 8; ks++) {
                int kp = ks * 8;
                uint32_t a0 = Arow0[kp], a1 = Arow8[kp];
                uint32_t a2 = Arow0[kp + 4], a3 = Arow8[kp + 4];
                #pragma unroll
                for (int nt = 0; nt < 16; nt++) {
                    const uint32_t* bp = Bbase + nt * 8 * BSTRIDE + kp;
                    mma_bf16(acc[nt][0], acc[nt][1], acc[nt][2], acc[nt][3],
                             a0, a1, a2, a3, bp[0], bp[4]);
                }
            }
        }
        __syncwarp();

        float s0 = 0.f, q0 = 0.f, s1 = 0.f, q1 = 0.f;
        #pragma unroll
        for (int nt = 0; nt < 16; nt++) {
            int col = nt * 8 + q4 * 2;
            float2 bv = *(const float2*)(b2 + col);
            float v0 = fmaxf(acc[nt][0] + bv.x, 0.f);
            float v1 = fmaxf(acc[nt][1] + bv.y, 0.f);
            float v2 = fmaxf(acc[nt][2] + bv.x, 0.f);
            float v3 = fmaxf(acc[nt][3] + bv.y, 0.f);
            acc[nt][0] = v0; acc[nt][1] = v1; acc[nt][2] = v2; acc[nt][3] = v3;
            s0 += v0 + v1; q0 = fmaf(v0, v0, fmaf(v1, v1, q0));
            s1 += v2 + v3; q1 = fmaf(v2, v2, fmaf(v3, v3, q1));
        }
        #pragma unroll
        for (int o = 1; o <= 2; o <<= 1) {
            s0 += __shfl_xor_sync(0xffffffffu, s0, o);
            q0 += __shfl_xor_sync(0xffffffffu, q0, o);
            s1 += __shfl_xor_sync(0xffffffffu, s1, o);
            q1 += __shfl_xor_sync(0xffffffffu, q1, o);
        }
        float mean0 = s0 * (1.f / 128.f);
        float var0 = fmaxf((q0 - s0 * mean0) * (1.f / 127.f), 0.f);
        float inv0 = 1.f / (sqrtf(var0) + 1e-6f);
        float mean1 = s1 * (1.f / 128.f);
        float var1 = fmaxf((q1 - s1 * mean1) * (1.f / 127.f), 0.f);
        float inv1 = 1.f / (sqrtf(var1) + 1e-6f);

        #pragma unroll
        for (int nt = 0; nt < 16; nt++) {
            int col = nt * 8 + q4 * 2;
            float2 gg = *(const float2*)(gamma + col);
            float2 be = *(const float2*)(beta + col);
            float o0 = gg.x * (acc[nt][0] - mean0) * inv0 + be.x;
            float o1 = gg.y * (acc[nt][1] - mean0) * inv0 + be.y;
            float o2 = gg.x * (acc[nt][2] - mean1) * inv1 + be.x;
            float o3 = gg.y * (acc[nt][3] - mean1) * inv1 + be.y;
            float r0, r1;
            uint32_t h0 = pack_bf2(o0, o1, r0, r1);
            Ahi[r4 * BSTRIDE + nt * 4 + q4] = h0;
            Alo[r4 * BSTRIDE + nt * 4 + q4] = pack_bf2n(r0, r1);
            uint32_t h1 = pack_bf2(o2, o3, r0, r1);
            Ahi[(r4 + 8) * BSTRIDE + nt * 4 + q4] = h1;
            Alo[(r4 + 8) * BSTRIDE + nt * 4 + q4] = pack_bf2n(r0, r1);
        }
        __syncwarp();
        for (int idx = lane; idx < 256; idx += 32) {
            int r = idx >> 4, qv = idx & 15;
            int row = rowBase + r;
            if (row < n) {
                uint4 vh = *(const uint4*)(Ahi + r * BSTRIDE + qv * 4);
                uint4 vl = *(const uint4*)(Alo + r * BSTRIDE + qv * 4);
                ((uint4*)(g_hh + (size_t)row * 128))[qv] = vh;
                ((uint4*)(g_hl + (size_t)row * 128))[qv] = vl;
            }
        }
        __syncwarp();
    }
}

// ---------------- HMMA GCN GEMM: cp.async + ldmatrix, M=32/group -------------
// Each warp owns 32 cols (B hi+lo in 128 regs) and 2 row-subtiles (8 acc chains).
// A tiles (32 rows, hi+lo) double-buffered in smem via cp.async.cg.
template <int N2>
__global__ void __launch_bounds__(256, 1) k_mma(
    const __nv_bfloat16* __restrict__ hh, const __nv_bfloat16* __restrict__ hl,
    const float* __restrict__ wn, const float* __restrict__ ws,
    const float* __restrict__ bias,
    float* __restrict__ sup, float* __restrict__ selfb, int n)
{
    constexpr int OUT = N2 / 2;
    constexpr int WPG = N2 / 32;           // warps per group
    constexpr int G = 8 / WPG;             // groups per CTA
    constexpr int BSTRIDE = 68;
    constexpr int TM = 32;                 // rows per tile
    constexpr int ABUF = 2 * TM * BSTRIDE; // u32 per (hi+lo) buffer
    constexpr int AOFF = 2 * N2 * BSTRIDE; // word offset of A region

    extern __shared__ __align__(16) uint32_t sm32[];
    uint32_t* Bh = sm32;                   // [N2][68]
    uint32_t* Bl = Bh + N2 * BSTRIDE;

    int tid = threadIdx.x, wid = tid >> 5, lane = tid & 31;
    int g = wid / WPG, wg = wid % WPG;
    int lt = tid - g * (WPG * 32);
    int q4 = lane & 3, r4 = lane >> 2;
    uint32_t smemU = smem_u32(sm32);

    // ---- stage + split weights into smem (w is [K=128][O] k-major)
    for (int i = tid; i < N2 * 64; i += 256) {
        int kp = i / N2, nn = i % N2;
        float a0, a1;
        if (nn < OUT) {
            a0 = wn[(2 * kp) * OUT + nn];
            a1 = wn[(2 * kp + 1) * OUT + nn];
        } else {
            a0 = ws[(2 * kp) * OUT + nn - OUT];
            a1 = ws[(2 * kp + 1) * OUT + nn - OUT];
        }
        float r0, r1;
        uint32_t h = pack_bf2(a0, a1, r0, r1);
        Bh[nn * BSTRIDE + kp] = h;
        Bl[nn * BSTRIDE + kp] = pack_bf2n(r0, r1);
    }
    __syncthreads();

    // ---- B fragments to registers (held entire kernel)
    uint32_t bh[4][8][2], bl[4][8][2];
    #pragma unroll
    for (int nt = 0; nt < 4; nt++) {
        #pragma unroll
        for (int ks = 0; ks < 8; ks++) {
            const uint32_t* p  = Bh + (wg * 32 + nt * 8 + r4) * BSTRIDE + ks * 8 + q4;
            const uint32_t* pl = Bl + (wg * 32 + nt * 8 + r4) * BSTRIDE + ks * 8 + q4;
            bh[nt][ks][0] = p[0];  bh[nt][ks][1] = p[4];
            bl[nt][ks][0] = pl[0]; bl[nt][ks][1] = pl[4];
        }
    }

    // ldmatrix per-lane byte offset within an A(hi or lo) 32x68 block
    uint32_t loff = ((((lane & 7) + ((lane >> 3) & 1) * 8) * BSTRIDE + (lane >> 4) * 4)) * 4;

    int ntasks = (n + TM - 1) / TM;
    int stride = 148 * G;
    int t0 = blockIdx.x * G + g;
    int iters = (ntasks + stride - 1) / stride;

    // prefetch lambda-equivalent
    auto prefetch = [&](int t, int buf) {
        uint32_t abU = smemU + (AOFF + (g * 2 + buf) * ABUF) * 4;
        int rowBase = t * TM;
        for (int i = lt; i < TM * 16; i += WPG * 32) {
            int r = i >> 4, q = i & 15;
            int grow = rowBase + r;
            if (grow > n - 1) grow = n - 1;
            uint32_t dh = abU + (r * BSTRIDE + q * 4) * 4;
            CP_ASYNC_CG(dh, ((const uint4*)(hh + (size_t)grow * 128)) + q);
            CP_ASYNC_CG(dh + TM * BSTRIDE * 4, ((const uint4*)(hl + (size_t)grow * 128)) + q);
        }
    };

    if (t0 < ntasks) prefetch(t0, 0);
    CP_COMMIT();

    int cur = 0;
    for (int it = 0; it < iters; it++) {
        int t = t0 + it * stride;
        int tn = t + stride;

        if (tn < ntasks) prefetch(tn, cur ^ 1);
        CP_COMMIT();
        CP_WAIT1();
        __syncthreads();

        if (t < ntasks) {
            uint32_t abU = smemU + (AOFF + (g * 2 + cur) * ABUF) * 4 + loff;

            float acc[2][4][4];
            #pragma unroll
            for (int s = 0; s < 2; s++)
                #pragma unroll
                for (int nt = 0; nt < 4; nt++)
                    #pragma unroll
                    for (int j = 0; j < 4; j++) acc[s][nt][j] = 0.f;

            #pragma unroll
            for (int ks = 0; ks < 8; ks++) {
                #pragma unroll
                for (int s = 0; s < 2; s++) {
                    uint32_t ah0, ah1, ah2, ah3, al0, al1, al2, al3;
                    uint32_t base = abU + (s * 16 * BSTRIDE + ks * 8) * 4;
                    ldsm4(ah0, ah1, ah2, ah3, base);
                    ldsm4(al0, al1, al2, al3, base + TM * BSTRIDE * 4);
                    #pragma unroll
                    for (int nt = 0; nt < 4; nt++) {
                        mma_bf16(acc[s][nt][0], acc[s][nt][1], acc[s][nt][2], acc[s][nt][3],
                                 ah0, ah1, ah2, ah3, bh[nt][ks][0], bh[nt][ks][1]);
                        mma_bf16(acc[s][nt][0], acc[s][nt][1], acc[s][nt][2], acc[s][nt][3],
                                 al0, al1, al2, al3, bh[nt][ks][0], bh[nt][ks][1]);
                        mma_bf16(acc[s][nt][0], acc[s][nt][1], acc[s][nt][2], acc[s][nt][3],
                                 ah0, ah1, ah2, ah3, bl[nt][ks][0], bl[nt][ks][1]);
                    }
                }
            }

            int rowBase = t * TM;
            #pragma unroll
            for (int s = 0; s < 2; s++) {
                int row0 = rowBase + s * 16 + r4, row1 = row0 + 8;
                #pragma unroll
                for (int nt = 0; nt < 4; nt++) {
                    int col = wg * 32 + nt * 8 + q4 * 2;
                    if (col < OUT) {
                        if (row0 < n) *(float2*)(sup + (size_t)row0 * OUT + col) = make_float2(acc[s][nt][0], acc[s][nt][1]);
                        if (row1 < n) *(float2*)(sup + (size_t)row1 * OUT + col) = make_float2(acc[s][nt][2], acc[s][nt][3]);
                    } else {
                        int c = col - OUT;
                        float2 bv = *(const float2*)(bias + c);
                        if (row0 < n) *(float2*)(selfb + (size_t)row0 * OUT + c) = make_float2(acc[s][nt][0] + bv.x, acc[s][nt][1] + bv.y);
                        if (row1 < n) *(float2*)(selfb + (size_t)row1 * OUT + c) = make_float2(acc[s][nt][2] + bv.x, acc[s][nt][3] + bv.y);
                    }
                }
            }
        }
        __syncthreads();
        cur ^= 1;
    }
}

// ---------------- sparse aggregation + relu ----------------------------------
__global__ void k_spmm128(const float* __restrict__ sup, const float* __restrict__ selfb, int n)
{
    int warp = (blockIdx.x * blockDim.x + threadIdx.x) >> 5;
    int lane = threadIdx.x & 31;
    if (warp >= n) return;
    int e0 = g_off[warp], e1 = g_off[warp + 1];

    float4 acc = make_float4(0.f, 0.f, 0.f, 0.f);
    int e = e0;
    for (; e + 1 < e1; e += 2) {
        int2 p0 = __ldg(&g_epack[e]);
        int2 p1 = __ldg(&g_epack[e + 1]);
        float v0 = __int_as_float(p0.y);
        float v1 = __int_as_float(p1.y);
        float4 s0 = ((const float4*)(sup + (size_t)p0.x * 128))[lane];
        float4 s1 = ((const float4*)(sup + (size_t)p1.x * 128))[lane];
        acc.x = fmaf(v0, s0.x, fmaf(v1, s1.x, acc.x));
        acc.y = fmaf(v0, s0.y, fmaf(v1, s1.y, acc.y));
        acc.z = fmaf(v0, s0.z, fmaf(v1, s1.z, acc.z));
        acc.w = fmaf(v0, s0.w, fmaf(v1, s1.w, acc.w));
    }
    if (e < e1) {
        int2 p0 = __ldg(&g_epack[e]);
        float v0 = __int_as_float(p0.y);
        float4 s0 = ((const float4*)(sup + (size_t)p0.x * 128))[lane];
        acc.x = fmaf(v0, s0.x, acc.x);
        acc.y = fmaf(v0, s0.y, acc.y);
        acc.z = fmaf(v0, s0.z, acc.z);
        acc.w = fmaf(v0, s0.w, acc.w);
    }
    float4 sb = ((const float4*)(selfb + (size_t)warp * 128))[lane];
    float o0 = fmaxf(acc.x + sb.x, 0.f);
    float o1 = fmaxf(acc.y + sb.y, 0.f);
    float o2 = fmaxf(acc.z + sb.z, 0.f);
    float o3 = fmaxf(acc.w + sb.w, 0.f);
    float l0, l1, l2, l3;
    unsigned p01 = pack_bf2(o0, o1, l0, l1);
    unsigned p23 = pack_bf2(o2, o3, l2, l3);
    ((uint2*)(g_hh + (size_t)warp * 128))[lane] = make_uint2(p01, p23);
    ((uint2*)(g_hl + (size_t)warp * 128))[lane] = make_uint2(pack_bf2n(l0, l1), pack_bf2n(l2, l3));
}

__global__ void k_spmm64(const float* __restrict__ sup, const float* __restrict__ selfb,
                         float* __restrict__ out, int n)
{
    int warp = (blockIdx.x * blockDim.x + threadIdx.x) >> 5;
    int lane = threadIdx.x & 31;
    if (warp >= n) return;
    int e0 = g_off[warp], e1 = g_off[warp + 1];

    float2 acc = make_float2(0.f, 0.f);
    int e = e0;
    for (; e + 1 < e1; e += 2) {
        int2 p0 = __ldg(&g_epack[e]);
        int2 p1 = __ldg(&g_epack[e + 1]);
        float v0 = __int_as_float(p0.y);
        float v1 = __int_as_float(p1.y);
        float2 s0 = ((const float2*)(sup + (size_t)p0.x * 64))[lane];
        float2 s1 = ((const float2*)(sup + (size_t)p1.x * 64))[lane];
        acc.x = fmaf(v0, s0.x, fmaf(v1, s1.x, acc.x));
        acc.y = fmaf(v0, s0.y, fmaf(v1, s1.y, acc.y));
    }
    if (e < e1) {
        int2 p0 = __ldg(&g_epack[e]);
        float v0 = __int_as_float(p0.y);
        float2 s0 = ((const float2*)(sup + (size_t)p0.x * 64))[lane];
        acc.x = fmaf(v0, s0.x, acc.x);
        acc.y = fmaf(v0, s0.y, acc.y);
    }
    float2 sb = ((const float2*)(selfb + (size_t)warp * 64))[lane];
    float2 o;
    o.x = fmaxf(acc.x + sb.x, 0.f);
    o.y = fmaxf(acc.y + sb.y, 0.f);
    ((float2*)(out + (size_t)warp * 64))[lane] = o;
}

// ---------------- launch -----------------------------------------------------
extern "C" void kernel_launch(void* const* d_in, const int* in_sizes, int n_in,
                              void* d_out, int out_size)
{
    const float* x    = (const float*)d_in[0];
    const int*   erow = (const int*)d_in[1];
    const int*   ecol = (const int*)d_in[2];
    const float* eval = (const float*)d_in[3];
    const float* w1   = (const float*)d_in[4];
    const float* b1   = (const float*)d_in[5];
    const float* w2   = (const float*)d_in[6];
    const float* b2   = (const float*)d_in[7];
    const float* gam  = (const float*)d_in[8];
    const float* bet  = (const float*)d_in[9];
    const float* gwn[4] = {(const float*)d_in[10], (const float*)d_in[13],
                           (const float*)d_in[16], (const float*)d_in[19]};
    const float* gws[4] = {(const float*)d_in[11], (const float*)d_in[14],
                           (const float*)d_in[17], (const float*)d_in[20]};
    const float* gb[4]  = {(const float*)d_in[12], (const float*)d_in[15],
                           (const float*)d_in[18], (const float*)d_in[21]};
    float* out = (float*)d_out;

    int n = in_sizes[0] / 128;
    int E = in_sizes[1];

    float *sup, *self;
    __nv_bfloat16 *hh, *hl;
    cudaGetSymbolAddress((void**)&sup, g_sup);
    cudaGetSymbolAddress((void**)&self, g_self);
    cudaGetSymbolAddress((void**)&hh, g_hh);
    cudaGetSymbolAddress((void**)&hl, g_hl);

    const int SMFC  = (4 * 128 * 68 + 8 * 2 * 16 * 68) * 4;          // 208896
    const int SM256 = (2 * 256 * 68 + 1 * 2 * 2 * 32 * 68) * 4;      // 174080
    const int SM128 = (2 * 128 * 68 + 2 * 2 * 2 * 32 * 68) * 4;      // 139264

    cudaFuncSetAttribute(k_fc, cudaFuncAttributeMaxDynamicSharedMemorySize, SMFC);
    cudaFuncSetAttribute(k_mma<256>, cudaFuncAttributeMaxDynamicSharedMemorySize, SM256);
    cudaFuncSetAttribute(k_mma<128>, cudaFuncAttributeMaxDynamicSharedMemorySize, SM128);

    int nb = (n + 1023) / 1024;
    int spblocks = (n + 7) / 8;

    // ordered so launch #3 (profiled) = k_mma<256> layer 1
    k_zero<<<(n + 255) / 256, 256>>>(n);
    k_fc<<<148, 256, SMFC>>>(x, w1, b1, w2, b2, gam, bet, n);
    k_hist<<<(E + 255) / 256, 256>>>(erow, E);
    k_mma<256><<<148, 256, SM256>>>(hh, hl, gwn[0], gws[0], gb[0], sup, self, n);

    k_scan1<<<nb, 1024>>>(n);
    k_scan2<<<1, 128>>>(nb);
    k_scan3<<<(n + 255) / 256, 256>>>(n);
    k_scatter<<<(E + 255) / 256, 256>>>(erow, ecol, eval, E);

    k_spmm128<<<spblocks, 256>>>(sup, self, n);

    k_mma<256><<<148, 256, SM256>>>(hh, hl, gwn[1], gws[1], gb[1], sup, self, n);
    k_spmm128<<<spblocks, 256>>>(sup, self, n);

    k_mma<256><<<148, 256, SM256>>>(hh, hl, gwn[2], gws[2], gb[2], sup, self, n);
    k_spmm128<<<spblocks, 256>>>(sup, self, n);

    k_mma<128><<<148, 256, SM128>>>(hh, hl, gwn[3], gws[3], gb[3], sup, self, n);
    k_spmm64<<<spblocks, 256>>>(sup, self, out, n);
}

// round 12
// speedup vs baseline: 1.5532x; 1.0518x over previous
#include <cuda_runtime.h>
#include <cuda_bf16.h>
#include <cstdint>

#define MAX_N 100000
#define MAX_E 3200000

// ---------------- scratch ----------------------------------------------------
__device__ __align__(16) unsigned g_supu[MAX_N * 64];   // u16x2-packed sup
__device__ float g_scale[MAX_N];
__device__ float g_self[MAX_N * 128];
__device__ __align__(16) __nv_bfloat16 g_hh[MAX_N * 128];
__device__ __align__(16) __nv_bfloat16 g_hl[MAX_N * 128];
__device__ int  g_cnt[MAX_N];
__device__ int  g_off[MAX_N + 1];
__device__ int  g_cur[MAX_N];
__device__ int  g_bsum[128];
__device__ int  g_bscan[128];
__device__ __align__(8) int2 g_epack[MAX_E];   // (col, val bits)

#define QMAX 32760.0f
#define MAGIC_BIAS 8421376.0f   // 2^23 + 32768

// ---------------- helpers ----------------------------------------------------
__device__ __forceinline__ unsigned pack_bf2(float a, float b, float& ra, float& rb) {
    __nv_bfloat16 ha = __float2bfloat16_rn(a), hb = __float2bfloat16_rn(b);
    ra = a - __bfloat162float(ha);
    rb = b - __bfloat162float(hb);
    return ((unsigned)__bfloat16_as_ushort(hb) << 16) | (unsigned)__bfloat16_as_ushort(ha);
}
__device__ __forceinline__ unsigned pack_bf2n(float a, float b) {
    __nv_bfloat16 ha = __float2bfloat16_rn(a), hb = __float2bfloat16_rn(b);
    return ((unsigned)__bfloat16_as_ushort(hb) << 16) | (unsigned)__bfloat16_as_ushort(ha);
}

__device__ __forceinline__ void mma_bf16(float& d0, float& d1, float& d2, float& d3,
                                         uint32_t a0, uint32_t a1, uint32_t a2, uint32_t a3,
                                         uint32_t b0, uint32_t b1) {
    asm volatile("mma.sync.aligned.m16n8k16.row.col.f32.bf16.bf16.f32 "
                 "{%0,%1,%2,%3}, {%4,%5,%6,%7}, {%8,%9}, {%0,%1,%2,%3};"
                 : "+f"(d0), "+f"(d1), "+f"(d2), "+f"(d3)
                 : "r"(a0), "r"(a1), "r"(a2), "r"(a3), "r"(b0), "r"(b1));
}

__device__ __forceinline__ void ldsm4(uint32_t& r0, uint32_t& r1, uint32_t& r2, uint32_t& r3,
                                      uint32_t addr) {
    asm volatile("ldmatrix.sync.aligned.m8n8.x4.shared.b16 {%0,%1,%2,%3}, [%4];"
                 : "=r"(r0), "=r"(r1), "=r"(r2), "=r"(r3) : "r"(addr));
}

__device__ __forceinline__ uint32_t smem_u32(const void* p) {
    uint32_t a;
    asm("{ .reg .u64 t; cvta.to.shared.u64 t, %1; cvt.u32.u64 %0, t; }" : "=r"(a) : "l"(p));
    return a;
}

#define CP_ASYNC_CG(dst, src) \
    asm volatile("cp.async.cg.shared.global [%0], [%1], 16;" :: "r"(dst), "l"(src))
#define CP_COMMIT() asm volatile("cp.async.commit_group;" ::: "memory")
#define CP_WAIT1()  asm volatile("cp.async.wait_group 1;" ::: "memory")

// dequant: u16 packed in u32 -> two floats (value - 32768), exact, no I2F
__device__ __forceinline__ float dq_lo(unsigned d) {
    return __uint_as_float(__byte_perm(d, 0x4B000000u, 0x7410)) - MAGIC_BIAS;
}
__device__ __forceinline__ float dq_hi(unsigned d) {
    return __uint_as_float(__byte_perm(d, 0x4B000000u, 0x7432)) - MAGIC_BIAS;
}

// ---------------- CSR build --------------------------------------------------
__global__ void k_zero(int n) {
    int i = blockIdx.x * blockDim.x + threadIdx.x;
    if (i < n) g_cnt[i] = 0;
}
__global__ void k_hist(const int* __restrict__ rows, int E) {
    int i = blockIdx.x * blockDim.x + threadIdx.x;
    if (i < E) atomicAdd(&g_cnt[rows[i]], 1);
}
__global__ void k_scan1(int n) {
    __shared__ int buf[2][1024];
    int i = blockIdx.x * 1024 + threadIdx.x;
    int v = (i < n) ? g_cnt[i] : 0;
    int src = 0;
    buf[0][threadIdx.x] = v;
    for (int ofs = 1; ofs < 1024; ofs <<= 1) {
        __syncthreads();
        int t = buf[src][threadIdx.x];
        if ((int)threadIdx.x >= ofs) t += buf[src][threadIdx.x - ofs];
        buf[1 - src][threadIdx.x] = t;
        src ^= 1;
    }
    __syncthreads();
    int incl = buf[src][threadIdx.x];
    if (i < n) g_cnt[i] = incl;
    if (threadIdx.x == 1023) g_bsum[blockIdx.x] = incl;
}
__global__ void k_scan2(int nb) {
    __shared__ int buf[2][128];
    int tid = threadIdx.x;
    int v = (tid < nb) ? g_bsum[tid] : 0;
    int src = 0;
    buf[0][tid] = v;
    for (int ofs = 1; ofs < 128; ofs <<= 1) {
        __syncthreads();
        int t = buf[src][tid];
        if (tid >= ofs) t += buf[src][tid - ofs];
        buf[1 - src][tid] = t;
        src ^= 1;
    }
    __syncthreads();
    g_bscan[tid] = buf[src][tid];
}
__global__ void k_scan3(int n) {
    int i = blockIdx.x * blockDim.x + threadIdx.x;
    if (i < n) {
        int blk = i >> 10;
        int pre = blk ? g_bscan[blk - 1] : 0;
        g_off[i + 1] = g_cnt[i] + pre;
        if (i == 0) g_off[0] = 0;
        int prev = (i & 1023) ? g_cnt[i - 1] : 0;
        g_cur[i] = prev + pre;
    }
}
__global__ void k_scatter(const int* __restrict__ rows, const int* __restrict__ cols,
                          const float* __restrict__ vals, int E) {
    int e = blockIdx.x * blockDim.x + threadIdx.x;
    if (e < E) {
        int r = rows[e];
        int p = atomicAdd(&g_cur[r], 1);
        g_epack[p] = make_int2(cols[e], __float_as_int(vals[e]));
    }
}

// ---------------- HMMA fc: h = LN(relu(relu(x@w1T+b1)@w2T+b2)) -> bf16 hi/lo --
__global__ void __launch_bounds__(256, 1) k_fc(
    const float* __restrict__ x,
    const float* __restrict__ w1, const float* __restrict__ b1,
    const float* __restrict__ w2, const float* __restrict__ b2,
    const float* __restrict__ gamma, const float* __restrict__ beta, int n)
{
    constexpr int BSTRIDE = 68;
    extern __shared__ __align__(16) uint32_t sm32[];
    uint32_t* W1h = sm32;                 // [128][68]
    uint32_t* W1l = W1h + 128 * BSTRIDE;
    uint32_t* W2h = W1l + 128 * BSTRIDE;
    uint32_t* W2l = W2h + 128 * BSTRIDE;
    int tid = threadIdx.x, wid = tid >> 5, lane = tid & 31;
    uint32_t* Aw  = W2l + 128 * BSTRIDE + wid * (2 * 16 * BSTRIDE);
    uint32_t* Ahi = Aw;
    uint32_t* Alo = Aw + 16 * BSTRIDE;

    for (int i = tid; i < 128 * 64; i += 256) {
        int nn = i >> 6, q = i & 63;
        float2 a = *(const float2*)(w1 + nn * 128 + q * 2);
        float r0, r1;
        uint32_t h = pack_bf2(a.x, a.y, r0, r1);
        W1h[nn * BSTRIDE + q] = h;
        W1l[nn * BSTRIDE + q] = pack_bf2n(r0, r1);
        float2 b = *(const float2*)(w2 + nn * 128 + q * 2);
        uint32_t h2 = pack_bf2(b.x, b.y, r0, r1);
        W2h[nn * BSTRIDE + q] = h2;
        W2l[nn * BSTRIDE + q] = pack_bf2n(r0, r1);
    }
    __syncthreads();

    int q4 = lane & 3, r4 = lane >> 2;
    int ntiles = (n + 15) >> 4;

    for (int t = blockIdx.x * 8 + wid; t < ntiles; t += 148 * 8) {
        int rowBase = t << 4;
        for (int i = lane; i < 512; i += 32) {
            int r = i >> 5, f4 = i & 31;
            int grow = rowBase + r;
            if (grow > n - 1) grow = n - 1;
            float4 v = ((const float4*)(x + (size_t)grow * 128))[f4];
            float r0, r1;
            uint32_t h0 = pack_bf2(v.x, v.y, r0, r1);
            uint32_t l0 = pack_bf2n(r0, r1);
            uint32_t h1 = pack_bf2(v.z, v.w, r0, r1);
            uint32_t l1 = pack_bf2n(r0, r1);
            Ahi[r * BSTRIDE + f4 * 2] = h0;
            Ahi[r * BSTRIDE + f4 * 2 + 1] = h1;
            Alo[r * BSTRIDE + f4 * 2] = l0;
            Alo[r * BSTRIDE + f4 * 2 + 1] = l1;
        }
        __syncwarp();

        float acc[16][4];
        #pragma unroll
        for (int nt = 0; nt < 16; nt++)
            #pragma unroll
            for (int j = 0; j < 4; j++) acc[nt][j] = 0.f;

        #pragma unroll 1
        for (int pass = 0; pass < 3; pass++) {
            const uint32_t* As = (pass == 1) ? Alo : Ahi;
            const uint32_t* Bs = (pass == 2) ? W1l : W1h;
            const uint32_t* Arow0 = As + r4 * BSTRIDE + q4;
            const uint32_t* Arow8 = As + (r4 + 8) * BSTRIDE + q4;
            const uint32_t* Bbase = Bs + r4 * BSTRIDE + q4;
            #pragma unroll 2
            for (int ks = 0; ks < 8; ks++) {
                int kp = ks * 8;
                uint32_t a0 = Arow0[kp], a1 = Arow8[kp];
                uint32_t a2 = Arow0[kp + 4], a3 = Arow8[kp + 4];
                #pragma unroll
                for (int nt = 0; nt < 16; nt++) {
                    const uint32_t* bp = Bbase + nt * 8 * BSTRIDE + kp;
                    mma_bf16(acc[nt][0], acc[nt][1], acc[nt][2], acc[nt][3],
                             a0, a1, a2, a3, bp[0], bp[4]);
                }
            }
        }
        __syncwarp();
        #pragma unroll
        for (int nt = 0; nt < 16; nt++) {
            int col = nt * 8 + q4 * 2;
            float2 bv = *(const float2*)(b1 + col);
            float v0 = fmaxf(acc[nt][0] + bv.x, 0.f);
            float v1 = fmaxf(acc[nt][1] + bv.y, 0.f);
            float v2 = fmaxf(acc[nt][2] + bv.x, 0.f);
            float v3 = fmaxf(acc[nt][3] + bv.y, 0.f);
            float r0, r1;
            uint32_t h0 = pack_bf2(v0, v1, r0, r1);
            Ahi[r4 * BSTRIDE + nt * 4 + q4] = h0;
            Alo[r4 * BSTRIDE + nt * 4 + q4] = pack_bf2n(r0, r1);
            uint32_t h1 = pack_bf2(v2, v3, r0, r1);
            Ahi[(r4 + 8) * BSTRIDE + nt * 4 + q4] = h1;
            Alo[(r4 + 8) * BSTRIDE + nt * 4 + q4] = pack_bf2n(r0, r1);
        }
        __syncwarp();

        #pragma unroll
        for (int nt = 0; nt < 16; nt++)
            #pragma unroll
            for (int j = 0; j < 4; j++) acc[nt][j] = 0.f;

        #pragma unroll 1
        for (int pass = 0; pass < 3; pass++) {
            const uint32_t* As = (pass == 1) ? Alo : Ahi;
            const uint32_t* Bs = (pass == 2) ? W2l : W2h;
            const uint32_t* Arow0 = As + r4 * BSTRIDE + q4;
            const uint32_t* Arow8 = As + (r4 + 8) * BSTRIDE + q4;
            const uint32_t* Bbase = Bs + r4 * BSTRIDE + q4;
            #pragma unroll 2
            for (int ks = 0; ks < 8; ks++) {
                int kp = ks * 8;
                uint32_t a0 = Arow0[kp], a1 = Arow8[kp];
                uint32_t a2 = Arow0[kp + 4], a3 = Arow8[kp + 4];
                #pragma unroll
                for (int nt = 0; nt < 16; nt++) {
                    const uint32_t* bp = Bbase + nt * 8 * BSTRIDE + kp;
                    mma_bf16(acc[nt][0], acc[nt][1], acc[nt][2], acc[nt][3],
                             a0, a1, a2, a3, bp[0], bp[4]);
                }
            }
        }
        __syncwarp();

        float s0 = 0.f, q0 = 0.f, s1 = 0.f, q1 = 0.f;
        #pragma unroll
        for (int nt = 0; nt < 16; nt++) {
            int col = nt * 8 + q4 * 2;
            float2 bv = *(const float2*)(b2 + col);
            float v0 = fmaxf(acc[nt][0] + bv.x, 0.f);
            float v1 = fmaxf(acc[nt][1] + bv.y, 0.f);
            float v2 = fmaxf(acc[nt][2] + bv.x, 0.f);
            float v3 = fmaxf(acc[nt][3] + bv.y, 0.f);
            acc[nt][0] = v0; acc[nt][1] = v1; acc[nt][2] = v2; acc[nt][3] = v3;
            s0 += v0 + v1; q0 = fmaf(v0, v0, fmaf(v1, v1, q0));
            s1 += v2 + v3; q1 = fmaf(v2, v2, fmaf(v3, v3, q1));
        }
        #pragma unroll
        for (int o = 1; o <= 2; o <<= 1) {
            s0 += __shfl_xor_sync(0xffffffffu, s0, o);
            q0 += __shfl_xor_sync(0xffffffffu, q0, o);
            s1 += __shfl_xor_sync(0xffffffffu, s1, o);
            q1 += __shfl_xor_sync(0xffffffffu, q1, o);
        }
        float mean0 = s0 * (1.f / 128.f);
        float var0 = fmaxf((q0 - s0 * mean0) * (1.f / 127.f), 0.f);
        float inv0 = 1.f / (sqrtf(var0) + 1e-6f);
        float mean1 = s1 * (1.f / 128.f);
        float var1 = fmaxf((q1 - s1 * mean1) * (1.f / 127.f), 0.f);
        float inv1 = 1.f / (sqrtf(var1) + 1e-6f);

        #pragma unroll
        for (int nt = 0; nt < 16; nt++) {
            int col = nt * 8 + q4 * 2;
            float2 gg = *(const float2*)(gamma + col);
            float2 be = *(const float2*)(beta + col);
            float o0 = gg.x * (acc[nt][0] - mean0) * inv0 + be.x;
            float o1 = gg.y * (acc[nt][1] - mean0) * inv0 + be.y;
            float o2 = gg.x * (acc[nt][2] - mean1) * inv1 + be.x;
            float o3 = gg.y * (acc[nt][3] - mean1) * inv1 + be.y;
            float r0, r1;
            uint32_t h0 = pack_bf2(o0, o1, r0, r1);
            Ahi[r4 * BSTRIDE + nt * 4 + q4] = h0;
            Alo[r4 * BSTRIDE + nt * 4 + q4] = pack_bf2n(r0, r1);
            uint32_t h1 = pack_bf2(o2, o3, r0, r1);
            Ahi[(r4 + 8) * BSTRIDE + nt * 4 + q4] = h1;
            Alo[(r4 + 8) * BSTRIDE + nt * 4 + q4] = pack_bf2n(r0, r1);
        }
        __syncwarp();
        for (int idx = lane; idx < 256; idx += 32) {
            int r = idx >> 4, qv = idx & 15;
            int row = rowBase + r;
            if (row < n) {
                uint4 vh = *(const uint4*)(Ahi + r * BSTRIDE + qv * 4);
                uint4 vl = *(const uint4*)(Alo + r * BSTRIDE + qv * 4);
                ((uint4*)(g_hh + (size_t)row * 128))[qv] = vh;
                ((uint4*)(g_hl + (size_t)row * 128))[qv] = vl;
            }
        }
        __syncwarp();
    }
}

// ---------------- HMMA GCN GEMM + int16 row-scaled sup quantization ----------
// sup (cols < OUT) written as u16 packed (offset +32768), per-row scale.
// selfb (cols >= OUT) stays fp32.
template <int N2>
__global__ void __launch_bounds__(256, 1) k_mma(
    const __nv_bfloat16* __restrict__ hh, const __nv_bfloat16* __restrict__ hl,
    const float* __restrict__ wn, const float* __restrict__ ws,
    const float* __restrict__ bias,
    unsigned* __restrict__ supu, float* __restrict__ scaleArr,
    float* __restrict__ selfb, int n)
{
    constexpr int OUT = N2 / 2;
    constexpr int WPG = N2 / 32;
    constexpr int G = 8 / WPG;
    constexpr int BSTRIDE = 68;
    constexpr int TM = 32;
    constexpr int ABUF = 2 * TM * BSTRIDE;
    constexpr int AOFF = 2 * N2 * BSTRIDE;
    constexpr int RMOFF = AOFF + G * 2 * ABUF;
    constexpr int SUPW = OUT / 2;          // u32 per sup row

    extern __shared__ __align__(16) uint32_t sm32[];
    uint32_t* Bh = sm32;
    uint32_t* Bl = Bh + N2 * BSTRIDE;

    int tid = threadIdx.x, wid = tid >> 5, lane = tid & 31;
    int g = wid / WPG, wg = wid % WPG;
    int lt = tid - g * (WPG * 32);
    int q4 = lane & 3, r4 = lane >> 2;
    uint32_t smemU = smem_u32(sm32);
    unsigned* rmax = (unsigned*)(sm32 + RMOFF + g * TM);

    for (int i = tid; i < N2 * 64; i += 256) {
        int kp = i / N2, nn = i % N2;
        float a0, a1;
        if (nn < OUT) {
            a0 = wn[(2 * kp) * OUT + nn];
            a1 = wn[(2 * kp + 1) * OUT + nn];
        } else {
            a0 = ws[(2 * kp) * OUT + nn - OUT];
            a1 = ws[(2 * kp + 1) * OUT + nn - OUT];
        }
        float r0, r1;
        uint32_t h = pack_bf2(a0, a1, r0, r1);
        Bh[nn * BSTRIDE + kp] = h;
        Bl[nn * BSTRIDE + kp] = pack_bf2n(r0, r1);
    }
    __syncthreads();

    uint32_t bh[4][8][2], bl[4][8][2];
    #pragma unroll
    for (int nt = 0; nt < 4; nt++) {
        #pragma unroll
        for (int ks = 0; ks < 8; ks++) {
            const uint32_t* p  = Bh + (wg * 32 + nt * 8 + r4) * BSTRIDE + ks * 8 + q4;
            const uint32_t* pl = Bl + (wg * 32 + nt * 8 + r4) * BSTRIDE + ks * 8 + q4;
            bh[nt][ks][0] = p[0];  bh[nt][ks][1] = p[4];
            bl[nt][ks][0] = pl[0]; bl[nt][ks][1] = pl[4];
        }
    }

    uint32_t loff = ((((lane & 7) + ((lane >> 3) & 1) * 8) * BSTRIDE + (lane >> 4) * 4)) * 4;

    int ntasks = (n + TM - 1) / TM;
    int stride = 148 * G;
    int t0 = blockIdx.x * G + g;
    int iters = (ntasks + stride - 1) / stride;

    auto prefetch = [&](int t, int buf) {
        uint32_t abU = smemU + (AOFF + (g * 2 + buf) * ABUF) * 4;
        int rowBase = t * TM;
        for (int i = lt; i < TM * 16; i += WPG * 32) {
            int r = i >> 4, q = i & 15;
            int grow = rowBase + r;
            if (grow > n - 1) grow = n - 1;
            uint32_t dh = abU + (r * BSTRIDE + q * 4) * 4;
            CP_ASYNC_CG(dh, ((const uint4*)(hh + (size_t)grow * 128)) + q);
            CP_ASYNC_CG(dh + TM * BSTRIDE * 4, ((const uint4*)(hl + (size_t)grow * 128)) + q);
        }
    };

    if (t0 < ntasks) prefetch(t0, 0);
    CP_COMMIT();

    int cur = 0;
    for (int it = 0; it < iters; it++) {
        int t = t0 + it * stride;
        int tn = t + stride;

        if (tn < ntasks) prefetch(tn, cur ^ 1);
        CP_COMMIT();
        CP_WAIT1();
        if (lt < TM) rmax[lt] = 0;
        __syncthreads();   // A tile ready + rowmax zeroed

        float acc[2][4][4];
        if (t < ntasks) {
            uint32_t abU = smemU + (AOFF + (g * 2 + cur) * ABUF) * 4 + loff;

            #pragma unroll
            for (int s = 0; s < 2; s++)
                #pragma unroll
                for (int nt = 0; nt < 4; nt++)
                    #pragma unroll
                    for (int j = 0; j < 4; j++) acc[s][nt][j] = 0.f;

            #pragma unroll
            for (int ks = 0; ks < 8; ks++) {
                #pragma unroll
                for (int s = 0; s < 2; s++) {
                    uint32_t ah0, ah1, ah2, ah3, al0, al1, al2, al3;
                    uint32_t base = abU + (s * 16 * BSTRIDE + ks * 8) * 4;
                    ldsm4(ah0, ah1, ah2, ah3, base);
                    ldsm4(al0, al1, al2, al3, base + TM * BSTRIDE * 4);
                    #pragma unroll
                    for (int nt = 0; nt < 4; nt++) {
                        mma_bf16(acc[s][nt][0], acc[s][nt][1], acc[s][nt][2], acc[s][nt][3],
                                 ah0, ah1, ah2, ah3, bh[nt][ks][0], bh[nt][ks][1]);
                        mma_bf16(acc[s][nt][0], acc[s][nt][1], acc[s][nt][2], acc[s][nt][3],
                                 al0, al1, al2, al3, bh[nt][ks][0], bh[nt][ks][1]);
                        mma_bf16(acc[s][nt][0], acc[s][nt][1], acc[s][nt][2], acc[s][nt][3],
                                 ah0, ah1, ah2, ah3, bl[nt][ks][0], bl[nt][ks][1]);
                    }
                }
            }

            // per-row absmax (sup-owning warps only)
            if (wg < WPG / 2) {
                #pragma unroll
                for (int s = 0; s < 2; s++) {
                    float m0 = 0.f, m1 = 0.f;
                    #pragma unroll
                    for (int nt = 0; nt < 4; nt++) {
                        m0 = fmaxf(m0, fmaxf(fabsf(acc[s][nt][0]), fabsf(acc[s][nt][1])));
                        m1 = fmaxf(m1, fmaxf(fabsf(acc[s][nt][2]), fabsf(acc[s][nt][3])));
                    }
                    #pragma unroll
                    for (int o = 1; o <= 2; o <<= 1) {
                        m0 = fmaxf(m0, __shfl_xor_sync(0xffffffffu, m0, o));
                        m1 = fmaxf(m1, __shfl_xor_sync(0xffffffffu, m1, o));
                    }
                    if (q4 == 0) {
                        atomicMax(&rmax[s * 16 + r4], __float_as_uint(m0));
                        atomicMax(&rmax[s * 16 + r4 + 8], __float_as_uint(m1));
                    }
                }
            }
        }
        __syncthreads();   // rowmax complete

        if (t < ntasks) {
            int rowBase = t * TM;
            if (wg < WPG / 2) {
                // quantize + store sup u16
                #pragma unroll
                for (int s = 0; s < 2; s++) {
                    int row0 = rowBase + s * 16 + r4, row1 = row0 + 8;
                    float rm0 = __uint_as_float(rmax[s * 16 + r4]);
                    float rm1 = __uint_as_float(rmax[s * 16 + r4 + 8]);
                    float iv0 = rm0 > 0.f ? QMAX / rm0 : 0.f;
                    float iv1 = rm1 > 0.f ? QMAX / rm1 : 0.f;
                    #pragma unroll
                    for (int nt = 0; nt < 4; nt++) {
                        int col = wg * 32 + nt * 8 + q4 * 2;
                        unsigned u0 = (unsigned)__float2int_rn(fmaf(acc[s][nt][0], iv0, 32768.f));
                        unsigned u1 = (unsigned)__float2int_rn(fmaf(acc[s][nt][1], iv0, 32768.f));
                        unsigned u2 = (unsigned)__float2int_rn(fmaf(acc[s][nt][2], iv1, 32768.f));
                        unsigned u3 = (unsigned)__float2int_rn(fmaf(acc[s][nt][3], iv1, 32768.f));
                        if (row0 < n) supu[(size_t)row0 * SUPW + (col >> 1)] = (u0 & 0xffffu) | (u1 << 16);
                        if (row1 < n) supu[(size_t)row1 * SUPW + (col >> 1)] = (u2 & 0xffffu) | (u3 << 16);
                    }
                    if (wg == 0 && q4 == 0) {
                        if (row0 < n) scaleArr[row0] = rm0 * (1.f / QMAX);
                        if (row1 < n) scaleArr[row1] = rm1 * (1.f / QMAX);
                    }
                }
            } else {
                #pragma unroll
                for (int s = 0; s < 2; s++) {
                    int row0 = rowBase + s * 16 + r4, row1 = row0 + 8;
                    #pragma unroll
                    for (int nt = 0; nt < 4; nt++) {
                        int c = wg * 32 + nt * 8 + q4 * 2 - OUT;
                        float2 bv = *(const float2*)(bias + c);
                        if (row0 < n) *(float2*)(selfb + (size_t)row0 * OUT + c) = make_float2(acc[s][nt][0] + bv.x, acc[s][nt][1] + bv.y);
                        if (row1 < n) *(float2*)(selfb + (size_t)row1 * OUT + c) = make_float2(acc[s][nt][2] + bv.x, acc[s][nt][3] + bv.y);
                    }
                }
            }
        }
        __syncthreads();
        cur ^= 1;
    }
}

// ---------------- sparse aggregation (u16 dequant) + relu --------------------
__global__ void k_spmm128(const unsigned* __restrict__ supu, const float* __restrict__ scaleArr,
                          const float* __restrict__ selfb, int n)
{
    int warp = (blockIdx.x * blockDim.x + threadIdx.x) >> 5;
    int lane = threadIdx.x & 31;
    if (warp >= n) return;
    int e0 = g_off[warp], e1 = g_off[warp + 1];

    float4 acc = make_float4(0.f, 0.f, 0.f, 0.f);
    int e = e0;
    for (; e + 1 < e1; e += 2) {
        int2 p0 = __ldg(&g_epack[e]);
        int2 p1 = __ldg(&g_epack[e + 1]);
        float m0 = __int_as_float(p0.y) * __ldg(&scaleArr[p0.x]);
        float m1 = __int_as_float(p1.y) * __ldg(&scaleArr[p1.x]);
        uint2 d0 = ((const uint2*)(supu + (size_t)p0.x * 64))[lane];
        uint2 d1 = ((const uint2*)(supu + (size_t)p1.x * 64))[lane];
        acc.x = fmaf(m0, dq_lo(d0.x), fmaf(m1, dq_lo(d1.x), acc.x));
        acc.y = fmaf(m0, dq_hi(d0.x), fmaf(m1, dq_hi(d1.x), acc.y));
        acc.z = fmaf(m0, dq_lo(d0.y), fmaf(m1, dq_lo(d1.y), acc.z));
        acc.w = fmaf(m0, dq_hi(d0.y), fmaf(m1, dq_hi(d1.y), acc.w));
    }
    if (e < e1) {
        int2 p0 = __ldg(&g_epack[e]);
        float m0 = __int_as_float(p0.y) * __ldg(&scaleArr[p0.x]);
        uint2 d0 = ((const uint2*)(supu + (size_t)p0.x * 64))[lane];
        acc.x = fmaf(m0, dq_lo(d0.x), acc.x);
        acc.y = fmaf(m0, dq_hi(d0.x), acc.y);
        acc.z = fmaf(m0, dq_lo(d0.y), acc.z);
        acc.w = fmaf(m0, dq_hi(d0.y), acc.w);
    }
    float4 sb = ((const float4*)(selfb + (size_t)warp * 128))[lane];
    float o0 = fmaxf(acc.x + sb.x, 0.f);
    float o1 = fmaxf(acc.y + sb.y, 0.f);
    float o2 = fmaxf(acc.z + sb.z, 0.f);
    float o3 = fmaxf(acc.w + sb.w, 0.f);
    float l0, l1, l2, l3;
    unsigned p01 = pack_bf2(o0, o1, l0, l1);
    unsigned p23 = pack_bf2(o2, o3, l2, l3);
    ((uint2*)(g_hh + (size_t)warp * 128))[lane] = make_uint2(p01, p23);
    ((uint2*)(g_hl + (size_t)warp * 128))[lane] = make_uint2(pack_bf2n(l0, l1), pack_bf2n(l2, l3));
}

__global__ void k_spmm64(const unsigned* __restrict__ supu, const float* __restrict__ scaleArr,
                         const float* __restrict__ selfb, float* __restrict__ out, int n)
{
    int warp = (blockIdx.x * blockDim.x + threadIdx.x) >> 5;
    int lane = threadIdx.x & 31;
    if (warp >= n) return;
    int e0 = g_off[warp], e1 = g_off[warp + 1];

    float2 acc = make_float2(0.f, 0.f);
    int e = e0;
    for (; e + 1 < e1; e += 2) {
        int2 p0 = __ldg(&g_epack[e]);
        int2 p1 = __ldg(&g_epack[e + 1]);
        float m0 = __int_as_float(p0.y) * __ldg(&scaleArr[p0.x]);
        float m1 = __int_as_float(p1.y) * __ldg(&scaleArr[p1.x]);
        unsigned d0 = ((const unsigned*)(supu + (size_t)p0.x * 32))[lane];
        unsigned d1 = ((const unsigned*)(supu + (size_t)p1.x * 32))[lane];
        acc.x = fmaf(m0, dq_lo(d0), fmaf(m1, dq_lo(d1), acc.x));
        acc.y = fmaf(m0, dq_hi(d0), fmaf(m1, dq_hi(d1), acc.y));
    }
    if (e < e1) {
        int2 p0 = __ldg(&g_epack[e]);
        float m0 = __int_as_float(p0.y) * __ldg(&scaleArr[p0.x]);
        unsigned d0 = ((const unsigned*)(supu + (size_t)p0.x * 32))[lane];
        acc.x = fmaf(m0, dq_lo(d0), acc.x);
        acc.y = fmaf(m0, dq_hi(d0), acc.y);
    }
    float2 sb = ((const float2*)(selfb + (size_t)warp * 64))[lane];
    float2 o;
    o.x = fmaxf(acc.x + sb.x, 0.f);
    o.y = fmaxf(acc.y + sb.y, 0.f);
    ((float2*)(out + (size_t)warp * 64))[lane] = o;
}

// ---------------- launch -----------------------------------------------------
extern "C" void kernel_launch(void* const* d_in, const int* in_sizes, int n_in,
                              void* d_out, int out_size)
{
    const float* x    = (const float*)d_in[0];
    const int*   erow = (const int*)d_in[1];
    const int*   ecol = (const int*)d_in[2];
    const float* eval = (const float*)d_in[3];
    const float* w1   = (const float*)d_in[4];
    const float* b1   = (const float*)d_in[5];
    const float* w2   = (const float*)d_in[6];
    const float* b2   = (const float*)d_in[7];
    const float* gam  = (const float*)d_in[8];
    const float* bet  = (const float*)d_in[9];
    const float* gwn[4] = {(const float*)d_in[10], (const float*)d_in[13],
                           (const float*)d_in[16], (const float*)d_in[19]};
    const float* gws[4] = {(const float*)d_in[11], (const float*)d_in[14],
                           (const float*)d_in[17], (const float*)d_in[20]};
    const float* gb[4]  = {(const float*)d_in[12], (const float*)d_in[15],
                           (const float*)d_in[18], (const float*)d_in[21]};
    float* out = (float*)d_out;

    int n = in_sizes[0] / 128;
    int E = in_sizes[1];

    float *self, *scl;
    unsigned* supu;
    __nv_bfloat16 *hh, *hl;
    cudaGetSymbolAddress((void**)&supu, g_supu);
    cudaGetSymbolAddress((void**)&scl, g_scale);
    cudaGetSymbolAddress((void**)&self, g_self);
    cudaGetSymbolAddress((void**)&hh, g_hh);
    cudaGetSymbolAddress((void**)&hl, g_hl);

    const int SMFC  = (4 * 128 * 68 + 8 * 2 * 16 * 68) * 4;               // 208896
    const int SM256 = (2 * 256 * 68 + 1 * 2 * 2 * 32 * 68) * 4 + 1 * 32 * 4;
    const int SM128 = (2 * 128 * 68 + 2 * 2 * 2 * 32 * 68) * 4 + 2 * 32 * 4;

    cudaFuncSetAttribute(k_fc, cudaFuncAttributeMaxDynamicSharedMemorySize, SMFC);
    cudaFuncSetAttribute(k_mma<256>, cudaFuncAttributeMaxDynamicSharedMemorySize, SM256);
    cudaFuncSetAttribute(k_mma<128>, cudaFuncAttributeMaxDynamicSharedMemorySize, SM128);

    int nb = (n + 1023) / 1024;
    int spblocks = (n + 7) / 8;

    // ordered so launch #3 (profiled) = k_mma<256> layer 1
    k_zero<<<(n + 255) / 256, 256>>>(n);
    k_fc<<<148, 256, SMFC>>>(x, w1, b1, w2, b2, gam, bet, n);
    k_hist<<<(E + 255) / 256, 256>>>(erow, E);
    k_mma<256><<<148, 256, SM256>>>(hh, hl, gwn[0], gws[0], gb[0], supu, scl, self, n);

    k_scan1<<<nb, 1024>>>(n);
    k_scan2<<<1, 128>>>(nb);
    k_scan3<<<(n + 255) / 256, 256>>>(n);
    k_scatter<<<(E + 255) / 256, 256>>>(erow, ecol, eval, E);

    k_spmm128<<<spblocks, 256>>>(supu, scl, self, n);

    k_mma<256><<<148, 256, SM256>>>(hh, hl, gwn[1], gws[1], gb[1], supu, scl, self, n);
    k_spmm128<<<spblocks, 256>>>(supu, scl, self, n);

    k_mma<256><<<148, 256, SM256>>>(hh, hl, gwn[2], gws[2], gb[2], supu, scl, self, n);
    k_spmm128<<<spblocks, 256>>>(supu, scl, self, n);

    k_mma<128><<<148, 256, SM128>>>(hh, hl, gwn[3], gws[3], gb[3], supu, scl, self, n);
    k_spmm64<<<spblocks, 256>>>(supu, scl, self, out, n);
}

// round 13
// speedup vs baseline: 1.5801x; 1.0173x over previous
#include <cuda_runtime.h>
#include <cuda_bf16.h>
#include <cstdint>

#define MAX_N 100000
#define MAX_E 3200000

// ---------------- scratch ----------------------------------------------------
__device__ __align__(16) unsigned g_supu[MAX_N * 64];   // u16x2-packed sup
__device__ float g_scale[MAX_N];
__device__ float g_self[MAX_N * 128];
__device__ __align__(16) __nv_bfloat16 g_hh[MAX_N * 128];
__device__ __align__(16) __nv_bfloat16 g_hl[MAX_N * 128];
__device__ int  g_cnt[MAX_N];
__device__ int  g_off[MAX_N + 1];
__device__ int  g_cur[MAX_N];
__device__ int  g_bsum[128];
__device__ int  g_bscan[128];
__device__ __align__(8) int2 g_epack[MAX_E];   // (col, val bits)

#define QMAX 32760.0f
#define MAGIC_BIAS 8421376.0f   // 2^23 + 32768

// ---------------- helpers ----------------------------------------------------
__device__ __forceinline__ unsigned pack_bf2(float a, float b, float& ra, float& rb) {
    __nv_bfloat16 ha = __float2bfloat16_rn(a), hb = __float2bfloat16_rn(b);
    ra = a - __bfloat162float(ha);
    rb = b - __bfloat162float(hb);
    return ((unsigned)__bfloat16_as_ushort(hb) << 16) | (unsigned)__bfloat16_as_ushort(ha);
}
__device__ __forceinline__ unsigned pack_bf2n(float a, float b) {
    __nv_bfloat16 ha = __float2bfloat16_rn(a), hb = __float2bfloat16_rn(b);
    return ((unsigned)__bfloat16_as_ushort(hb) << 16) | (unsigned)__bfloat16_as_ushort(ha);
}

__device__ __forceinline__ void mma_bf16(float& d0, float& d1, float& d2, float& d3,
                                         uint32_t a0, uint32_t a1, uint32_t a2, uint32_t a3,
                                         uint32_t b0, uint32_t b1) {
    asm volatile("mma.sync.aligned.m16n8k16.row.col.f32.bf16.bf16.f32 "
                 "{%0,%1,%2,%3}, {%4,%5,%6,%7}, {%8,%9}, {%0,%1,%2,%3};"
                 : "+f"(d0), "+f"(d1), "+f"(d2), "+f"(d3)
                 : "r"(a0), "r"(a1), "r"(a2), "r"(a3), "r"(b0), "r"(b1));
}

__device__ __forceinline__ void ldsm4(uint32_t& r0, uint32_t& r1, uint32_t& r2, uint32_t& r3,
                                      uint32_t addr) {
    asm volatile("ldmatrix.sync.aligned.m8n8.x4.shared.b16 {%0,%1,%2,%3}, [%4];"
                 : "=r"(r0), "=r"(r1), "=r"(r2), "=r"(r3) : "r"(addr));
}

__device__ __forceinline__ uint32_t smem_u32(const void* p) {
    uint32_t a;
    asm("{ .reg .u64 t; cvta.to.shared.u64 t, %1; cvt.u32.u64 %0, t; }" : "=r"(a) : "l"(p));
    return a;
}

#define CP_ASYNC_CG(dst, src) \
    asm volatile("cp.async.cg.shared.global [%0], [%1], 16;" :: "r"(dst), "l"(src))
#define CP_COMMIT() asm volatile("cp.async.commit_group;" ::: "memory")
#define CP_WAIT1()  asm volatile("cp.async.wait_group 1;" ::: "memory")

// dequant: u16 packed in u32 -> two floats (value - 32768), exact, no I2F
__device__ __forceinline__ float dq_lo(unsigned d) {
    return __uint_as_float(__byte_perm(d, 0x4B000000u, 0x7410)) - MAGIC_BIAS;
}
__device__ __forceinline__ float dq_hi(unsigned d) {
    return __uint_as_float(__byte_perm(d, 0x4B000000u, 0x7432)) - MAGIC_BIAS;
}

// ---------------- CSR build --------------------------------------------------
__global__ void k_zero(int n) {
    int i = blockIdx.x * blockDim.x + threadIdx.x;
    if (i < n) g_cnt[i] = 0;
}
__global__ void k_hist(const int* __restrict__ rows, int E) {
    int i = blockIdx.x * blockDim.x + threadIdx.x;
    if (i < E) atomicAdd(&g_cnt[rows[i]], 1);
}
__global__ void k_scan1(int n) {
    __shared__ int buf[2][1024];
    int i = blockIdx.x * 1024 + threadIdx.x;
    int v = (i < n) ? g_cnt[i] : 0;
    int src = 0;
    buf[0][threadIdx.x] = v;
    for (int ofs = 1; ofs < 1024; ofs <<= 1) {
        __syncthreads();
        int t = buf[src][threadIdx.x];
        if ((int)threadIdx.x >= ofs) t += buf[src][threadIdx.x - ofs];
        buf[1 - src][threadIdx.x] = t;
        src ^= 1;
    }
    __syncthreads();
    int incl = buf[src][threadIdx.x];
    if (i < n) g_cnt[i] = incl;
    if (threadIdx.x == 1023) g_bsum[blockIdx.x] = incl;
}
__global__ void k_scan2(int nb) {
    __shared__ int buf[2][128];
    int tid = threadIdx.x;
    int v = (tid < nb) ? g_bsum[tid] : 0;
    int src = 0;
    buf[0][tid] = v;
    for (int ofs = 1; ofs < 128; ofs <<= 1) {
        __syncthreads();
        int t = buf[src][tid];
        if (tid >= ofs) t += buf[src][tid - ofs];
        buf[1 - src][tid] = t;
        src ^= 1;
    }
    __syncthreads();
    g_bscan[tid] = buf[src][tid];
}
__global__ void k_scan3(int n) {
    int i = blockIdx.x * blockDim.x + threadIdx.x;
    if (i < n) {
        int blk = i >> 10;
        int pre = blk ? g_bscan[blk - 1] : 0;
        g_off[i + 1] = g_cnt[i] + pre;
        if (i == 0) g_off[0] = 0;
        int prev = (i & 1023) ? g_cnt[i - 1] : 0;
        g_cur[i] = prev + pre;
    }
}
__global__ void k_scatter(const int* __restrict__ rows, const int* __restrict__ cols,
                          const float* __restrict__ vals, int E) {
    int e = blockIdx.x * blockDim.x + threadIdx.x;
    if (e < E) {
        int r = rows[e];
        int p = atomicAdd(&g_cur[r], 1);
        g_epack[p] = make_int2(cols[e], __float_as_int(vals[e]));
    }
}

// ---------------- HMMA fc: h = LN(relu(relu(x@w1T+b1)@w2T+b2)) -> bf16 hi/lo --
__global__ void __launch_bounds__(256, 1) k_fc(
    const float* __restrict__ x,
    const float* __restrict__ w1, const float* __restrict__ b1,
    const float* __restrict__ w2, const float* __restrict__ b2,
    const float* __restrict__ gamma, const float* __restrict__ beta, int n)
{
    constexpr int BSTRIDE = 68;
    extern __shared__ __align__(16) uint32_t sm32[];
    uint32_t* W1h = sm32;                 // [128][68]
    uint32_t* W1l = W1h + 128 * BSTRIDE;
    uint32_t* W2h = W1l + 128 * BSTRIDE;
    uint32_t* W2l = W2h + 128 * BSTRIDE;
    int tid = threadIdx.x, wid = tid >> 5, lane = tid & 31;
    uint32_t* Aw  = W2l + 128 * BSTRIDE + wid * (2 * 16 * BSTRIDE);
    uint32_t* Ahi = Aw;
    uint32_t* Alo = Aw + 16 * BSTRIDE;

    for (int i = tid; i < 128 * 64; i += 256) {
        int nn = i >> 6, q = i & 63;
        float2 a = *(const float2*)(w1 + nn * 128 + q * 2);
        float r0, r1;
        uint32_t h = pack_bf2(a.x, a.y, r0, r1);
        W1h[nn * BSTRIDE + q] = h;
        W1l[nn * BSTRIDE + q] = pack_bf2n(r0, r1);
        float2 b = *(const float2*)(w2 + nn * 128 + q * 2);
        uint32_t h2 = pack_bf2(b.x, b.y, r0, r1);
        W2h[nn * BSTRIDE + q] = h2;
        W2l[nn * BSTRIDE + q] = pack_bf2n(r0, r1);
    }
    __syncthreads();

    int q4 = lane & 3, r4 = lane >> 2;
    int ntiles = (n + 15) >> 4;

    for (int t = blockIdx.x * 8 + wid; t < ntiles; t += 148 * 8) {
        int rowBase = t << 4;
        for (int i = lane; i < 512; i += 32) {
            int r = i >> 5, f4 = i & 31;
            int grow = rowBase + r;
            if (grow > n - 1) grow = n - 1;
            float4 v = ((const float4*)(x + (size_t)grow * 128))[f4];
            float r0, r1;
            uint32_t h0 = pack_bf2(v.x, v.y, r0, r1);
            uint32_t l0 = pack_bf2n(r0, r1);
            uint32_t h1 = pack_bf2(v.z, v.w, r0, r1);
            uint32_t l1 = pack_bf2n(r0, r1);
            Ahi[r * BSTRIDE + f4 * 2] = h0;
            Ahi[r * BSTRIDE + f4 * 2 + 1] = h1;
            Alo[r * BSTRIDE + f4 * 2] = l0;
            Alo[r * BSTRIDE + f4 * 2 + 1] = l1;
        }
        __syncwarp();

        float acc[16][4];
        #pragma unroll
        for (int nt = 0; nt < 16; nt++)
            #pragma unroll
            for (int j = 0; j < 4; j++) acc[nt][j] = 0.f;

        #pragma unroll 1
        for (int pass = 0; pass < 3; pass++) {
            const uint32_t* As = (pass == 1) ? Alo : Ahi;
            const uint32_t* Bs = (pass == 2) ? W1l : W1h;
            const uint32_t* Arow0 = As + r4 * BSTRIDE + q4;
            const uint32_t* Arow8 = As + (r4 + 8) * BSTRIDE + q4;
            const uint32_t* Bbase = Bs + r4 * BSTRIDE + q4;
            #pragma unroll 2
            for (int ks = 0; ks < 8; ks++) {
                int kp = ks * 8;
                uint32_t a0 = Arow0[kp], a1 = Arow8[kp];
                uint32_t a2 = Arow0[kp + 4], a3 = Arow8[kp + 4];
                #pragma unroll
                for (int nt = 0; nt < 16; nt++) {
                    const uint32_t* bp = Bbase + nt * 8 * BSTRIDE + kp;
                    mma_bf16(acc[nt][0], acc[nt][1], acc[nt][2], acc[nt][3],
                             a0, a1, a2, a3, bp[0], bp[4]);
                }
            }
        }
        __syncwarp();
        #pragma unroll
        for (int nt = 0; nt < 16; nt++) {
            int col = nt * 8 + q4 * 2;
            float2 bv = *(const float2*)(b1 + col);
            float v0 = fmaxf(acc[nt][0] + bv.x, 0.f);
            float v1 = fmaxf(acc[nt][1] + bv.y, 0.f);
            float v2 = fmaxf(acc[nt][2] + bv.x, 0.f);
            float v3 = fmaxf(acc[nt][3] + bv.y, 0.f);
            float r0, r1;
            uint32_t h0 = pack_bf2(v0, v1, r0, r1);
            Ahi[r4 * BSTRIDE + nt * 4 + q4] = h0;
            Alo[r4 * BSTRIDE + nt * 4 + q4] = pack_bf2n(r0, r1);
            uint32_t h1 = pack_bf2(v2, v3, r0, r1);
            Ahi[(r4 + 8) * BSTRIDE + nt * 4 + q4] = h1;
            Alo[(r4 + 8) * BSTRIDE + nt * 4 + q4] = pack_bf2n(r0, r1);
        }
        __syncwarp();

        #pragma unroll
        for (int nt = 0; nt < 16; nt++)
            #pragma unroll
            for (int j = 0; j < 4; j++) acc[nt][j] = 0.f;

        #pragma unroll 1
        for (int pass = 0; pass < 3; pass++) {
            const uint32_t* As = (pass == 1) ? Alo : Ahi;
            const uint32_t* Bs = (pass == 2) ? W2l : W2h;
            const uint32_t* Arow0 = As + r4 * BSTRIDE + q4;
            const uint32_t* Arow8 = As + (r4 + 8) * BSTRIDE + q4;
            const uint32_t* Bbase = Bs + r4 * BSTRIDE + q4;
            #pragma unroll 2
            for (int ks = 0; ks < 8; ks++) {
                int kp = ks * 8;
                uint32_t a0 = Arow0[kp], a1 = Arow8[kp];
                uint32_t a2 = Arow0[kp + 4], a3 = Arow8[kp + 4];
                #pragma unroll
                for (int nt = 0; nt < 16; nt++) {
                    const uint32_t* bp = Bbase + nt * 8 * BSTRIDE + kp;
                    mma_bf16(acc[nt][0], acc[nt][1], acc[nt][2], acc[nt][3],
                             a0, a1, a2, a3, bp[0], bp[4]);
                }
            }
        }
        __syncwarp();

        float s0 = 0.f, q0 = 0.f, s1 = 0.f, q1 = 0.f;
        #pragma unroll
        for (int nt = 0; nt < 16; nt++) {
            int col = nt * 8 + q4 * 2;
            float2 bv = *(const float2*)(b2 + col);
            float v0 = fmaxf(acc[nt][0] + bv.x, 0.f);
            float v1 = fmaxf(acc[nt][1] + bv.y, 0.f);
            float v2 = fmaxf(acc[nt][2] + bv.x, 0.f);
            float v3 = fmaxf(acc[nt][3] + bv.y, 0.f);
            acc[nt][0] = v0; acc[nt][1] = v1; acc[nt][2] = v2; acc[nt][3] = v3;
            s0 += v0 + v1; q0 = fmaf(v0, v0, fmaf(v1, v1, q0));
            s1 += v2 + v3; q1 = fmaf(v2, v2, fmaf(v3, v3, q1));
        }
        #pragma unroll
        for (int o = 1; o <= 2; o <<= 1) {
            s0 += __shfl_xor_sync(0xffffffffu, s0, o);
            q0 += __shfl_xor_sync(0xffffffffu, q0, o);
            s1 += __shfl_xor_sync(0xffffffffu, s1, o);
            q1 += __shfl_xor_sync(0xffffffffu, q1, o);
        }
        float mean0 = s0 * (1.f / 128.f);
        float var0 = fmaxf((q0 - s0 * mean0) * (1.f / 127.f), 0.f);
        float inv0 = 1.f / (sqrtf(var0) + 1e-6f);
        float mean1 = s1 * (1.f / 128.f);
        float var1 = fmaxf((q1 - s1 * mean1) * (1.f / 127.f), 0.f);
        float inv1 = 1.f / (sqrtf(var1) + 1e-6f);

        #pragma unroll
        for (int nt = 0; nt < 16; nt++) {
            int col = nt * 8 + q4 * 2;
            float2 gg = *(const float2*)(gamma + col);
            float2 be = *(const float2*)(beta + col);
            float o0 = gg.x * (acc[nt][0] - mean0) * inv0 + be.x;
            float o1 = gg.y * (acc[nt][1] - mean0) * inv0 + be.y;
            float o2 = gg.x * (acc[nt][2] - mean1) * inv1 + be.x;
            float o3 = gg.y * (acc[nt][3] - mean1) * inv1 + be.y;
            float r0, r1;
            uint32_t h0 = pack_bf2(o0, o1, r0, r1);
            Ahi[r4 * BSTRIDE + nt * 4 + q4] = h0;
            Alo[r4 * BSTRIDE + nt * 4 + q4] = pack_bf2n(r0, r1);
            uint32_t h1 = pack_bf2(o2, o3, r0, r1);
            Ahi[(r4 + 8) * BSTRIDE + nt * 4 + q4] = h1;
            Alo[(r4 + 8) * BSTRIDE + nt * 4 + q4] = pack_bf2n(r0, r1);
        }
        __syncwarp();
        for (int idx = lane; idx < 256; idx += 32) {
            int r = idx >> 4, qv = idx & 15;
            int row = rowBase + r;
            if (row < n) {
                uint4 vh = *(const uint4*)(Ahi + r * BSTRIDE + qv * 4);
                uint4 vl = *(const uint4*)(Alo + r * BSTRIDE + qv * 4);
                ((uint4*)(g_hh + (size_t)row * 128))[qv] = vh;
                ((uint4*)(g_hl + (size_t)row * 128))[qv] = vl;
            }
        }
        __syncwarp();
    }
}

// ---------------- HMMA GCN GEMM + int16 row-scaled sup quantization ----------
template <int N2>
__global__ void __launch_bounds__(256, 1) k_mma(
    const __nv_bfloat16* __restrict__ hh, const __nv_bfloat16* __restrict__ hl,
    const float* __restrict__ wn, const float* __restrict__ ws,
    const float* __restrict__ bias,
    unsigned* __restrict__ supu, float* __restrict__ scaleArr,
    float* __restrict__ selfb, int n)
{
    constexpr int OUT = N2 / 2;
    constexpr int WPG = N2 / 32;
    constexpr int G = 8 / WPG;
    constexpr int BSTRIDE = 68;
    constexpr int TM = 32;
    constexpr int ABUF = 2 * TM * BSTRIDE;
    constexpr int AOFF = 2 * N2 * BSTRIDE;
    constexpr int RMOFF = AOFF + G * 2 * ABUF;
    constexpr int SUPW = OUT / 2;

    extern __shared__ __align__(16) uint32_t sm32[];
    uint32_t* Bh = sm32;
    uint32_t* Bl = Bh + N2 * BSTRIDE;

    int tid = threadIdx.x, wid = tid >> 5, lane = tid & 31;
    int g = wid / WPG, wg = wid % WPG;
    int lt = tid - g * (WPG * 32);
    int q4 = lane & 3, r4 = lane >> 2;
    uint32_t smemU = smem_u32(sm32);
    unsigned* rmax = (unsigned*)(sm32 + RMOFF + g * TM);

    for (int i = tid; i < N2 * 64; i += 256) {
        int kp = i / N2, nn = i % N2;
        float a0, a1;
        if (nn < OUT) {
            a0 = wn[(2 * kp) * OUT + nn];
            a1 = wn[(2 * kp + 1) * OUT + nn];
        } else {
            a0 = ws[(2 * kp) * OUT + nn - OUT];
            a1 = ws[(2 * kp + 1) * OUT + nn - OUT];
        }
        float r0, r1;
        uint32_t h = pack_bf2(a0, a1, r0, r1);
        Bh[nn * BSTRIDE + kp] = h;
        Bl[nn * BSTRIDE + kp] = pack_bf2n(r0, r1);
    }
    __syncthreads();

    uint32_t bh[4][8][2], bl[4][8][2];
    #pragma unroll
    for (int nt = 0; nt < 4; nt++) {
        #pragma unroll
        for (int ks = 0; ks < 8; ks++) {
            const uint32_t* p  = Bh + (wg * 32 + nt * 8 + r4) * BSTRIDE + ks * 8 + q4;
            const uint32_t* pl = Bl + (wg * 32 + nt * 8 + r4) * BSTRIDE + ks * 8 + q4;
            bh[nt][ks][0] = p[0];  bh[nt][ks][1] = p[4];
            bl[nt][ks][0] = pl[0]; bl[nt][ks][1] = pl[4];
        }
    }

    uint32_t loff = ((((lane & 7) + ((lane >> 3) & 1) * 8) * BSTRIDE + (lane >> 4) * 4)) * 4;

    int ntasks = (n + TM - 1) / TM;
    int stride = 148 * G;
    int t0 = blockIdx.x * G + g;
    int iters = (ntasks + stride - 1) / stride;

    auto prefetch = [&](int t, int buf) {
        uint32_t abU = smemU + (AOFF + (g * 2 + buf) * ABUF) * 4;
        int rowBase = t * TM;
        for (int i = lt; i < TM * 16; i += WPG * 32) {
            int r = i >> 4, q = i & 15;
            int grow = rowBase + r;
            if (grow > n - 1) grow = n - 1;
            uint32_t dh = abU + (r * BSTRIDE + q * 4) * 4;
            CP_ASYNC_CG(dh, ((const uint4*)(hh + (size_t)grow * 128)) + q);
            CP_ASYNC_CG(dh + TM * BSTRIDE * 4, ((const uint4*)(hl + (size_t)grow * 128)) + q);
        }
    };

    if (t0 < ntasks) prefetch(t0, 0);
    CP_COMMIT();

    int cur = 0;
    for (int it = 0; it < iters; it++) {
        int t = t0 + it * stride;
        int tn = t + stride;

        if (tn < ntasks) prefetch(tn, cur ^ 1);
        CP_COMMIT();
        CP_WAIT1();
        if (lt < TM) rmax[lt] = 0;
        __syncthreads();

        float acc[2][4][4];
        if (t < ntasks) {
            uint32_t abU = smemU + (AOFF + (g * 2 + cur) * ABUF) * 4 + loff;

            #pragma unroll
            for (int s = 0; s < 2; s++)
                #pragma unroll
                for (int nt = 0; nt < 4; nt++)
                    #pragma unroll
                    for (int j = 0; j < 4; j++) acc[s][nt][j] = 0.f;

            #pragma unroll
            for (int ks = 0; ks < 8; ks++) {
                #pragma unroll
                for (int s = 0; s < 2; s++) {
                    uint32_t ah0, ah1, ah2, ah3, al0, al1, al2, al3;
                    uint32_t base = abU + (s * 16 * BSTRIDE + ks * 8) * 4;
                    ldsm4(ah0, ah1, ah2, ah3, base);
                    ldsm4(al0, al1, al2, al3, base + TM * BSTRIDE * 4);
                    #pragma unroll
                    for (int nt = 0; nt < 4; nt++) {
                        mma_bf16(acc[s][nt][0], acc[s][nt][1], acc[s][nt][2], acc[s][nt][3],
                                 ah0, ah1, ah2, ah3, bh[nt][ks][0], bh[nt][ks][1]);
                        mma_bf16(acc[s][nt][0], acc[s][nt][1], acc[s][nt][2], acc[s][nt][3],
                                 al0, al1, al2, al3, bh[nt][ks][0], bh[nt][ks][1]);
                        mma_bf16(acc[s][nt][0], acc[s][nt][1], acc[s][nt][2], acc[s][nt][3],
                                 ah0, ah1, ah2, ah3, bl[nt][ks][0], bl[nt][ks][1]);
                    }
                }
            }

            if (wg < WPG / 2) {
                #pragma unroll
                for (int s = 0; s < 2; s++) {
                    float m0 = 0.f, m1 = 0.f;
                    #pragma unroll
                    for (int nt = 0; nt < 4; nt++) {
                        m0 = fmaxf(m0, fmaxf(fabsf(acc[s][nt][0]), fabsf(acc[s][nt][1])));
                        m1 = fmaxf(m1, fmaxf(fabsf(acc[s][nt][2]), fabsf(acc[s][nt][3])));
                    }
                    #pragma unroll
                    for (int o = 1; o <= 2; o <<= 1) {
                        m0 = fmaxf(m0, __shfl_xor_sync(0xffffffffu, m0, o));
                        m1 = fmaxf(m1, __shfl_xor_sync(0xffffffffu, m1, o));
                    }
                    if (q4 == 0) {
                        atomicMax(&rmax[s * 16 + r4], __float_as_uint(m0));
                        atomicMax(&rmax[s * 16 + r4 + 8], __float_as_uint(m1));
                    }
                }
            }
        }
        __syncthreads();

        if (t < ntasks) {
            int rowBase = t * TM;
            if (wg < WPG / 2) {
                #pragma unroll
                for (int s = 0; s < 2; s++) {
                    int row0 = rowBase + s * 16 + r4, row1 = row0 + 8;
                    float rm0 = __uint_as_float(rmax[s * 16 + r4]);
                    float rm1 = __uint_as_float(rmax[s * 16 + r4 + 8]);
                    float iv0 = rm0 > 0.f ? QMAX / rm0 : 0.f;
                    float iv1 = rm1 > 0.f ? QMAX / rm1 : 0.f;
                    #pragma unroll
                    for (int nt = 0; nt < 4; nt++) {
                        int col = wg * 32 + nt * 8 + q4 * 2;
                        unsigned u0 = (unsigned)__float2int_rn(fmaf(acc[s][nt][0], iv0, 32768.f));
                        unsigned u1 = (unsigned)__float2int_rn(fmaf(acc[s][nt][1], iv0, 32768.f));
                        unsigned u2 = (unsigned)__float2int_rn(fmaf(acc[s][nt][2], iv1, 32768.f));
                        unsigned u3 = (unsigned)__float2int_rn(fmaf(acc[s][nt][3], iv1, 32768.f));
                        if (row0 < n) supu[(size_t)row0 * SUPW + (col >> 1)] = (u0 & 0xffffu) | (u1 << 16);
                        if (row1 < n) supu[(size_t)row1 * SUPW + (col >> 1)] = (u2 & 0xffffu) | (u3 << 16);
                    }
                    if (wg == 0 && q4 == 0) {
                        if (row0 < n) scaleArr[row0] = rm0 * (1.f / QMAX);
                        if (row1 < n) scaleArr[row1] = rm1 * (1.f / QMAX);
                    }
                }
            } else {
                #pragma unroll
                for (int s = 0; s < 2; s++) {
                    int row0 = rowBase + s * 16 + r4, row1 = row0 + 8;
                    #pragma unroll
                    for (int nt = 0; nt < 4; nt++) {
                        int c = wg * 32 + nt * 8 + q4 * 2 - OUT;
                        float2 bv = *(const float2*)(bias + c);
                        if (row0 < n) *(float2*)(selfb + (size_t)row0 * OUT + c) = make_float2(acc[s][nt][0] + bv.x, acc[s][nt][1] + bv.y);
                        if (row1 < n) *(float2*)(selfb + (size_t)row1 * OUT + c) = make_float2(acc[s][nt][2] + bv.x, acc[s][nt][3] + bv.y);
                    }
                }
            }
        }
        __syncthreads();
        cur ^= 1;
    }
}

// ---------------- sparse aggregation (u16 dequant, 4-edge MLP) + relu --------
__global__ void k_spmm128(const unsigned* __restrict__ supu, const float* __restrict__ scaleArr,
                          const float* __restrict__ selfb, int n)
{
    int warp = (blockIdx.x * blockDim.x + threadIdx.x) >> 5;
    int lane = threadIdx.x & 31;
    if (warp >= n) return;
    int e0 = g_off[warp], e1 = g_off[warp + 1];

    float4 acc = make_float4(0.f, 0.f, 0.f, 0.f);
    int e = e0;
    for (; e + 3 < e1; e += 4) {
        int2 p0 = __ldg(&g_epack[e]);
        int2 p1 = __ldg(&g_epack[e + 1]);
        int2 p2 = __ldg(&g_epack[e + 2]);
        int2 p3 = __ldg(&g_epack[e + 3]);
        float m0 = __int_as_float(p0.y) * __ldg(&scaleArr[p0.x]);
        float m1 = __int_as_float(p1.y) * __ldg(&scaleArr[p1.x]);
        float m2 = __int_as_float(p2.y) * __ldg(&scaleArr[p2.x]);
        float m3 = __int_as_float(p3.y) * __ldg(&scaleArr[p3.x]);
        uint2 d0 = ((const uint2*)(supu + (size_t)p0.x * 64))[lane];
        uint2 d1 = ((const uint2*)(supu + (size_t)p1.x * 64))[lane];
        uint2 d2 = ((const uint2*)(supu + (size_t)p2.x * 64))[lane];
        uint2 d3 = ((const uint2*)(supu + (size_t)p3.x * 64))[lane];
        acc.x = fmaf(m0, dq_lo(d0.x), fmaf(m1, dq_lo(d1.x), acc.x));
        acc.y = fmaf(m0, dq_hi(d0.x), fmaf(m1, dq_hi(d1.x), acc.y));
        acc.z = fmaf(m0, dq_lo(d0.y), fmaf(m1, dq_lo(d1.y), acc.z));
        acc.w = fmaf(m0, dq_hi(d0.y), fmaf(m1, dq_hi(d1.y), acc.w));
        acc.x = fmaf(m2, dq_lo(d2.x), fmaf(m3, dq_lo(d3.x), acc.x));
        acc.y = fmaf(m2, dq_hi(d2.x), fmaf(m3, dq_hi(d3.x), acc.y));
        acc.z = fmaf(m2, dq_lo(d2.y), fmaf(m3, dq_lo(d3.y), acc.z));
        acc.w = fmaf(m2, dq_hi(d2.y), fmaf(m3, dq_hi(d3.y), acc.w));
    }
    for (; e < e1; e++) {
        int2 p0 = __ldg(&g_epack[e]);
        float m0 = __int_as_float(p0.y) * __ldg(&scaleArr[p0.x]);
        uint2 d0 = ((const uint2*)(supu + (size_t)p0.x * 64))[lane];
        acc.x = fmaf(m0, dq_lo(d0.x), acc.x);
        acc.y = fmaf(m0, dq_hi(d0.x), acc.y);
        acc.z = fmaf(m0, dq_lo(d0.y), acc.z);
        acc.w = fmaf(m0, dq_hi(d0.y), acc.w);
    }
    float4 sb = ((const float4*)(selfb + (size_t)warp * 128))[lane];
    float o0 = fmaxf(acc.x + sb.x, 0.f);
    float o1 = fmaxf(acc.y + sb.y, 0.f);
    float o2 = fmaxf(acc.z + sb.z, 0.f);
    float o3 = fmaxf(acc.w + sb.w, 0.f);
    float l0, l1, l2, l3;
    unsigned p01 = pack_bf2(o0, o1, l0, l1);
    unsigned p23 = pack_bf2(o2, o3, l2, l3);
    ((uint2*)(g_hh + (size_t)warp * 128))[lane] = make_uint2(p01, p23);
    ((uint2*)(g_hl + (size_t)warp * 128))[lane] = make_uint2(pack_bf2n(l0, l1), pack_bf2n(l2, l3));
}

__global__ void k_spmm64(const unsigned* __restrict__ supu, const float* __restrict__ scaleArr,
                         const float* __restrict__ selfb, float* __restrict__ out, int n)
{
    int warp = (blockIdx.x * blockDim.x + threadIdx.x) >> 5;
    int lane = threadIdx.x & 31;
    if (warp >= n) return;
    int e0 = g_off[warp], e1 = g_off[warp + 1];

    float2 acc = make_float2(0.f, 0.f);
    int e = e0;
    for (; e + 3 < e1; e += 4) {
        int2 p0 = __ldg(&g_epack[e]);
        int2 p1 = __ldg(&g_epack[e + 1]);
        int2 p2 = __ldg(&g_epack[e + 2]);
        int2 p3 = __ldg(&g_epack[e + 3]);
        float m0 = __int_as_float(p0.y) * __ldg(&scaleArr[p0.x]);
        float m1 = __int_as_float(p1.y) * __ldg(&scaleArr[p1.x]);
        float m2 = __int_as_float(p2.y) * __ldg(&scaleArr[p2.x]);
        float m3 = __int_as_float(p3.y) * __ldg(&scaleArr[p3.x]);
        unsigned d0 = ((const unsigned*)(supu + (size_t)p0.x * 32))[lane];
        unsigned d1 = ((const unsigned*)(supu + (size_t)p1.x * 32))[lane];
        unsigned d2 = ((const unsigned*)(supu + (size_t)p2.x * 32))[lane];
        unsigned d3 = ((const unsigned*)(supu + (size_t)p3.x * 32))[lane];
        acc.x = fmaf(m0, dq_lo(d0), fmaf(m1, dq_lo(d1), acc.x));
        acc.y = fmaf(m0, dq_hi(d0), fmaf(m1, dq_hi(d1), acc.y));
        acc.x = fmaf(m2, dq_lo(d2), fmaf(m3, dq_lo(d3), acc.x));
        acc.y = fmaf(m2, dq_hi(d2), fmaf(m3, dq_hi(d3), acc.y));
    }
    for (; e < e1; e++) {
        int2 p0 = __ldg(&g_epack[e]);
        float m0 = __int_as_float(p0.y) * __ldg(&scaleArr[p0.x]);
        unsigned d0 = ((const unsigned*)(supu + (size_t)p0.x * 32))[lane];
        acc.x = fmaf(m0, dq_lo(d0), acc.x);
        acc.y = fmaf(m0, dq_hi(d0), acc.y);
    }
    float2 sb = ((const float2*)(selfb + (size_t)warp * 64))[lane];
    float2 o;
    o.x = fmaxf(acc.x + sb.x, 0.f);
    o.y = fmaxf(acc.y + sb.y, 0.f);
    ((float2*)(out + (size_t)warp * 64))[lane] = o;
}

// ---------------- launch -----------------------------------------------------
extern "C" void kernel_launch(void* const* d_in, const int* in_sizes, int n_in,
                              void* d_out, int out_size)
{
    const float* x    = (const float*)d_in[0];
    const int*   erow = (const int*)d_in[1];
    const int*   ecol = (const int*)d_in[2];
    const float* eval = (const float*)d_in[3];
    const float* w1   = (const float*)d_in[4];
    const float* b1   = (const float*)d_in[5];
    const float* w2   = (const float*)d_in[6];
    const float* b2   = (const float*)d_in[7];
    const float* gam  = (const float*)d_in[8];
    const float* bet  = (const float*)d_in[9];
    const float* gwn[4] = {(const float*)d_in[10], (const float*)d_in[13],
                           (const float*)d_in[16], (const float*)d_in[19]};
    const float* gws[4] = {(const float*)d_in[11], (const float*)d_in[14],
                           (const float*)d_in[17], (const float*)d_in[20]};
    const float* gb[4]  = {(const float*)d_in[12], (const float*)d_in[15],
                           (const float*)d_in[18], (const float*)d_in[21]};
    float* out = (float*)d_out;

    int n = in_sizes[0] / 128;
    int E = in_sizes[1];

    float *self, *scl;
    unsigned* supu;
    __nv_bfloat16 *hh, *hl;
    cudaGetSymbolAddress((void**)&supu, g_supu);
    cudaGetSymbolAddress((void**)&scl, g_scale);
    cudaGetSymbolAddress((void**)&self, g_self);
    cudaGetSymbolAddress((void**)&hh, g_hh);
    cudaGetSymbolAddress((void**)&hl, g_hl);

    const int SMFC  = (4 * 128 * 68 + 8 * 2 * 16 * 68) * 4;               // 208896
    const int SM256 = (2 * 256 * 68 + 1 * 2 * 2 * 32 * 68) * 4 + 1 * 32 * 4;
    const int SM128 = (2 * 128 * 68 + 2 * 2 * 2 * 32 * 68) * 4 + 2 * 32 * 4;

    cudaFuncSetAttribute(k_fc, cudaFuncAttributeMaxDynamicSharedMemorySize, SMFC);
    cudaFuncSetAttribute(k_mma<256>, cudaFuncAttributeMaxDynamicSharedMemorySize, SM256);
    cudaFuncSetAttribute(k_mma<128>, cudaFuncAttributeMaxDynamicSharedMemorySize, SM128);

    int nb = (n + 1023) / 1024;
    int spblocks = (n + 7) / 8;

    // ordered so launch #3 (profiled) = k_fc this round
    k_zero<<<(n + 255) / 256, 256>>>(n);
    k_hist<<<(E + 255) / 256, 256>>>(erow, E);
    k_scan1<<<nb, 1024>>>(n);
    k_fc<<<148, 256, SMFC>>>(x, w1, b1, w2, b2, gam, bet, n);

    k_scan2<<<1, 128>>>(nb);
    k_scan3<<<(n + 255) / 256, 256>>>(n);
    k_scatter<<<(E + 255) / 256, 256>>>(erow, ecol, eval, E);

    k_mma<256><<<148, 256, SM256>>>(hh, hl, gwn[0], gws[0], gb[0], supu, scl, self, n);
    k_spmm128<<<spblocks, 256>>>(supu, scl, self, n);

    k_mma<256><<<148, 256, SM256>>>(hh, hl, gwn[1], gws[1], gb[1], supu, scl, self, n);
    k_spmm128<<<spblocks, 256>>>(supu, scl, self, n);

    k_mma<256><<<148, 256, SM256>>>(hh, hl, gwn[2], gws[2], gb[2], supu, scl, self, n);
    k_spmm128<<<spblocks, 256>>>(supu, scl, self, n);

    k_mma<128><<<148, 256, SM128>>>(hh, hl, gwn[3], gws[3], gb[3], supu, scl, self, n);
    k_spmm64<<<spblocks, 256>>>(supu, scl, self, out, n);
}

// round 14
// speedup vs baseline: 1.6994x; 1.0755x over previous
#include <cuda_runtime.h>
#include <cuda_fp16.h>
#include <cstdint>

#define MAX_N 100000
#define MAX_E 3200000

// ---------------- scratch ----------------------------------------------------
__device__ __align__(16) unsigned g_supu[MAX_N * 64];   // u16x2-packed sup
__device__ float g_scale[MAX_N];
__device__ float g_self[MAX_N * 128];
// fp16 hi/lo planes of h (16-bit containers)
__device__ __align__(16) unsigned short g_hh[MAX_N * 128];
__device__ __align__(16) unsigned short g_hl[MAX_N * 128];
__device__ int  g_cnt[MAX_N];
__device__ int  g_off[MAX_N + 1];
__device__ int  g_cur[MAX_N];
__device__ int  g_bsum[128];
__device__ int  g_bscan[128];
__device__ __align__(8) int2 g_epack[MAX_E];   // (col, val bits)

#define QMAX 32760.0f
#define MAGIC_BIAS 8421376.0f   // 2^23 + 32768

// ---------------- helpers ----------------------------------------------------
// pack two floats into fp16x2 word, returning fp32 residuals
__device__ __forceinline__ unsigned pack_h2(float a, float b, float& ra, float& rb) {
    __half ha = __float2half_rn(a), hb = __float2half_rn(b);
    ra = a - __half2float(ha);
    rb = b - __half2float(hb);
    return ((unsigned)__half_as_ushort(hb) << 16) | (unsigned)__half_as_ushort(ha);
}
__device__ __forceinline__ unsigned pack_h2n(float a, float b) {
    __half ha = __float2half_rn(a), hb = __float2half_rn(b);
    return ((unsigned)__half_as_ushort(hb) << 16) | (unsigned)__half_as_ushort(ha);
}

__device__ __forceinline__ void mma_f16(float& d0, float& d1, float& d2, float& d3,
                                        uint32_t a0, uint32_t a1, uint32_t a2, uint32_t a3,
                                        uint32_t b0, uint32_t b1) {
    asm volatile("mma.sync.aligned.m16n8k16.row.col.f32.f16.f16.f32 "
                 "{%0,%1,%2,%3}, {%4,%5,%6,%7}, {%8,%9}, {%0,%1,%2,%3};"
                 : "+f"(d0), "+f"(d1), "+f"(d2), "+f"(d3)
                 : "r"(a0), "r"(a1), "r"(a2), "r"(a3), "r"(b0), "r"(b1));
}

__device__ __forceinline__ void ldsm4(uint32_t& r0, uint32_t& r1, uint32_t& r2, uint32_t& r3,
                                      uint32_t addr) {
    asm volatile("ldmatrix.sync.aligned.m8n8.x4.shared.b16 {%0,%1,%2,%3}, [%4];"
                 : "=r"(r0), "=r"(r1), "=r"(r2), "=r"(r3) : "r"(addr));
}

__device__ __forceinline__ uint32_t smem_u32(const void* p) {
    uint32_t a;
    asm("{ .reg .u64 t; cvta.to.shared.u64 t, %1; cvt.u32.u64 %0, t; }" : "=r"(a) : "l"(p));
    return a;
}

#define CP_ASYNC_CG(dst, src) \
    asm volatile("cp.async.cg.shared.global [%0], [%1], 16;" :: "r"(dst), "l"(src))
#define CP_COMMIT() asm volatile("cp.async.commit_group;" ::: "memory")
#define CP_WAIT1()  asm volatile("cp.async.wait_group 1;" ::: "memory")

// dequant: u16 packed in u32 -> two floats (value - 32768), exact, no I2F
__device__ __forceinline__ float dq_lo(unsigned d) {
    return __uint_as_float(__byte_perm(d, 0x4B000000u, 0x7410)) - MAGIC_BIAS;
}
__device__ __forceinline__ float dq_hi(unsigned d) {
    return __uint_as_float(__byte_perm(d, 0x4B000000u, 0x7432)) - MAGIC_BIAS;
}

// ---------------- CSR build --------------------------------------------------
__global__ void k_zero(int n) {
    int i = blockIdx.x * blockDim.x + threadIdx.x;
    if (i < n) g_cnt[i] = 0;
}
__global__ void k_hist(const int* __restrict__ rows, int E) {
    int i = blockIdx.x * blockDim.x + threadIdx.x;
    if (i < E) atomicAdd(&g_cnt[rows[i]], 1);
}
__global__ void k_scan1(int n) {
    __shared__ int buf[2][1024];
    int i = blockIdx.x * 1024 + threadIdx.x;
    int v = (i < n) ? g_cnt[i] : 0;
    int src = 0;
    buf[0][threadIdx.x] = v;
    for (int ofs = 1; ofs < 1024; ofs <<= 1) {
        __syncthreads();
        int t = buf[src][threadIdx.x];
        if ((int)threadIdx.x >= ofs) t += buf[src][threadIdx.x - ofs];
        buf[1 - src][threadIdx.x] = t;
        src ^= 1;
    }
    __syncthreads();
    int incl = buf[src][threadIdx.x];
    if (i < n) g_cnt[i] = incl;
    if (threadIdx.x == 1023) g_bsum[blockIdx.x] = incl;
}
__global__ void k_scan2(int nb) {
    __shared__ int buf[2][128];
    int tid = threadIdx.x;
    int v = (tid < nb) ? g_bsum[tid] : 0;
    int src = 0;
    buf[0][tid] = v;
    for (int ofs = 1; ofs < 128; ofs <<= 1) {
        __syncthreads();
        int t = buf[src][tid];
        if (tid >= ofs) t += buf[src][tid - ofs];
        buf[1 - src][tid] = t;
        src ^= 1;
    }
    __syncthreads();
    g_bscan[tid] = buf[src][tid];
}
__global__ void k_scan3(int n) {
    int i = blockIdx.x * blockDim.x + threadIdx.x;
    if (i < n) {
        int blk = i >> 10;
        int pre = blk ? g_bscan[blk - 1] : 0;
        g_off[i + 1] = g_cnt[i] + pre;
        if (i == 0) g_off[0] = 0;
        int prev = (i & 1023) ? g_cnt[i - 1] : 0;
        g_cur[i] = prev + pre;
    }
}
__global__ void k_scatter(const int* __restrict__ rows, const int* __restrict__ cols,
                          const float* __restrict__ vals, int E) {
    int e = blockIdx.x * blockDim.x + threadIdx.x;
    if (e < E) {
        int r = rows[e];
        int p = atomicAdd(&g_cur[r], 1);
        g_epack[p] = make_int2(cols[e], __float_as_int(vals[e]));
    }
}

// ---------------- HMMA fc (fp16 2-pass): h = LN(relu(relu(x@w1T+b1)@w2T+b2)) --
__global__ void __launch_bounds__(256, 1) k_fc(
    const float* __restrict__ x,
    const float* __restrict__ w1, const float* __restrict__ b1,
    const float* __restrict__ w2, const float* __restrict__ b2,
    const float* __restrict__ gamma, const float* __restrict__ beta, int n)
{
    constexpr int BSTRIDE = 68;
    extern __shared__ __align__(16) uint32_t sm32[];
    uint32_t* W1h = sm32;                 // [128][68] fp16x2 hi
    uint32_t* W2h = W1h + 128 * BSTRIDE;
    int tid = threadIdx.x, wid = tid >> 5, lane = tid & 31;
    uint32_t* Aw  = W2h + 128 * BSTRIDE + wid * (2 * 16 * BSTRIDE);
    uint32_t* Ahi = Aw;
    uint32_t* Alo = Aw + 16 * BSTRIDE;

    for (int i = tid; i < 128 * 64; i += 256) {
        int nn = i >> 6, q = i & 63;
        float2 a = *(const float2*)(w1 + nn * 128 + q * 2);
        W1h[nn * BSTRIDE + q] = pack_h2n(a.x, a.y);
        float2 b = *(const float2*)(w2 + nn * 128 + q * 2);
        W2h[nn * BSTRIDE + q] = pack_h2n(b.x, b.y);
    }
    __syncthreads();

    int q4 = lane & 3, r4 = lane >> 2;
    int ntiles = (n + 15) >> 4;

    for (int t = blockIdx.x * 8 + wid; t < ntiles; t += 148 * 8) {
        int rowBase = t << 4;
        for (int i = lane; i < 512; i += 32) {
            int r = i >> 5, f4 = i & 31;
            int grow = rowBase + r;
            if (grow > n - 1) grow = n - 1;
            float4 v = ((const float4*)(x + (size_t)grow * 128))[f4];
            float r0, r1;
            uint32_t h0 = pack_h2(v.x, v.y, r0, r1);
            uint32_t l0 = pack_h2n(r0, r1);
            uint32_t h1 = pack_h2(v.z, v.w, r0, r1);
            uint32_t l1 = pack_h2n(r0, r1);
            Ahi[r * BSTRIDE + f4 * 2] = h0;
            Ahi[r * BSTRIDE + f4 * 2 + 1] = h1;
            Alo[r * BSTRIDE + f4 * 2] = l0;
            Alo[r * BSTRIDE + f4 * 2 + 1] = l1;
        }
        __syncwarp();

        float acc[16][4];
        #pragma unroll
        for (int nt = 0; nt < 16; nt++)
            #pragma unroll
            for (int j = 0; j < 4; j++) acc[nt][j] = 0.f;

        #pragma unroll 1
        for (int pass = 0; pass < 2; pass++) {
            const uint32_t* As = pass ? Alo : Ahi;
            const uint32_t* Arow0 = As + r4 * BSTRIDE + q4;
            const uint32_t* Arow8 = As + (r4 + 8) * BSTRIDE + q4;
            const uint32_t* Bbase = W1h + r4 * BSTRIDE + q4;
            #pragma unroll 2
            for (int ks = 0; ks < 8; ks++) {
                int kp = ks * 8;
                uint32_t a0 = Arow0[kp], a1 = Arow8[kp];
                uint32_t a2 = Arow0[kp + 4], a3 = Arow8[kp + 4];
                #pragma unroll
                for (int nt = 0; nt < 16; nt++) {
                    const uint32_t* bp = Bbase + nt * 8 * BSTRIDE + kp;
                    mma_f16(acc[nt][0], acc[nt][1], acc[nt][2], acc[nt][3],
                            a0, a1, a2, a3, bp[0], bp[4]);
                }
            }
        }
        __syncwarp();
        #pragma unroll
        for (int nt = 0; nt < 16; nt++) {
            int col = nt * 8 + q4 * 2;
            float2 bv = *(const float2*)(b1 + col);
            float v0 = fmaxf(acc[nt][0] + bv.x, 0.f);
            float v1 = fmaxf(acc[nt][1] + bv.y, 0.f);
            float v2 = fmaxf(acc[nt][2] + bv.x, 0.f);
            float v3 = fmaxf(acc[nt][3] + bv.y, 0.f);
            float r0, r1;
            uint32_t h0 = pack_h2(v0, v1, r0, r1);
            Ahi[r4 * BSTRIDE + nt * 4 + q4] = h0;
            Alo[r4 * BSTRIDE + nt * 4 + q4] = pack_h2n(r0, r1);
            uint32_t h1 = pack_h2(v2, v3, r0, r1);
            Ahi[(r4 + 8) * BSTRIDE + nt * 4 + q4] = h1;
            Alo[(r4 + 8) * BSTRIDE + nt * 4 + q4] = pack_h2n(r0, r1);
        }
        __syncwarp();

        #pragma unroll
        for (int nt = 0; nt < 16; nt++)
            #pragma unroll
            for (int j = 0; j < 4; j++) acc[nt][j] = 0.f;

        #pragma unroll 1
        for (int pass = 0; pass < 2; pass++) {
            const uint32_t* As = pass ? Alo : Ahi;
            const uint32_t* Arow0 = As + r4 * BSTRIDE + q4;
            const uint32_t* Arow8 = As + (r4 + 8) * BSTRIDE + q4;
            const uint32_t* Bbase = W2h + r4 * BSTRIDE + q4;
            #pragma unroll 2
            for (int ks = 0; ks < 8; ks++) {
                int kp = ks * 8;
                uint32_t a0 = Arow0[kp], a1 = Arow8[kp];
                uint32_t a2 = Arow0[kp + 4], a3 = Arow8[kp + 4];
                #pragma unroll
                for (int nt = 0; nt < 16; nt++) {
                    const uint32_t* bp = Bbase + nt * 8 * BSTRIDE + kp;
                    mma_f16(acc[nt][0], acc[nt][1], acc[nt][2], acc[nt][3],
                            a0, a1, a2, a3, bp[0], bp[4]);
                }
            }
        }
        __syncwarp();

        float s0 = 0.f, q0 = 0.f, s1 = 0.f, q1 = 0.f;
        #pragma unroll
        for (int nt = 0; nt < 16; nt++) {
            int col = nt * 8 + q4 * 2;
            float2 bv = *(const float2*)(b2 + col);
            float v0 = fmaxf(acc[nt][0] + bv.x, 0.f);
            float v1 = fmaxf(acc[nt][1] + bv.y, 0.f);
            float v2 = fmaxf(acc[nt][2] + bv.x, 0.f);
            float v3 = fmaxf(acc[nt][3] + bv.y, 0.f);
            acc[nt][0] = v0; acc[nt][1] = v1; acc[nt][2] = v2; acc[nt][3] = v3;
            s0 += v0 + v1; q0 = fmaf(v0, v0, fmaf(v1, v1, q0));
            s1 += v2 + v3; q1 = fmaf(v2, v2, fmaf(v3, v3, q1));
        }
        #pragma unroll
        for (int o = 1; o <= 2; o <<= 1) {
            s0 += __shfl_xor_sync(0xffffffffu, s0, o);
            q0 += __shfl_xor_sync(0xffffffffu, q0, o);
            s1 += __shfl_xor_sync(0xffffffffu, s1, o);
            q1 += __shfl_xor_sync(0xffffffffu, q1, o);
        }
        float mean0 = s0 * (1.f / 128.f);
        float var0 = fmaxf((q0 - s0 * mean0) * (1.f / 127.f), 0.f);
        float inv0 = 1.f / (sqrtf(var0) + 1e-6f);
        float mean1 = s1 * (1.f / 128.f);
        float var1 = fmaxf((q1 - s1 * mean1) * (1.f / 127.f), 0.f);
        float inv1 = 1.f / (sqrtf(var1) + 1e-6f);

        #pragma unroll
        for (int nt = 0; nt < 16; nt++) {
            int col = nt * 8 + q4 * 2;
            float2 gg = *(const float2*)(gamma + col);
            float2 be = *(const float2*)(beta + col);
            float o0 = gg.x * (acc[nt][0] - mean0) * inv0 + be.x;
            float o1 = gg.y * (acc[nt][1] - mean0) * inv0 + be.y;
            float o2 = gg.x * (acc[nt][2] - mean1) * inv1 + be.x;
            float o3 = gg.y * (acc[nt][3] - mean1) * inv1 + be.y;
            float r0, r1;
            uint32_t h0 = pack_h2(o0, o1, r0, r1);
            Ahi[r4 * BSTRIDE + nt * 4 + q4] = h0;
            Alo[r4 * BSTRIDE + nt * 4 + q4] = pack_h2n(r0, r1);
            uint32_t h1 = pack_h2(o2, o3, r0, r1);
            Ahi[(r4 + 8) * BSTRIDE + nt * 4 + q4] = h1;
            Alo[(r4 + 8) * BSTRIDE + nt * 4 + q4] = pack_h2n(r0, r1);
        }
        __syncwarp();
        for (int idx = lane; idx < 256; idx += 32) {
            int r = idx >> 4, qv = idx & 15;
            int row = rowBase + r;
            if (row < n) {
                uint4 vh = *(const uint4*)(Ahi + r * BSTRIDE + qv * 4);
                uint4 vl = *(const uint4*)(Alo + r * BSTRIDE + qv * 4);
                ((uint4*)(g_hh + (size_t)row * 128))[qv] = vh;
                ((uint4*)(g_hl + (size_t)row * 128))[qv] = vl;
            }
        }
        __syncwarp();
    }
}

// ---------------- HMMA GCN GEMM (fp16 2-pass) + int16 sup quantization -------
template <int N2>
__global__ void __launch_bounds__(256, 1) k_mma(
    const unsigned short* __restrict__ hh, const unsigned short* __restrict__ hl,
    const float* __restrict__ wn, const float* __restrict__ ws,
    const float* __restrict__ bias,
    unsigned* __restrict__ supu, float* __restrict__ scaleArr,
    float* __restrict__ selfb, int n)
{
    constexpr int OUT = N2 / 2;
    constexpr int WPG = N2 / 32;
    constexpr int G = 8 / WPG;
    constexpr int BSTRIDE = 68;
    constexpr int TM = 32;
    constexpr int ABUF = 2 * TM * BSTRIDE;
    constexpr int AOFF = N2 * BSTRIDE;         // only B-hi plane
    constexpr int RMOFF = AOFF + G * 2 * ABUF;
    constexpr int SUPW = OUT / 2;

    extern __shared__ __align__(16) uint32_t sm32[];
    uint32_t* Bh = sm32;

    int tid = threadIdx.x, wid = tid >> 5, lane = tid & 31;
    int g = wid / WPG, wg = wid % WPG;
    int lt = tid - g * (WPG * 32);
    int q4 = lane & 3, r4 = lane >> 2;
    uint32_t smemU = smem_u32(sm32);
    unsigned* rmax = (unsigned*)(sm32 + RMOFF + g * TM);

    for (int i = tid; i < N2 * 64; i += 256) {
        int kp = i / N2, nn = i % N2;
        float a0, a1;
        if (nn < OUT) {
            a0 = wn[(2 * kp) * OUT + nn];
            a1 = wn[(2 * kp + 1) * OUT + nn];
        } else {
            a0 = ws[(2 * kp) * OUT + nn - OUT];
            a1 = ws[(2 * kp + 1) * OUT + nn - OUT];
        }
        Bh[nn * BSTRIDE + kp] = pack_h2n(a0, a1);
    }
    __syncthreads();

    uint32_t bh[4][8][2];
    #pragma unroll
    for (int nt = 0; nt < 4; nt++) {
        #pragma unroll
        for (int ks = 0; ks < 8; ks++) {
            const uint32_t* p = Bh + (wg * 32 + nt * 8 + r4) * BSTRIDE + ks * 8 + q4;
            bh[nt][ks][0] = p[0];
            bh[nt][ks][1] = p[4];
        }
    }

    uint32_t loff = ((((lane & 7) + ((lane >> 3) & 1) * 8) * BSTRIDE + (lane >> 4) * 4)) * 4;

    int ntasks = (n + TM - 1) / TM;
    int stride = 148 * G;
    int t0 = blockIdx.x * G + g;
    int iters = (ntasks + stride - 1) / stride;

    auto prefetch = [&](int t, int buf) {
        uint32_t abU = smemU + (AOFF + (g * 2 + buf) * ABUF) * 4;
        int rowBase = t * TM;
        for (int i = lt; i < TM * 16; i += WPG * 32) {
            int r = i >> 4, q = i & 15;
            int grow = rowBase + r;
            if (grow > n - 1) grow = n - 1;
            uint32_t dh = abU + (r * BSTRIDE + q * 4) * 4;
            CP_ASYNC_CG(dh, ((const uint4*)(hh + (size_t)grow * 128)) + q);
            CP_ASYNC_CG(dh + TM * BSTRIDE * 4, ((const uint4*)(hl + (size_t)grow * 128)) + q);
        }
    };

    if (t0 < ntasks) prefetch(t0, 0);
    CP_COMMIT();

    int cur = 0;
    for (int it = 0; it < iters; it++) {
        int t = t0 + it * stride;
        int tn = t + stride;

        if (tn < ntasks) prefetch(tn, cur ^ 1);
        CP_COMMIT();
        CP_WAIT1();
        if (lt < TM) rmax[lt] = 0;
        __syncthreads();

        float acc[2][4][4];
        if (t < ntasks) {
            uint32_t abU = smemU + (AOFF + (g * 2 + cur) * ABUF) * 4 + loff;

            #pragma unroll
            for (int s = 0; s < 2; s++)
                #pragma unroll
                for (int nt = 0; nt < 4; nt++)
                    #pragma unroll
                    for (int j = 0; j < 4; j++) acc[s][nt][j] = 0.f;

            #pragma unroll
            for (int ks = 0; ks < 8; ks++) {
                #pragma unroll
                for (int s = 0; s < 2; s++) {
                    uint32_t ah0, ah1, ah2, ah3, al0, al1, al2, al3;
                    uint32_t base = abU + (s * 16 * BSTRIDE + ks * 8) * 4;
                    ldsm4(ah0, ah1, ah2, ah3, base);
                    ldsm4(al0, al1, al2, al3, base + TM * BSTRIDE * 4);
                    #pragma unroll
                    for (int nt = 0; nt < 4; nt++) {
                        mma_f16(acc[s][nt][0], acc[s][nt][1], acc[s][nt][2], acc[s][nt][3],
                                ah0, ah1, ah2, ah3, bh[nt][ks][0], bh[nt][ks][1]);
                        mma_f16(acc[s][nt][0], acc[s][nt][1], acc[s][nt][2], acc[s][nt][3],
                                al0, al1, al2, al3, bh[nt][ks][0], bh[nt][ks][1]);
                    }
                }
            }

            if (wg < WPG / 2) {
                #pragma unroll
                for (int s = 0; s < 2; s++) {
                    float m0 = 0.f, m1 = 0.f;
                    #pragma unroll
                    for (int nt = 0; nt < 4; nt++) {
                        m0 = fmaxf(m0, fmaxf(fabsf(acc[s][nt][0]), fabsf(acc[s][nt][1])));
                        m1 = fmaxf(m1, fmaxf(fabsf(acc[s][nt][2]), fabsf(acc[s][nt][3])));
                    }
                    #pragma unroll
                    for (int o = 1; o <= 2; o <<= 1) {
                        m0 = fmaxf(m0, __shfl_xor_sync(0xffffffffu, m0, o));
                        m1 = fmaxf(m1, __shfl_xor_sync(0xffffffffu, m1, o));
                    }
                    if (q4 == 0) {
                        atomicMax(&rmax[s * 16 + r4], __float_as_uint(m0));
                        atomicMax(&rmax[s * 16 + r4 + 8], __float_as_uint(m1));
                    }
                }
            }
        }
        __syncthreads();

        if (t < ntasks) {
            int rowBase = t * TM;
            if (wg < WPG / 2) {
                #pragma unroll
                for (int s = 0; s < 2; s++) {
                    int row0 = rowBase + s * 16 + r4, row1 = row0 + 8;
                    float rm0 = __uint_as_float(rmax[s * 16 + r4]);
                    float rm1 = __uint_as_float(rmax[s * 16 + r4 + 8]);
                    float iv0 = rm0 > 0.f ? QMAX / rm0 : 0.f;
                    float iv1 = rm1 > 0.f ? QMAX / rm1 : 0.f;
                    #pragma unroll
                    for (int nt = 0; nt < 4; nt++) {
                        int col = wg * 32 + nt * 8 + q4 * 2;
                        unsigned u0 = (unsigned)__float2int_rn(fmaf(acc[s][nt][0], iv0, 32768.f));
                        unsigned u1 = (unsigned)__float2int_rn(fmaf(acc[s][nt][1], iv0, 32768.f));
                        unsigned u2 = (unsigned)__float2int_rn(fmaf(acc[s][nt][2], iv1, 32768.f));
                        unsigned u3 = (unsigned)__float2int_rn(fmaf(acc[s][nt][3], iv1, 32768.f));
                        if (row0 < n) supu[(size_t)row0 * SUPW + (col >> 1)] = (u0 & 0xffffu) | (u1 << 16);
                        if (row1 < n) supu[(size_t)row1 * SUPW + (col >> 1)] = (u2 & 0xffffu) | (u3 << 16);
                    }
                    if (wg == 0 && q4 == 0) {
                        if (row0 < n) scaleArr[row0] = rm0 * (1.f / QMAX);
                        if (row1 < n) scaleArr[row1] = rm1 * (1.f / QMAX);
                    }
                }
            } else {
                #pragma unroll
                for (int s = 0; s < 2; s++) {
                    int row0 = rowBase + s * 16 + r4, row1 = row0 + 8;
                    #pragma unroll
                    for (int nt = 0; nt < 4; nt++) {
                        int c = wg * 32 + nt * 8 + q4 * 2 - OUT;
                        float2 bv = *(const float2*)(bias + c);
                        if (row0 < n) *(float2*)(selfb + (size_t)row0 * OUT + c) = make_float2(acc[s][nt][0] + bv.x, acc[s][nt][1] + bv.y);
                        if (row1 < n) *(float2*)(selfb + (size_t)row1 * OUT + c) = make_float2(acc[s][nt][2] + bv.x, acc[s][nt][3] + bv.y);
                    }
                }
            }
        }
        __syncthreads();
        cur ^= 1;
    }
}

// ---------------- sparse aggregation (u16 dequant, 4-edge MLP) + relu --------
__global__ void k_spmm128(const unsigned* __restrict__ supu, const float* __restrict__ scaleArr,
                          const float* __restrict__ selfb, int n)
{
    int warp = (blockIdx.x * blockDim.x + threadIdx.x) >> 5;
    int lane = threadIdx.x & 31;
    if (warp >= n) return;
    int e0 = g_off[warp], e1 = g_off[warp + 1];

    float4 acc = make_float4(0.f, 0.f, 0.f, 0.f);
    int e = e0;
    for (; e + 3 < e1; e += 4) {
        int2 p0 = __ldg(&g_epack[e]);
        int2 p1 = __ldg(&g_epack[e + 1]);
        int2 p2 = __ldg(&g_epack[e + 2]);
        int2 p3 = __ldg(&g_epack[e + 3]);
        float m0 = __int_as_float(p0.y) * __ldg(&scaleArr[p0.x]);
        float m1 = __int_as_float(p1.y) * __ldg(&scaleArr[p1.x]);
        float m2 = __int_as_float(p2.y) * __ldg(&scaleArr[p2.x]);
        float m3 = __int_as_float(p3.y) * __ldg(&scaleArr[p3.x]);
        uint2 d0 = ((const uint2*)(supu + (size_t)p0.x * 64))[lane];
        uint2 d1 = ((const uint2*)(supu + (size_t)p1.x * 64))[lane];
        uint2 d2 = ((const uint2*)(supu + (size_t)p2.x * 64))[lane];
        uint2 d3 = ((const uint2*)(supu + (size_t)p3.x * 64))[lane];
        acc.x = fmaf(m0, dq_lo(d0.x), fmaf(m1, dq_lo(d1.x), acc.x));
        acc.y = fmaf(m0, dq_hi(d0.x), fmaf(m1, dq_hi(d1.x), acc.y));
        acc.z = fmaf(m0, dq_lo(d0.y), fmaf(m1, dq_lo(d1.y), acc.z));
        acc.w = fmaf(m0, dq_hi(d0.y), fmaf(m1, dq_hi(d1.y), acc.w));
        acc.x = fmaf(m2, dq_lo(d2.x), fmaf(m3, dq_lo(d3.x), acc.x));
        acc.y = fmaf(m2, dq_hi(d2.x), fmaf(m3, dq_hi(d3.x), acc.y));
        acc.z = fmaf(m2, dq_lo(d2.y), fmaf(m3, dq_lo(d3.y), acc.z));
        acc.w = fmaf(m2, dq_hi(d2.y), fmaf(m3, dq_hi(d3.y), acc.w));
    }
    for (; e < e1; e++) {
        int2 p0 = __ldg(&g_epack[e]);
        float m0 = __int_as_float(p0.y) * __ldg(&scaleArr[p0.x]);
        uint2 d0 = ((const uint2*)(supu + (size_t)p0.x * 64))[lane];
        acc.x = fmaf(m0, dq_lo(d0.x), acc.x);
        acc.y = fmaf(m0, dq_hi(d0.x), acc.y);
        acc.z = fmaf(m0, dq_lo(d0.y), acc.z);
        acc.w = fmaf(m0, dq_hi(d0.y), acc.w);
    }
    float4 sb = ((const float4*)(selfb + (size_t)warp * 128))[lane];
    float o0 = fmaxf(acc.x + sb.x, 0.f);
    float o1 = fmaxf(acc.y + sb.y, 0.f);
    float o2 = fmaxf(acc.z + sb.z, 0.f);
    float o3 = fmaxf(acc.w + sb.w, 0.f);
    float l0, l1, l2, l3;
    unsigned p01 = pack_h2(o0, o1, l0, l1);
    unsigned p23 = pack_h2(o2, o3, l2, l3);
    ((uint2*)(g_hh + (size_t)warp * 128))[lane] = make_uint2(p01, p23);
    ((uint2*)(g_hl + (size_t)warp * 128))[lane] = make_uint2(pack_h2n(l0, l1), pack_h2n(l2, l3));
}

__global__ void k_spmm64(const unsigned* __restrict__ supu, const float* __restrict__ scaleArr,
                         const float* __restrict__ selfb, float* __restrict__ out, int n)
{
    int warp = (blockIdx.x * blockDim.x + threadIdx.x) >> 5;
    int lane = threadIdx.x & 31;
    if (warp >= n) return;
    int e0 = g_off[warp], e1 = g_off[warp + 1];

    float2 acc = make_float2(0.f, 0.f);
    int e = e0;
    for (; e + 3 < e1; e += 4) {
        int2 p0 = __ldg(&g_epack[e]);
        int2 p1 = __ldg(&g_epack[e + 1]);
        int2 p2 = __ldg(&g_epack[e + 2]);
        int2 p3 = __ldg(&g_epack[e + 3]);
        float m0 = __int_as_float(p0.y) * __ldg(&scaleArr[p0.x]);
        float m1 = __int_as_float(p1.y) * __ldg(&scaleArr[p1.x]);
        float m2 = __int_as_float(p2.y) * __ldg(&scaleArr[p2.x]);
        float m3 = __int_as_float(p3.y) * __ldg(&scaleArr[p3.x]);
        unsigned d0 = ((const unsigned*)(supu + (size_t)p0.x * 32))[lane];
        unsigned d1 = ((const unsigned*)(supu + (size_t)p1.x * 32))[lane];
        unsigned d2 = ((const unsigned*)(supu + (size_t)p2.x * 32))[lane];
        unsigned d3 = ((const unsigned*)(supu + (size_t)p3.x * 32))[lane];
        acc.x = fmaf(m0, dq_lo(d0), fmaf(m1, dq_lo(d1), acc.x));
        acc.y = fmaf(m0, dq_hi(d0), fmaf(m1, dq_hi(d1), acc.y));
        acc.x = fmaf(m2, dq_lo(d2), fmaf(m3, dq_lo(d3), acc.x));
        acc.y = fmaf(m2, dq_hi(d2), fmaf(m3, dq_hi(d3), acc.y));
    }
    for (; e < e1; e++) {
        int2 p0 = __ldg(&g_epack[e]);
        float m0 = __int_as_float(p0.y) * __ldg(&scaleArr[p0.x]);
        unsigned d0 = ((const unsigned*)(supu + (size_t)p0.x * 32))[lane];
        acc.x = fmaf(m0, dq_lo(d0), acc.x);
        acc.y = fmaf(m0, dq_hi(d0), acc.y);
    }
    float2 sb = ((const float2*)(selfb + (size_t)warp * 64))[lane];
    float2 o;
    o.x = fmaxf(acc.x + sb.x, 0.f);
    o.y = fmaxf(acc.y + sb.y, 0.f);
    ((float2*)(out + (size_t)warp * 64))[lane] = o;
}

// ---------------- launch -----------------------------------------------------
extern "C" void kernel_launch(void* const* d_in, const int* in_sizes, int n_in,
                              void* d_out, int out_size)
{
    const float* x    = (const float*)d_in[0];
    const int*   erow = (const int*)d_in[1];
    const int*   ecol = (const int*)d_in[2];
    const float* eval = (const float*)d_in[3];
    const float* w1   = (const float*)d_in[4];
    const float* b1   = (const float*)d_in[5];
    const float* w2   = (const float*)d_in[6];
    const float* b2   = (const float*)d_in[7];
    const float* gam  = (const float*)d_in[8];
    const float* bet  = (const float*)d_in[9];
    const float* gwn[4] = {(const float*)d_in[10], (const float*)d_in[13],
                           (const float*)d_in[16], (const float*)d_in[19]};
    const float* gws[4] = {(const float*)d_in[11], (const float*)d_in[14],
                           (const float*)d_in[17], (const float*)d_in[20]};
    const float* gb[4]  = {(const float*)d_in[12], (const float*)d_in[15],
                           (const float*)d_in[18], (const float*)d_in[21]};
    float* out = (float*)d_out;

    int n = in_sizes[0] / 128;
    int E = in_sizes[1];

    float *self, *scl;
    unsigned* supu;
    unsigned short *hh, *hl;
    cudaGetSymbolAddress((void**)&supu, g_supu);
    cudaGetSymbolAddress((void**)&scl, g_scale);
    cudaGetSymbolAddress((void**)&self, g_self);
    cudaGetSymbolAddress((void**)&hh, g_hh);
    cudaGetSymbolAddress((void**)&hl, g_hl);

    const int SMFC  = (2 * 128 * 68 + 8 * 2 * 16 * 68) * 4;                 // 139264
    const int SM256 = (256 * 68 + 1 * 2 * 2 * 32 * 68) * 4 + 1 * 32 * 4;    // 104576
    const int SM128 = (128 * 68 + 2 * 2 * 2 * 32 * 68) * 4 + 2 * 32 * 4;    // 104704

    cudaFuncSetAttribute(k_fc, cudaFuncAttributeMaxDynamicSharedMemorySize, SMFC);
    cudaFuncSetAttribute(k_mma<256>, cudaFuncAttributeMaxDynamicSharedMemorySize, SM256);
    cudaFuncSetAttribute(k_mma<128>, cudaFuncAttributeMaxDynamicSharedMemorySize, SM128);

    int nb = (n + 1023) / 1024;
    int spblocks = (n + 7) / 8;

    // ordered so the profiled (4th) launch = k_fc
    k_zero<<<(n + 255) / 256, 256>>>(n);
    k_hist<<<(E + 255) / 256, 256>>>(erow, E);
    k_scan1<<<nb, 1024>>>(n);
    k_fc<<<148, 256, SMFC>>>(x, w1, b1, w2, b2, gam, bet, n);

    k_scan2<<<1, 128>>>(nb);
    k_scan3<<<(n + 255) / 256, 256>>>(n);
    k_scatter<<<(E + 255) / 256, 256>>>(erow, ecol, eval, E);

    k_mma<256><<<148, 256, SM256>>>(hh, hl, gwn[0], gws[0], gb[0], supu, scl, self, n);
    k_spmm128<<<spblocks, 256>>>(supu, scl, self, n);

    k_mma<256><<<148, 256, SM256>>>(hh, hl, gwn[1], gws[1], gb[1], supu, scl, self, n);
    k_spmm128<<<spblocks, 256>>>(supu, scl, self, n);

    k_mma<256><<<148, 256, SM256>>>(hh, hl, gwn[2], gws[2], gb[2], supu, scl, self, n);
    k_spmm128<<<spblocks, 256>>>(supu, scl, self, n);

    k_mma<128><<<148, 256, SM128>>>(hh, hl, gwn[3], gws[3], gb[3], supu, scl, self, n);
    k_spmm64<<<spblocks, 256>>>(supu, scl, self, out, n);
}